// round 1
// baseline (speedup 1.0000x reference)
#include <cuda_runtime.h>
#include <math.h>

#define NN   512
#define CZ   128
#define NR   (NN*NN)          // 262144 rows
#define ZPAD 68               // padded row stride (floats), 16B-aligned
#define WPAD 132
#define EPSV 1e-5f

// ---------------- scratch (device globals; alloc-free) ----------------
__device__ float g_a[(size_t)CZ * NN * NN];     // a[c][i][k]   128 MiB
__device__ float g_b[(size_t)CZ * NN * NN];     // b[c][j][k]   128 MiB
__device__ float g_gate[(size_t)NR * CZ];       // gate[r][c]   128 MiB
__device__ float g_x[(size_t)CZ * NN * NN];     // x[c][i][j]   128 MiB

// 64x64 tile GEMM core: acc[4x4] = znS(rows ty*4..) . wS(cols tx*4..), K=128
__device__ __forceinline__ void gemm64(const float* __restrict__ aS,
                                       const float* __restrict__ bS,
                                       int tx, int ty, float acc[16]) {
    #pragma unroll
    for (int q = 0; q < 16; ++q) acc[q] = 0.f;
    #pragma unroll 4
    for (int k = 0; k < 128; ++k) {
        float4 a = *(const float4*)(aS + k * ZPAD + ty * 4);
        float4 b = *(const float4*)(bS + k * ZPAD + tx * 4);
        acc[0]  += a.x*b.x; acc[1]  += a.x*b.y; acc[2]  += a.x*b.z; acc[3]  += a.x*b.w;
        acc[4]  += a.y*b.x; acc[5]  += a.y*b.y; acc[6]  += a.y*b.z; acc[7]  += a.y*b.w;
        acc[8]  += a.z*b.x; acc[9]  += a.z*b.y; acc[10] += a.z*b.z; acc[11] += a.z*b.w;
        acc[12] += a.w*b.x; acc[13] += a.w*b.y; acc[14] += a.w*b.z; acc[15] += a.w*b.w;
    }
}

// =====================================================================
// Kernel 1: fused LayerNorm(z) + projections:
//   a/b = mask * sigmoid(zn@Wg_ab + bg) * (zn@Wp_ab + bp)   -> g_a/g_b (c-major)
//   gate = sigmoid(zn@Wg + bg_g)                            -> g_gate (row-major)
// Block: 64 rows x 256 threads. Loops 6 column chunks of 64.
// =====================================================================
__global__ void __launch_bounds__(256) k1_proj(
    const float* __restrict__ z, const float* __restrict__ mask,
    const float* __restrict__ w_ab_p, const float* __restrict__ b_ab_p,
    const float* __restrict__ w_ab_g, const float* __restrict__ b_ab_g,
    const float* __restrict__ w_g,   const float* __restrict__ b_g,
    const float* __restrict__ ln_g,  const float* __restrict__ ln_b)
{
    extern __shared__ float sm[];
    float* znS  = sm;                    // [128][ZPAD] transposed: znS[c][row]
    float* wS   = sm + 128 * ZPAD;       // [128][ZPAD] (also reused as stage)
    float* sum1 = sm + 2 * 128 * ZPAD;   // [4][64]
    float* sum2 = sum1 + 256;            // [4][64]
    float* muS  = sum2 + 256;            // [64]
    float* rsS  = muS + 64;              // [64]

    const int t  = threadIdx.x;
    const int r0 = blockIdx.x * 64;      // 64 rows share one i (64 | 512)
    const int i0 = r0 >> 9;
    const int k0 = r0 & 511;

    // ---- load z tile (64x128) transposed into znS ----
    #pragma unroll
    for (int pass = 0; pass < 8; ++pass) {
        int idx = pass * 256 + t;
        int row = idx >> 5;
        int c4  = idx & 31;
        float4 v = *(const float4*)(z + (size_t)(r0 + row) * CZ + c4 * 4);
        znS[(c4*4+0)*ZPAD + row] = v.x;
        znS[(c4*4+1)*ZPAD + row] = v.y;
        znS[(c4*4+2)*ZPAD + row] = v.z;
        znS[(c4*4+3)*ZPAD + row] = v.w;
    }
    __syncthreads();

    // ---- layernorm in smem ----
    {
        const int row  = t & 63;
        const int part = t >> 6;
        float s = 0.f, s2 = 0.f;
        #pragma unroll
        for (int q = 0; q < 32; ++q) {
            float v = znS[(part*32 + q) * ZPAD + row];
            s += v; s2 += v * v;
        }
        sum1[part*64 + row] = s;
        sum2[part*64 + row] = s2;
        __syncthreads();
        if (part == 0) {
            float ts  = sum1[row] + sum1[64+row] + sum1[128+row] + sum1[192+row];
            float ts2 = sum2[row] + sum2[64+row] + sum2[128+row] + sum2[192+row];
            float mu  = ts * (1.0f/128.0f);
            float var = fmaxf(ts2 * (1.0f/128.0f) - mu*mu, 0.f);
            muS[row] = mu;
            rsS[row] = rsqrtf(var + EPSV);
        }
        __syncthreads();
        const float mu = muS[row], rs = rsS[row];
        #pragma unroll
        for (int q = 0; q < 32; ++q) {
            int c = part*32 + q;
            znS[c*ZPAD + row] = (znS[c*ZPAD + row] - mu) * rs * ln_g[c] + ln_b[c];
        }
    }
    __syncthreads();

    const int tx = t & 15;     // 4 cols each
    const int ty = t >> 4;     // 4 rows each
    float accG[16], accP[16];

    // ---- ab chunks: 4 chunks of 64 output channels (256 total) ----
    for (int chunk = 0; chunk < 4; ++chunk) {
        const int c0 = chunk * 64;
        #pragma unroll
        for (int pass = 0; pass < 8; ++pass) {
            int idx = pass*256 + t;
            int wr = idx >> 4, wc4 = idx & 15;
            *(float4*)(wS + wr*ZPAD + wc4*4) =
                *(const float4*)(w_ab_g + wr*256 + c0 + wc4*4);
        }
        __syncthreads();
        gemm64(znS, wS, tx, ty, accG);
        __syncthreads();
        #pragma unroll
        for (int pass = 0; pass < 8; ++pass) {
            int idx = pass*256 + t;
            int wr = idx >> 4, wc4 = idx & 15;
            *(float4*)(wS + wr*ZPAD + wc4*4) =
                *(const float4*)(w_ab_p + wr*256 + c0 + wc4*4);
        }
        __syncthreads();
        gemm64(znS, wS, tx, ty, accP);

        float outv[16];
        #pragma unroll
        for (int ii = 0; ii < 4; ++ii) {
            float mv = mask[r0 + ty*4 + ii];
            #pragma unroll
            for (int jj = 0; jj < 4; ++jj) {
                int c = c0 + tx*4 + jj;
                float gv = 1.0f / (1.0f + __expf(-(accG[ii*4+jj] + b_ab_g[c])));
                outv[ii*4+jj] = mv * gv * (accP[ii*4+jj] + b_ab_p[c]);
            }
        }
        __syncthreads();
        // stage transposed: sS[col][row] (reuse wS)
        #pragma unroll
        for (int ii = 0; ii < 4; ++ii)
            #pragma unroll
            for (int jj = 0; jj < 4; ++jj)
                wS[(tx*4 + jj) * ZPAD + (ty*4 + ii)] = outv[ii*4+jj];
        __syncthreads();
        // coalesced c-major write: a[c][i][k] / b[c][i][k]
        {
            int col  = t >> 2;            // 0..63 (local channel)
            int rowb = (t & 3) * 16;      // 16 consecutive k's
            int ch   = c0 + col;
            float* dst = (ch < CZ) ? g_a : g_b;
            int cc = ch & (CZ - 1);
            float* p = dst + ((size_t)cc * NN + i0) * NN + k0 + rowb;
            #pragma unroll
            for (int q = 0; q < 16; q += 4) {
                float4 v;
                v.x = wS[col*ZPAD + rowb + q + 0];
                v.y = wS[col*ZPAD + rowb + q + 1];
                v.z = wS[col*ZPAD + rowb + q + 2];
                v.w = wS[col*ZPAD + rowb + q + 3];
                *(float4*)(p + q) = v;
            }
        }
        __syncthreads();
    }

    // ---- gate chunks: 2 chunks of 64 (128 total), row-major direct store ----
    for (int chunk = 0; chunk < 2; ++chunk) {
        const int c0 = chunk * 64;
        #pragma unroll
        for (int pass = 0; pass < 8; ++pass) {
            int idx = pass*256 + t;
            int wr = idx >> 4, wc4 = idx & 15;
            *(float4*)(wS + wr*ZPAD + wc4*4) =
                *(const float4*)(w_g + wr*CZ + c0 + wc4*4);
        }
        __syncthreads();
        gemm64(znS, wS, tx, ty, accG);
        #pragma unroll
        for (int ii = 0; ii < 4; ++ii) {
            int r = r0 + ty*4 + ii;
            float4 v;
            v.x = 1.0f / (1.0f + __expf(-(accG[ii*4+0] + b_g[c0 + tx*4 + 0])));
            v.y = 1.0f / (1.0f + __expf(-(accG[ii*4+1] + b_g[c0 + tx*4 + 1])));
            v.z = 1.0f / (1.0f + __expf(-(accG[ii*4+2] + b_g[c0 + tx*4 + 2])));
            v.w = 1.0f / (1.0f + __expf(-(accG[ii*4+3] + b_g[c0 + tx*4 + 3])));
            *(float4*)(g_gate + (size_t)r * CZ + c0 + tx*4) = v;
        }
        __syncthreads();
    }
}

// =====================================================================
// Kernel 2: einsum — per channel c: X_c(512x512) = A_c @ B_c^T
// Classic 128x128 tile SGEMM, 8x8 per thread, TK=8, register prefetch.
// grid (4,4,128)
// =====================================================================
__global__ void __launch_bounds__(256) k2_einsum() {
    __shared__ float As[8][WPAD];
    __shared__ float Bs[8][WPAD];
    const int t  = threadIdx.x;
    const int c  = blockIdx.z;
    const int m0 = blockIdx.y * 128;
    const int n0 = blockIdx.x * 128;
    const float* A  = g_a + (size_t)c * NR;
    const float* Bm = g_b + (size_t)c * NR;
    const int tx = t & 15, ty = t >> 4;
    const int lrow = t >> 1, lpart = t & 1;

    float acc[8][8];
    #pragma unroll
    for (int m = 0; m < 8; ++m)
        #pragma unroll
        for (int n = 0; n < 8; ++n) acc[m][n] = 0.f;

    float4 va = *(const float4*)(A  + (size_t)(m0 + lrow) * NN + lpart*4);
    float4 vb = *(const float4*)(Bm + (size_t)(n0 + lrow) * NN + lpart*4);

    for (int kk = 0; kk < NN; kk += 8) {
        As[lpart*4+0][lrow] = va.x;  As[lpart*4+1][lrow] = va.y;
        As[lpart*4+2][lrow] = va.z;  As[lpart*4+3][lrow] = va.w;
        Bs[lpart*4+0][lrow] = vb.x;  Bs[lpart*4+1][lrow] = vb.y;
        Bs[lpart*4+2][lrow] = vb.z;  Bs[lpart*4+3][lrow] = vb.w;
        __syncthreads();
        if (kk + 8 < NN) {
            va = *(const float4*)(A  + (size_t)(m0 + lrow) * NN + kk + 8 + lpart*4);
            vb = *(const float4*)(Bm + (size_t)(n0 + lrow) * NN + kk + 8 + lpart*4);
        }
        #pragma unroll
        for (int k = 0; k < 8; ++k) {
            float4 a0 = *(const float4*)(&As[k][ty*8]);
            float4 a1 = *(const float4*)(&As[k][ty*8 + 4]);
            float4 b0 = *(const float4*)(&Bs[k][tx*8]);
            float4 b1 = *(const float4*)(&Bs[k][tx*8 + 4]);
            float av[8] = {a0.x,a0.y,a0.z,a0.w,a1.x,a1.y,a1.z,a1.w};
            float bv[8] = {b0.x,b0.y,b0.z,b0.w,b1.x,b1.y,b1.z,b1.w};
            #pragma unroll
            for (int m = 0; m < 8; ++m)
                #pragma unroll
                for (int n = 0; n < 8; ++n)
                    acc[m][n] += av[m] * bv[n];
        }
        __syncthreads();
    }

    float* X = g_x + (size_t)c * NR;
    #pragma unroll
    for (int m = 0; m < 8; ++m) {
        float* p = X + (size_t)(m0 + ty*8 + m) * NN + n0 + tx*8;
        *(float4*)(p)     = make_float4(acc[m][0], acc[m][1], acc[m][2], acc[m][3]);
        *(float4*)(p + 4) = make_float4(acc[m][4], acc[m][5], acc[m][6], acc[m][7]);
    }
}

// =====================================================================
// Kernel 3: gather x (c-major) -> LN over c -> @ w_z + b_z -> * gate -> out
// Block: 64 rows x 256 threads.
// =====================================================================
__global__ void __launch_bounds__(256) k3_final(
    const float* __restrict__ w_z, const float* __restrict__ b_z,
    const float* __restrict__ ln_g, const float* __restrict__ ln_b,
    float* __restrict__ out)
{
    extern __shared__ float sm[];
    float* xS   = sm;                     // [128][ZPAD] xS[c][row]
    float* wS   = sm + 128 * ZPAD;        // [128][WPAD] wS[k][n]
    float* sum1 = wS + 128 * WPAD;
    float* sum2 = sum1 + 256;
    float* muS  = sum2 + 256;
    float* rsS  = muS + 64;

    const int t  = threadIdx.x;
    const int r0 = blockIdx.x * 64;
    const int i0 = r0 >> 9;
    const int j0 = r0 & 511;

    // gather x tile from c-major g_x: coalesced 64-wide per channel
    {
        const int joff = t & 63, part = t >> 6;
        const float* src = g_x + (size_t)(part*32) * NR + (size_t)i0 * NN + j0 + joff;
        #pragma unroll 8
        for (int q = 0; q < 32; ++q)
            xS[(part*32 + q) * ZPAD + joff] = src[(size_t)q * NR];
    }
    #pragma unroll
    for (int pass = 0; pass < 16; ++pass) {
        int idx = pass*256 + t;
        int wr = idx >> 5, wc4 = idx & 31;
        *(float4*)(wS + wr*WPAD + wc4*4) = *(const float4*)(w_z + wr*CZ + wc4*4);
    }
    __syncthreads();

    // layernorm over c
    {
        const int row  = t & 63;
        const int part = t >> 6;
        float s = 0.f, s2 = 0.f;
        #pragma unroll
        for (int q = 0; q < 32; ++q) {
            float v = xS[(part*32 + q) * ZPAD + row];
            s += v; s2 += v * v;
        }
        sum1[part*64 + row] = s;
        sum2[part*64 + row] = s2;
        __syncthreads();
        if (part == 0) {
            float ts  = sum1[row] + sum1[64+row] + sum1[128+row] + sum1[192+row];
            float ts2 = sum2[row] + sum2[64+row] + sum2[128+row] + sum2[192+row];
            float mu  = ts * (1.0f/128.0f);
            float var = fmaxf(ts2 * (1.0f/128.0f) - mu*mu, 0.f);
            muS[row] = mu;
            rsS[row] = rsqrtf(var + EPSV);
        }
        __syncthreads();
        const float mu = muS[row], rs = rsS[row];
        #pragma unroll
        for (int q = 0; q < 32; ++q) {
            int cch = part*32 + q;
            xS[cch*ZPAD + row] = (xS[cch*ZPAD + row] - mu) * rs * ln_g[cch] + ln_b[cch];
        }
    }
    __syncthreads();

    // 64x128 GEMM (K=128): thread tile 4 rows x 8 cols
    const int tx = t & 15, ty = t >> 4;
    float acc[4][8];
    #pragma unroll
    for (int m = 0; m < 4; ++m)
        #pragma unroll
        for (int n = 0; n < 8; ++n) acc[m][n] = 0.f;

    #pragma unroll 4
    for (int k = 0; k < 128; ++k) {
        float4 a  = *(const float4*)(xS + k*ZPAD + ty*4);
        float4 b0 = *(const float4*)(wS + k*WPAD + tx*8);
        float4 b1 = *(const float4*)(wS + k*WPAD + tx*8 + 4);
        float av[4] = {a.x, a.y, a.z, a.w};
        float bv[8] = {b0.x,b0.y,b0.z,b0.w,b1.x,b1.y,b1.z,b1.w};
        #pragma unroll
        for (int m = 0; m < 4; ++m)
            #pragma unroll
            for (int n = 0; n < 8; ++n)
                acc[m][n] += av[m] * bv[n];
    }

    float4 bz0 = *(const float4*)(b_z + tx*8);
    float4 bz1 = *(const float4*)(b_z + tx*8 + 4);
    #pragma unroll
    for (int ii = 0; ii < 4; ++ii) {
        int r = r0 + ty*4 + ii;
        float4 gg0 = *(const float4*)(g_gate + (size_t)r * CZ + tx*8);
        float4 gg1 = *(const float4*)(g_gate + (size_t)r * CZ + tx*8 + 4);
        float4 v0, v1;
        v0.x = (acc[ii][0] + bz0.x) * gg0.x;
        v0.y = (acc[ii][1] + bz0.y) * gg0.y;
        v0.z = (acc[ii][2] + bz0.z) * gg0.z;
        v0.w = (acc[ii][3] + bz0.w) * gg0.w;
        v1.x = (acc[ii][4] + bz1.x) * gg1.x;
        v1.y = (acc[ii][5] + bz1.y) * gg1.y;
        v1.z = (acc[ii][6] + bz1.z) * gg1.z;
        v1.w = (acc[ii][7] + bz1.w) * gg1.w;
        *(float4*)(out + (size_t)r * CZ + tx*8)     = v0;
        *(float4*)(out + (size_t)r * CZ + tx*8 + 4) = v1;
    }
}

// =====================================================================
extern "C" void kernel_launch(void* const* d_in, const int* in_sizes, int n_in,
                              void* d_out, int out_size) {
    const float* z       = (const float*)d_in[0];
    const float* mask    = (const float*)d_in[1];
    const float* w_ab_p  = (const float*)d_in[2];
    const float* b_ab_p  = (const float*)d_in[3];
    const float* w_ab_g  = (const float*)d_in[4];
    const float* b_ab_g  = (const float*)d_in[5];
    const float* w_g     = (const float*)d_in[6];
    const float* b_g     = (const float*)d_in[7];
    const float* w_z     = (const float*)d_in[8];
    const float* b_z     = (const float*)d_in[9];
    const float* ln_in_g = (const float*)d_in[10];
    const float* ln_in_b = (const float*)d_in[11];
    const float* ln_out_g= (const float*)d_in[12];
    const float* ln_out_b= (const float*)d_in[13];
    float* out = (float*)d_out;

    const int SM1 = (2 * 128 * ZPAD + 640) * (int)sizeof(float);            // 72192
    const int SM3 = (128 * ZPAD + 128 * WPAD + 640) * (int)sizeof(float);   // 104960
    cudaFuncSetAttribute(k1_proj,  cudaFuncAttributeMaxDynamicSharedMemorySize, SM1);
    cudaFuncSetAttribute(k3_final, cudaFuncAttributeMaxDynamicSharedMemorySize, SM3);

    k1_proj<<<NR / 64, 256, SM1>>>(z, mask, w_ab_p, b_ab_p, w_ab_g, b_ab_g,
                                   w_g, b_g, ln_in_g, ln_in_b);
    k2_einsum<<<dim3(4, 4, 128), 256>>>();
    k3_final<<<NR / 64, 256, SM3>>>(w_z, b_z, ln_out_g, ln_out_b, out);
}

// round 4
// speedup vs baseline: 1.2262x; 1.2262x over previous
#include <cuda_runtime.h>
#include <cuda_bf16.h>
#include <math.h>
#include <cstdint>

#define NN   512
#define CZ   128
#define NR   (NN*NN)          // 262144
#define ZPAD 68
#define WPAD 132
#define EPSV 1e-5f

// ---------------- scratch (device globals; alloc-free) ----------------
__device__ __nv_bfloat16 g_ah[(size_t)CZ * NR];   // a hi [c][i][k]
__device__ __nv_bfloat16 g_al[(size_t)CZ * NR];   // a lo
__device__ __nv_bfloat16 g_bh[(size_t)CZ * NR];   // b hi [c][j][k]
__device__ __nv_bfloat16 g_bl[(size_t)CZ * NR];   // b lo
__device__ float g_gate[(size_t)NR * CZ];         // gate[r][c]
__device__ float g_x[(size_t)CZ * NR];            // x[c][i][j]

static __device__ __forceinline__ uint32_t smem_u32(const void* p) {
    return (uint32_t)__cvta_generic_to_shared(p);
}
static __device__ __forceinline__ void cp16(uint32_t dst, const void* src) {
    asm volatile("cp.async.cg.shared.global [%0], [%1], 16;" :: "r"(dst), "l"(src));
}
static __device__ __forceinline__ void cp_commit() {
    asm volatile("cp.async.commit_group;" ::: "memory");
}
static __device__ __forceinline__ void cp_wait1() {
    asm volatile("cp.async.wait_group 1;" ::: "memory");
}
static __device__ __forceinline__ void cp_wait0() {
    asm volatile("cp.async.wait_group 0;" ::: "memory");
}
static __device__ __forceinline__ void ldmx4(uint32_t* r, uint32_t addr) {
    asm volatile("ldmatrix.sync.aligned.m8n8.x4.shared.b16 {%0,%1,%2,%3}, [%4];"
                 : "=r"(r[0]), "=r"(r[1]), "=r"(r[2]), "=r"(r[3]) : "r"(addr));
}
static __device__ __forceinline__ void ldmx2(uint32_t* r, uint32_t addr) {
    asm volatile("ldmatrix.sync.aligned.m8n8.x2.shared.b16 {%0,%1}, [%2];"
                 : "=r"(r[0]), "=r"(r[1]) : "r"(addr));
}
static __device__ __forceinline__ void mma16816(float* d, const uint32_t* a, const uint32_t* b) {
    asm volatile("mma.sync.aligned.m16n8k16.row.col.f32.bf16.bf16.f32 "
                 "{%0,%1,%2,%3}, {%4,%5,%6,%7}, {%8,%9}, {%0,%1,%2,%3};"
                 : "+f"(d[0]), "+f"(d[1]), "+f"(d[2]), "+f"(d[3])
                 : "r"(a[0]), "r"(a[1]), "r"(a[2]), "r"(a[3]), "r"(b[0]), "r"(b[1]));
}

// ================= fp32 64x64 gemm core (k1/k3) =================
__device__ __forceinline__ void gemm64(const float* __restrict__ aS,
                                       const float* __restrict__ bS,
                                       int tx, int ty, float acc[16]) {
    #pragma unroll
    for (int q = 0; q < 16; ++q) acc[q] = 0.f;
    #pragma unroll 4
    for (int k = 0; k < 128; ++k) {
        float4 a = *(const float4*)(aS + k * ZPAD + ty * 4);
        float4 b = *(const float4*)(bS + k * ZPAD + tx * 4);
        acc[0]  += a.x*b.x; acc[1]  += a.x*b.y; acc[2]  += a.x*b.z; acc[3]  += a.x*b.w;
        acc[4]  += a.y*b.x; acc[5]  += a.y*b.y; acc[6]  += a.y*b.z; acc[7]  += a.y*b.w;
        acc[8]  += a.z*b.x; acc[9]  += a.z*b.y; acc[10] += a.z*b.z; acc[11] += a.z*b.w;
        acc[12] += a.w*b.x; acc[13] += a.w*b.y; acc[14] += a.w*b.z; acc[15] += a.w*b.w;
    }
}

// =====================================================================
// Kernel 1: LN(z) + projections -> a/b (bf16 hi/lo, c-major), gate (fp32)
// =====================================================================
__global__ void __launch_bounds__(256) k1_proj(
    const float* __restrict__ z, const float* __restrict__ mask,
    const float* __restrict__ w_ab_p, const float* __restrict__ b_ab_p,
    const float* __restrict__ w_ab_g, const float* __restrict__ b_ab_g,
    const float* __restrict__ w_g,   const float* __restrict__ b_g,
    const float* __restrict__ ln_g,  const float* __restrict__ ln_b)
{
    extern __shared__ float sm[];
    float* znS  = sm;
    float* wS   = sm + 128 * ZPAD;
    float* sum1 = sm + 2 * 128 * ZPAD;
    float* sum2 = sum1 + 256;
    float* muS  = sum2 + 256;
    float* rsS  = muS + 64;

    const int t  = threadIdx.x;
    const int r0 = blockIdx.x * 64;
    const int i0 = r0 >> 9;
    const int k0 = r0 & 511;

    #pragma unroll
    for (int pass = 0; pass < 8; ++pass) {
        int idx = pass * 256 + t;
        int row = idx >> 5;
        int c4  = idx & 31;
        float4 v = *(const float4*)(z + (size_t)(r0 + row) * CZ + c4 * 4);
        znS[(c4*4+0)*ZPAD + row] = v.x;
        znS[(c4*4+1)*ZPAD + row] = v.y;
        znS[(c4*4+2)*ZPAD + row] = v.z;
        znS[(c4*4+3)*ZPAD + row] = v.w;
    }
    __syncthreads();

    {
        const int row  = t & 63;
        const int part = t >> 6;
        float s = 0.f, s2 = 0.f;
        #pragma unroll
        for (int q = 0; q < 32; ++q) {
            float v = znS[(part*32 + q) * ZPAD + row];
            s += v; s2 += v * v;
        }
        sum1[part*64 + row] = s;
        sum2[part*64 + row] = s2;
        __syncthreads();
        if (part == 0) {
            float ts  = sum1[row] + sum1[64+row] + sum1[128+row] + sum1[192+row];
            float ts2 = sum2[row] + sum2[64+row] + sum2[128+row] + sum2[192+row];
            float mu  = ts * (1.0f/128.0f);
            float var = fmaxf(ts2 * (1.0f/128.0f) - mu*mu, 0.f);
            muS[row] = mu;
            rsS[row] = rsqrtf(var + EPSV);
        }
        __syncthreads();
        const float mu = muS[row], rs = rsS[row];
        #pragma unroll
        for (int q = 0; q < 32; ++q) {
            int c = part*32 + q;
            znS[c*ZPAD + row] = (znS[c*ZPAD + row] - mu) * rs * ln_g[c] + ln_b[c];
        }
    }
    __syncthreads();

    const int tx = t & 15;
    const int ty = t >> 4;
    float accG[16], accP[16];

    for (int chunk = 0; chunk < 4; ++chunk) {
        const int c0 = chunk * 64;
        #pragma unroll
        for (int pass = 0; pass < 8; ++pass) {
            int idx = pass*256 + t;
            int wr = idx >> 4, wc4 = idx & 15;
            *(float4*)(wS + wr*ZPAD + wc4*4) =
                *(const float4*)(w_ab_g + wr*256 + c0 + wc4*4);
        }
        __syncthreads();
        gemm64(znS, wS, tx, ty, accG);
        __syncthreads();
        #pragma unroll
        for (int pass = 0; pass < 8; ++pass) {
            int idx = pass*256 + t;
            int wr = idx >> 4, wc4 = idx & 15;
            *(float4*)(wS + wr*ZPAD + wc4*4) =
                *(const float4*)(w_ab_p + wr*256 + c0 + wc4*4);
        }
        __syncthreads();
        gemm64(znS, wS, tx, ty, accP);

        float outv[16];
        #pragma unroll
        for (int ii = 0; ii < 4; ++ii) {
            float mv = mask[r0 + ty*4 + ii];
            #pragma unroll
            for (int jj = 0; jj < 4; ++jj) {
                int c = c0 + tx*4 + jj;
                float gv = 1.0f / (1.0f + __expf(-(accG[ii*4+jj] + b_ab_g[c])));
                outv[ii*4+jj] = mv * gv * (accP[ii*4+jj] + b_ab_p[c]);
            }
        }
        __syncthreads();
        #pragma unroll
        for (int ii = 0; ii < 4; ++ii)
            #pragma unroll
            for (int jj = 0; jj < 4; ++jj)
                wS[(tx*4 + jj) * ZPAD + (ty*4 + ii)] = outv[ii*4+jj];
        __syncthreads();
        {
            int col  = t >> 2;
            int rowb = (t & 3) * 16;
            int ch   = c0 + col;
            __nv_bfloat16* dh = (ch < CZ) ? g_ah : g_bh;
            __nv_bfloat16* dl = (ch < CZ) ? g_al : g_bl;
            int cc = ch & (CZ - 1);
            size_t off = ((size_t)cc * NN + i0) * NN + k0 + rowb;
            __align__(16) __nv_bfloat16 hbuf[16];
            __align__(16) __nv_bfloat16 lbuf[16];
            #pragma unroll
            for (int q = 0; q < 16; ++q) {
                float v = wS[col*ZPAD + rowb + q];
                __nv_bfloat16 h = __float2bfloat16(v);
                hbuf[q] = h;
                lbuf[q] = __float2bfloat16(v - __bfloat162float(h));
            }
            *(uint4*)(dh + off)     = *(uint4*)(hbuf);
            *(uint4*)(dh + off + 8) = *(uint4*)(hbuf + 8);
            *(uint4*)(dl + off)     = *(uint4*)(lbuf);
            *(uint4*)(dl + off + 8) = *(uint4*)(lbuf + 8);
        }
        __syncthreads();
    }

    for (int chunk = 0; chunk < 2; ++chunk) {
        const int c0 = chunk * 64;
        #pragma unroll
        for (int pass = 0; pass < 8; ++pass) {
            int idx = pass*256 + t;
            int wr = idx >> 4, wc4 = idx & 15;
            *(float4*)(wS + wr*ZPAD + wc4*4) =
                *(const float4*)(w_g + wr*CZ + c0 + wc4*4);
        }
        __syncthreads();
        gemm64(znS, wS, tx, ty, accG);
        #pragma unroll
        for (int ii = 0; ii < 4; ++ii) {
            int r = r0 + ty*4 + ii;
            float4 v;
            v.x = 1.0f / (1.0f + __expf(-(accG[ii*4+0] + b_g[c0 + tx*4 + 0])));
            v.y = 1.0f / (1.0f + __expf(-(accG[ii*4+1] + b_g[c0 + tx*4 + 1])));
            v.z = 1.0f / (1.0f + __expf(-(accG[ii*4+2] + b_g[c0 + tx*4 + 2])));
            v.w = 1.0f / (1.0f + __expf(-(accG[ii*4+3] + b_g[c0 + tx*4 + 3])));
            *(float4*)(g_gate + (size_t)r * CZ + c0 + tx*4) = v;
        }
        __syncthreads();
    }
}

// =====================================================================
// Kernel 2: einsum via mma.sync bf16 3-pass split.
// Per channel c: X_c = A_c @ B_c^T (512^3).  CTA tile 128x128, 512 thr,
// warp tile 32x32, K-chunk 32, cp.async double buffer.
// STR=40 (80B rows): cp.async dst 16B-aligned, ldmatrix conflict-free.
// grid (4,4,128).
// =====================================================================
#define KC     32
#define STR    40                       // bf16 row stride in smem (80 B)
#define TILE_E (128*STR)                // elems per tile
#define BUF_E  (4*TILE_E)               // AH, AL, BH, BL
#define K2_SMEM (2 * BUF_E * 2)         // bytes (two buffers) = 81920

__global__ void __launch_bounds__(512) k2_einsum_mma() {
    extern __shared__ __nv_bfloat16 sb[];
    const uint32_t sbase = smem_u32(sb);

    const int t   = threadIdx.x;
    const int lid = t & 31;
    const int w   = t >> 5;          // 0..15
    const int wm  = w >> 2;          // 0..3
    const int wn  = w & 3;           // 0..3
    const int c   = blockIdx.z;
    const int m0  = blockIdx.y * 128;
    const int n0  = blockIdx.x * 128;

    const __nv_bfloat16* pAh = g_ah + (size_t)c * NR;
    const __nv_bfloat16* pAl = g_al + (size_t)c * NR;
    const __nv_bfloat16* pBh = g_bh + (size_t)c * NR;
    const __nv_bfloat16* pBl = g_bl + (size_t)c * NR;

    // global-load mapping: one 16B segment per tile per thread
    const int grow = t >> 2;         // 0..127
    const int gseg = t & 3;          // 0..3 (8 bf16 each)
    const size_t gA0 = (size_t)(m0 + grow) * NN + gseg * 8;
    const size_t gB0 = (size_t)(n0 + grow) * NN + gseg * 8;
    const uint32_t sw = (grow * STR + gseg * 8) * 2;   // 16B-aligned

    // ldmatrix per-lane address offsets (bytes, within a buffer)
    const int quad = lid >> 3;
    const int l7   = lid & 7;
    uint32_t aoff[2];
    #pragma unroll
    for (int mf = 0; mf < 2; ++mf) {
        int r = wm*32 + mf*16 + (quad & 1)*8 + l7;
        int kcol = (quad >> 1) * 8;
        aoff[mf] = (r * STR + kcol) * 2;
    }
    uint32_t boff[4];
    #pragma unroll
    for (int nf = 0; nf < 4; ++nf) {
        int r = wn*32 + nf*8 + l7;
        int kcol = ((lid >> 3) & 1) * 8;
        boff[nf] = (r * STR + kcol) * 2;
    }

    float d[2][4][4];
    #pragma unroll
    for (int mf = 0; mf < 2; ++mf)
        #pragma unroll
        for (int nf = 0; nf < 4; ++nf)
            #pragma unroll
            for (int q = 0; q < 4; ++q) d[mf][nf][q] = 0.f;

    // prefetch chunk 0 into buffer 0
    {
        uint32_t b0 = sbase;
        cp16(b0 + 0*TILE_E*2 + sw, pAh + gA0);
        cp16(b0 + 1*TILE_E*2 + sw, pAl + gA0);
        cp16(b0 + 2*TILE_E*2 + sw, pBh + gB0);
        cp16(b0 + 3*TILE_E*2 + sw, pBl + gB0);
        cp_commit();
    }

    for (int ch = 0; ch < 16; ++ch) {
        if (ch < 15) {
            uint32_t bb = sbase + ((ch + 1) & 1) * BUF_E * 2;
            int kk = (ch + 1) * KC;
            cp16(bb + 0*TILE_E*2 + sw, pAh + gA0 + kk);
            cp16(bb + 1*TILE_E*2 + sw, pAl + gA0 + kk);
            cp16(bb + 2*TILE_E*2 + sw, pBh + gB0 + kk);
            cp16(bb + 3*TILE_E*2 + sw, pBl + gB0 + kk);
            cp_commit();
            cp_wait1();
        } else {
            cp_wait0();
        }
        __syncthreads();

        const uint32_t bb = sbase + (ch & 1) * BUF_E * 2;
        const uint32_t bAH = bb;
        const uint32_t bAL = bb + TILE_E*2;
        const uint32_t bBH = bb + 2*TILE_E*2;
        const uint32_t bBL = bb + 3*TILE_E*2;

        #pragma unroll
        for (int ks = 0; ks < KC; ks += 16) {
            uint32_t ah[2][4], al[2][4], bh[4][2], bl[4][2];
            #pragma unroll
            for (int mf = 0; mf < 2; ++mf) ldmx4(ah[mf], bAH + aoff[mf] + ks*2);
            #pragma unroll
            for (int nf = 0; nf < 4; ++nf) ldmx2(bh[nf], bBH + boff[nf] + ks*2);
            #pragma unroll
            for (int nf = 0; nf < 4; ++nf) ldmx2(bl[nf], bBL + boff[nf] + ks*2);
            #pragma unroll
            for (int mf = 0; mf < 2; ++mf)
                #pragma unroll
                for (int nf = 0; nf < 4; ++nf)
                    mma16816(d[mf][nf], ah[mf], bh[nf]);
            #pragma unroll
            for (int mf = 0; mf < 2; ++mf)
                #pragma unroll
                for (int nf = 0; nf < 4; ++nf)
                    mma16816(d[mf][nf], ah[mf], bl[nf]);
            #pragma unroll
            for (int mf = 0; mf < 2; ++mf) ldmx4(al[mf], bAL + aoff[mf] + ks*2);
            #pragma unroll
            for (int mf = 0; mf < 2; ++mf)
                #pragma unroll
                for (int nf = 0; nf < 4; ++nf)
                    mma16816(d[mf][nf], al[mf], bh[nf]);
        }
        __syncthreads();
    }

    // epilogue: write fp32 X
    float* X = g_x + (size_t)c * NR;
    const int rb = m0 + wm*32 + (lid >> 2);
    const int cb = n0 + wn*32 + (lid & 3) * 2;
    #pragma unroll
    for (int mf = 0; mf < 2; ++mf)
        #pragma unroll
        for (int nf = 0; nf < 4; ++nf) {
            int row = rb + mf*16;
            int col = cb + nf*8;
            *(float2*)(X + (size_t)row * NN + col) =
                make_float2(d[mf][nf][0], d[mf][nf][1]);
            *(float2*)(X + (size_t)(row + 8) * NN + col) =
                make_float2(d[mf][nf][2], d[mf][nf][3]);
        }
}

// =====================================================================
// Kernel 3: gather x (c-major) -> LN over c -> @ w_z + b_z -> * gate -> out
// =====================================================================
__global__ void __launch_bounds__(256) k3_final(
    const float* __restrict__ w_z, const float* __restrict__ b_z,
    const float* __restrict__ ln_g, const float* __restrict__ ln_b,
    float* __restrict__ out)
{
    extern __shared__ float sm[];
    float* xS   = sm;
    float* wS   = sm + 128 * ZPAD;
    float* sum1 = wS + 128 * WPAD;
    float* sum2 = sum1 + 256;
    float* muS  = sum2 + 256;
    float* rsS  = muS + 64;

    const int t  = threadIdx.x;
    const int r0 = blockIdx.x * 64;
    const int i0 = r0 >> 9;
    const int j0 = r0 & 511;

    {
        const int joff = t & 63, part = t >> 6;
        const float* src = g_x + (size_t)(part*32) * NR + (size_t)i0 * NN + j0 + joff;
        #pragma unroll 8
        for (int q = 0; q < 32; ++q)
            xS[(part*32 + q) * ZPAD + joff] = src[(size_t)q * NR];
    }
    #pragma unroll
    for (int pass = 0; pass < 16; ++pass) {
        int idx = pass*256 + t;
        int wr = idx >> 5, wc4 = idx & 31;
        *(float4*)(wS + wr*WPAD + wc4*4) = *(const float4*)(w_z + wr*CZ + wc4*4);
    }
    __syncthreads();

    {
        const int row  = t & 63;
        const int part = t >> 6;
        float s = 0.f, s2 = 0.f;
        #pragma unroll
        for (int q = 0; q < 32; ++q) {
            float v = xS[(part*32 + q) * ZPAD + row];
            s += v; s2 += v * v;
        }
        sum1[part*64 + row] = s;
        sum2[part*64 + row] = s2;
        __syncthreads();
        if (part == 0) {
            float ts  = sum1[row] + sum1[64+row] + sum1[128+row] + sum1[192+row];
            float ts2 = sum2[row] + sum2[64+row] + sum2[128+row] + sum2[192+row];
            float mu  = ts * (1.0f/128.0f);
            float var = fmaxf(ts2 * (1.0f/128.0f) - mu*mu, 0.f);
            muS[row] = mu;
            rsS[row] = rsqrtf(var + EPSV);
        }
        __syncthreads();
        const float mu = muS[row], rs = rsS[row];
        #pragma unroll
        for (int q = 0; q < 32; ++q) {
            int cch = part*32 + q;
            xS[cch*ZPAD + row] = (xS[cch*ZPAD + row] - mu) * rs * ln_g[cch] + ln_b[cch];
        }
    }
    __syncthreads();

    const int tx = t & 15, ty = t >> 4;
    float acc[4][8];
    #pragma unroll
    for (int m = 0; m < 4; ++m)
        #pragma unroll
        for (int n = 0; n < 8; ++n) acc[m][n] = 0.f;

    #pragma unroll 4
    for (int k = 0; k < 128; ++k) {
        float4 a  = *(const float4*)(xS + k*ZPAD + ty*4);
        float4 b0 = *(const float4*)(wS + k*WPAD + tx*8);
        float4 b1 = *(const float4*)(wS + k*WPAD + tx*8 + 4);
        float av[4] = {a.x, a.y, a.z, a.w};
        float bv[8] = {b0.x,b0.y,b0.z,b0.w,b1.x,b1.y,b1.z,b1.w};
        #pragma unroll
        for (int m = 0; m < 4; ++m)
            #pragma unroll
            for (int n = 0; n < 8; ++n)
                acc[m][n] += av[m] * bv[n];
    }

    float4 bz0 = *(const float4*)(b_z + tx*8);
    float4 bz1 = *(const float4*)(b_z + tx*8 + 4);
    #pragma unroll
    for (int ii = 0; ii < 4; ++ii) {
        int r = r0 + ty*4 + ii;
        float4 gg0 = *(const float4*)(g_gate + (size_t)r * CZ + tx*8);
        float4 gg1 = *(const float4*)(g_gate + (size_t)r * CZ + tx*8 + 4);
        float4 v0, v1;
        v0.x = (acc[ii][0] + bz0.x) * gg0.x;
        v0.y = (acc[ii][1] + bz0.y) * gg0.y;
        v0.z = (acc[ii][2] + bz0.z) * gg0.z;
        v0.w = (acc[ii][3] + bz0.w) * gg0.w;
        v1.x = (acc[ii][4] + bz1.x) * gg1.x;
        v1.y = (acc[ii][5] + bz1.y) * gg1.y;
        v1.z = (acc[ii][6] + bz1.z) * gg1.z;
        v1.w = (acc[ii][7] + bz1.w) * gg1.w;
        *(float4*)(out + (size_t)r * CZ + tx*8)     = v0;
        *(float4*)(out + (size_t)r * CZ + tx*8 + 4) = v1;
    }
}

// =====================================================================
extern "C" void kernel_launch(void* const* d_in, const int* in_sizes, int n_in,
                              void* d_out, int out_size) {
    const float* z       = (const float*)d_in[0];
    const float* mask    = (const float*)d_in[1];
    const float* w_ab_p  = (const float*)d_in[2];
    const float* b_ab_p  = (const float*)d_in[3];
    const float* w_ab_g  = (const float*)d_in[4];
    const float* b_ab_g  = (const float*)d_in[5];
    const float* w_g     = (const float*)d_in[6];
    const float* b_g     = (const float*)d_in[7];
    const float* w_z     = (const float*)d_in[8];
    const float* b_z     = (const float*)d_in[9];
    const float* ln_in_g = (const float*)d_in[10];
    const float* ln_in_b = (const float*)d_in[11];
    const float* ln_out_g= (const float*)d_in[12];
    const float* ln_out_b= (const float*)d_in[13];
    float* out = (float*)d_out;

    const int SM1 = (2 * 128 * ZPAD + 640) * (int)sizeof(float);
    const int SM3 = (128 * ZPAD + 128 * WPAD + 640) * (int)sizeof(float);
    cudaFuncSetAttribute(k1_proj,       cudaFuncAttributeMaxDynamicSharedMemorySize, SM1);
    cudaFuncSetAttribute(k2_einsum_mma, cudaFuncAttributeMaxDynamicSharedMemorySize, K2_SMEM);
    cudaFuncSetAttribute(k3_final,      cudaFuncAttributeMaxDynamicSharedMemorySize, SM3);

    k1_proj<<<NR / 64, 256, SM1>>>(z, mask, w_ab_p, b_ab_p, w_ab_g, b_ab_g,
                                   w_g, b_g, ln_in_g, ln_in_b);
    k2_einsum_mma<<<dim3(4, 4, 128), 512, K2_SMEM>>>();
    k3_final<<<NR / 64, 256, SM3>>>(w_z, b_z, ln_out_g, ln_out_b, out);
}

// round 6
// speedup vs baseline: 1.5175x; 1.2376x over previous
#include <cuda_runtime.h>
#include <cuda_bf16.h>
#include <math.h>
#include <cstdint>

#define NN   512
#define CZ   128
#define NR   (NN*NN)          // 262144
#define WPAD 132
#define ZPAD 68
#define EPSV 1e-5f

// ---------------- scratch (device globals; alloc-free) ----------------
__device__ __nv_bfloat16 g_ah[(size_t)CZ * NR];   // a hi [c][i][k]
__device__ __nv_bfloat16 g_al[(size_t)CZ * NR];   // a lo
__device__ __nv_bfloat16 g_bh[(size_t)CZ * NR];   // b hi [c][j][k]
__device__ __nv_bfloat16 g_bl[(size_t)CZ * NR];   // b lo
__device__ float g_gate[(size_t)NR * CZ];         // gate[r][c]
__device__ float g_x[(size_t)CZ * NR];            // x[c][i][j]
__device__ __nv_bfloat16 g_wH[640 * 128];         // packed weights hi [n][k]
__device__ __nv_bfloat16 g_wL[640 * 128];         // packed weights lo [n][k]

static __device__ __forceinline__ uint32_t smem_u32(const void* p) {
    return (uint32_t)__cvta_generic_to_shared(p);
}
static __device__ __forceinline__ void cp16(uint32_t dst, const void* src) {
    asm volatile("cp.async.cg.shared.global [%0], [%1], 16;" :: "r"(dst), "l"(src));
}
static __device__ __forceinline__ void cp_commit() {
    asm volatile("cp.async.commit_group;" ::: "memory");
}
static __device__ __forceinline__ void cp_wait1() {
    asm volatile("cp.async.wait_group 1;" ::: "memory");
}
static __device__ __forceinline__ void cp_wait0() {
    asm volatile("cp.async.wait_group 0;" ::: "memory");
}
static __device__ __forceinline__ void ldmx4(uint32_t* r, uint32_t addr) {
    asm volatile("ldmatrix.sync.aligned.m8n8.x4.shared.b16 {%0,%1,%2,%3}, [%4];"
                 : "=r"(r[0]), "=r"(r[1]), "=r"(r[2]), "=r"(r[3]) : "r"(addr));
}
static __device__ __forceinline__ void ldmx2(uint32_t* r, uint32_t addr) {
    asm volatile("ldmatrix.sync.aligned.m8n8.x2.shared.b16 {%0,%1}, [%2];"
                 : "=r"(r[0]), "=r"(r[1]) : "r"(addr));
}
static __device__ __forceinline__ void mma16816(float* d, const uint32_t* a, const uint32_t* b) {
    asm volatile("mma.sync.aligned.m16n8k16.row.col.f32.bf16.bf16.f32 "
                 "{%0,%1,%2,%3}, {%4,%5,%6,%7}, {%8,%9}, {%0,%1,%2,%3};"
                 : "+f"(d[0]), "+f"(d[1]), "+f"(d[2]), "+f"(d[3])
                 : "r"(a[0]), "r"(a[1]), "r"(a[2]), "r"(a[3]), "r"(b[0]), "r"(b[1]));
}

// =====================================================================
// Kernel 0: split packed weights into bf16 hi/lo, transposed to [n][k].
// n: 0-255 = w_ab_g, 256-511 = w_ab_p, 512-639 = w_g
// =====================================================================
__global__ void __launch_bounds__(256) k0_wsplit(
    const float* __restrict__ w_ab_g, const float* __restrict__ w_ab_p,
    const float* __restrict__ w_g)
{
    int idx = blockIdx.x * 256 + threadIdx.x;   // 320 blocks
    if (idx >= 640 * 128) return;
    int n = idx >> 7, k = idx & 127;
    float v;
    if (n < 256)      v = w_ab_g[k * 256 + n];
    else if (n < 512) v = w_ab_p[k * 256 + (n - 256)];
    else              v = w_g[k * 128 + (n - 512)];
    __nv_bfloat16 h = __float2bfloat16(v);
    g_wH[idx] = h;
    g_wL[idx] = __float2bfloat16(v - __bfloat162float(h));
}

// =====================================================================
// Kernel 1: LN(z) + projections on tensor cores (bf16 hi/lo 3-pass).
// 2048 CTAs x 128 rows, 256 thr (8 warps: 4m x 2n), warp tile 32x64.
// Chunks (n-offset into packed 640): {0(Ga),256(Pa),128(Gb),384(Pb),512(gate)}
// =====================================================================
#define RSTR  132                     // fp32 z stride
#define ASTR  136                     // bf16 stride (272 B rows)
#define OFF_ZU 0                      // 69632 B: z fp32 / sigmoid stash
#define OFF_AH 69632                  // 34816 B
#define OFF_AL (OFF_AH + 34816)
#define OFF_WH (OFF_AL + 34816)       // also transpose staging H
#define OFF_WL (OFF_WH + 34816)       // also transpose staging L
#define K1_SMEM (OFF_WL + 34816)      // 208896 B

__global__ void __launch_bounds__(256, 1) k1_mma(
    const float* __restrict__ z, const float* __restrict__ mask,
    const float* __restrict__ b_ab_p, const float* __restrict__ b_ab_g,
    const float* __restrict__ b_g,
    const float* __restrict__ ln_g,  const float* __restrict__ ln_b)
{
    extern __shared__ char smem[];
    const uint32_t sbase = smem_u32(smem);
    float* zS = (float*)smem;                       // [128][RSTR]
    const int t   = threadIdx.x;
    const int lid = t & 31;
    const int w   = t >> 5;
    const int wm  = w >> 1;            // 0..3
    const int wn  = w & 1;             // 0..1
    const int r0  = blockIdx.x * 128;
    const int i0  = r0 >> 9;
    const int k0  = r0 & 511;

    // ---- phase 1: load z tile fp32 ----
    #pragma unroll
    for (int p = 0; p < 16; ++p) {
        int idx = p * 256 + t;
        int row = idx >> 5, c4 = idx & 31;
        cp16(sbase + OFF_ZU + row * (RSTR*4) + c4 * 16,
             z + (size_t)(r0 + row) * CZ + c4 * 4);
    }
    cp_commit(); cp_wait0();
    __syncthreads();

    // ---- phase 2: LN + convert to bf16 hi/lo (2 threads per row) ----
    {
        const int row = t >> 1, half = t & 1;
        const float* zr = zS + row * RSTR + half * 64;
        float s = 0.f, s2 = 0.f;
        #pragma unroll
        for (int q = 0; q < 16; ++q) {
            float4 v = *(const float4*)(zr + q * 4);
            s  += v.x + v.y + v.z + v.w;
            s2 += v.x*v.x + v.y*v.y + v.z*v.z + v.w*v.w;
        }
        s  += __shfl_xor_sync(0xffffffffu, s, 1);
        s2 += __shfl_xor_sync(0xffffffffu, s2, 1);
        float mu  = s * (1.0f/128.0f);
        float var = fmaxf(s2 * (1.0f/128.0f) - mu*mu, 0.f);
        float rs  = rsqrtf(var + EPSV);

        __nv_bfloat16* aH = (__nv_bfloat16*)(smem + OFF_AH) + row * ASTR + half * 64;
        __nv_bfloat16* aL = (__nv_bfloat16*)(smem + OFF_AL) + row * ASTR + half * 64;
        #pragma unroll
        for (int q8 = 0; q8 < 8; ++q8) {
            __align__(16) __nv_bfloat16 hb[8], lb[8];
            #pragma unroll
            for (int j = 0; j < 8; ++j) {
                int c = half * 64 + q8 * 8 + j;
                float v = (zr[q8*8 + j] - mu) * rs * __ldg(ln_g + c) + __ldg(ln_b + c);
                __nv_bfloat16 h = __float2bfloat16(v);
                hb[j] = h;
                lb[j] = __float2bfloat16(v - __bfloat162float(h));
            }
            *(uint4*)(aH + q8*8) = *(uint4*)hb;
            *(uint4*)(aL + q8*8) = *(uint4*)lb;
        }
    }
    __syncthreads();

    // ldmatrix lane offsets (bytes)
    const int quad = lid >> 3;
    const int l7   = lid & 7;
    uint32_t aoff[2];
    #pragma unroll
    for (int mf = 0; mf < 2; ++mf) {
        int r = wm*32 + mf*16 + (quad & 1)*8 + l7;
        aoff[mf] = (r * ASTR + (quad >> 1) * 8) * 2;
    }
    uint32_t boff[4];   // x4 B: pairs of n-frags
    #pragma unroll
    for (int nf2 = 0; nf2 < 4; ++nf2) {
        int r = wn*64 + nf2*16 + (quad & 1)*8 + l7;
        boff[nf2] = (r * ASTR + (quad >> 1) * 8) * 2;
    }

    const int noff[5] = {0, 256, 128, 384, 512};

    for (int ci = 0; ci < 5; ++ci) {
        __syncthreads();   // staging reads / prior mma done before overwriting W
        // ---- load weight chunk [128 n][128 k] bf16 hi/lo ----
        #pragma unroll
        for (int p = 0; p < 8; ++p) {
            int idx = p * 256 + t;
            int n = idx >> 4, seg = idx & 15;
            const __nv_bfloat16* sh = g_wH + (size_t)(noff[ci] + n) * 128 + seg * 8;
            const __nv_bfloat16* sl = g_wL + (size_t)(noff[ci] + n) * 128 + seg * 8;
            cp16(sbase + OFF_WH + n * (ASTR*2) + seg * 16, sh);
            cp16(sbase + OFF_WL + n * (ASTR*2) + seg * 16, sl);
        }
        cp_commit(); cp_wait0();
        __syncthreads();

        // ---- mma: 3-pass hi/lo ----
        float acc[2][8][4];
        #pragma unroll
        for (int mf = 0; mf < 2; ++mf)
            #pragma unroll
            for (int nf = 0; nf < 8; ++nf)
                #pragma unroll
                for (int q = 0; q < 4; ++q) acc[mf][nf][q] = 0.f;

        #pragma unroll
        for (int ks = 0; ks < 128; ks += 16) {
            uint32_t ah[2][4], al[2][4], bh[8][2], bl[8][2];
            #pragma unroll
            for (int mf = 0; mf < 2; ++mf) ldmx4(ah[mf], sbase + OFF_AH + aoff[mf] + ks*2);
            #pragma unroll
            for (int mf = 0; mf < 2; ++mf) ldmx4(al[mf], sbase + OFF_AL + aoff[mf] + ks*2);
            #pragma unroll
            for (int nf2 = 0; nf2 < 4; ++nf2) {
                uint32_t r4[4];
                ldmx4(r4, sbase + OFF_WH + boff[nf2] + ks*2);
                bh[nf2*2][0]   = r4[0]; bh[nf2*2][1]   = r4[2];
                bh[nf2*2+1][0] = r4[1]; bh[nf2*2+1][1] = r4[3];
                ldmx4(r4, sbase + OFF_WL + boff[nf2] + ks*2);
                bl[nf2*2][0]   = r4[0]; bl[nf2*2][1]   = r4[2];
                bl[nf2*2+1][0] = r4[1]; bl[nf2*2+1][1] = r4[3];
            }
            #pragma unroll
            for (int mf = 0; mf < 2; ++mf)
                #pragma unroll
                for (int nf = 0; nf < 8; ++nf)
                    mma16816(acc[mf][nf], ah[mf], bh[nf]);
            #pragma unroll
            for (int mf = 0; mf < 2; ++mf)
                #pragma unroll
                for (int nf = 0; nf < 8; ++nf)
                    mma16816(acc[mf][nf], ah[mf], bl[nf]);
            #pragma unroll
            for (int mf = 0; mf < 2; ++mf)
                #pragma unroll
                for (int nf = 0; nf < 8; ++nf)
                    mma16816(acc[mf][nf], al[mf], bh[nf]);
        }

        const int cbase = (ci == 2 || ci == 3) ? 128 : 0;
        const int rA = wm*32 + (lid >> 2);          // local row of d0/d1
        const int cA = wn*64 + (lid & 3)*2;         // local col of d0

        if (ci == 0 || ci == 2) {
            // G chunk: sigmoid(acc + b_ab_g) -> fp32 stash in zU (same-thread readback)
            #pragma unroll
            for (int mf = 0; mf < 2; ++mf)
                #pragma unroll
                for (int nf = 0; nf < 8; ++nf) {
                    int cc = cA + nf*8;
                    float bg0 = __ldg(b_ab_g + cbase + cc);
                    float bg1 = __ldg(b_ab_g + cbase + cc + 1);
                    int rr0 = rA + mf*16, rr1 = rr0 + 8;
                    zS[rr0*RSTR + cc]     = 1.f/(1.f + __expf(-(acc[mf][nf][0] + bg0)));
                    zS[rr0*RSTR + cc + 1] = 1.f/(1.f + __expf(-(acc[mf][nf][1] + bg1)));
                    zS[rr1*RSTR + cc]     = 1.f/(1.f + __expf(-(acc[mf][nf][2] + bg0)));
                    zS[rr1*RSTR + cc + 1] = 1.f/(1.f + __expf(-(acc[mf][nf][3] + bg1)));
                }
        } else if (ci == 1 || ci == 3) {
            // P chunk: val = mask * stash * (acc + b_ab_p); transpose-stage bf16 hi/lo
            __syncthreads();   // all warps done reading W before staging overwrites it
            __nv_bfloat16* stH = (__nv_bfloat16*)(smem + OFF_WH);
            __nv_bfloat16* stL = (__nv_bfloat16*)(smem + OFF_WL);
            #pragma unroll
            for (int mf = 0; mf < 2; ++mf) {
                int rr0 = rA + mf*16, rr1 = rr0 + 8;
                float m0v = __ldg(mask + r0 + rr0);
                float m1v = __ldg(mask + r0 + rr1);
                #pragma unroll
                for (int nf = 0; nf < 8; ++nf) {
                    int cc = cA + nf*8;
                    float bp0 = __ldg(b_ab_p + cbase + cc);
                    float bp1 = __ldg(b_ab_p + cbase + cc + 1);
                    float v00 = m0v * zS[rr0*RSTR + cc]     * (acc[mf][nf][0] + bp0);
                    float v01 = m0v * zS[rr0*RSTR + cc + 1] * (acc[mf][nf][1] + bp1);
                    float v10 = m1v * zS[rr1*RSTR + cc]     * (acc[mf][nf][2] + bp0);
                    float v11 = m1v * zS[rr1*RSTR + cc + 1] * (acc[mf][nf][3] + bp1);
                    __nv_bfloat16 h;
                    h = __float2bfloat16(v00); stH[cc*ASTR + rr0] = h;
                    stL[cc*ASTR + rr0] = __float2bfloat16(v00 - __bfloat162float(h));
                    h = __float2bfloat16(v01); stH[(cc+1)*ASTR + rr0] = h;
                    stL[(cc+1)*ASTR + rr0] = __float2bfloat16(v01 - __bfloat162float(h));
                    h = __float2bfloat16(v10); stH[cc*ASTR + rr1] = h;
                    stL[cc*ASTR + rr1] = __float2bfloat16(v10 - __bfloat162float(h));
                    h = __float2bfloat16(v11); stH[(cc+1)*ASTR + rr1] = h;
                    stL[(cc+1)*ASTR + rr1] = __float2bfloat16(v11 - __bfloat162float(h));
                }
            }
            __syncthreads();
            // coalesced c-major global write
            __nv_bfloat16* dH = (ci == 1) ? g_ah : g_bh;
            __nv_bfloat16* dL = (ci == 1) ? g_al : g_bl;
            const int ccc = t >> 1, half = t & 1;
            size_t off = (size_t)ccc * NR + (size_t)i0 * NN + k0 + half * 64;
            const __nv_bfloat16* sH = stH + ccc * ASTR + half * 64;
            const __nv_bfloat16* sL = stL + ccc * ASTR + half * 64;
            #pragma unroll
            for (int q = 0; q < 8; ++q) {
                *(uint4*)(dH + off + q*8) = *(const uint4*)(sH + q*8);
                *(uint4*)(dL + off + q*8) = *(const uint4*)(sL + q*8);
            }
        } else {
            // gate chunk: sigmoid -> fp32 row-major g_gate
            #pragma unroll
            for (int mf = 0; mf < 2; ++mf) {
                int rr0 = rA + mf*16, rr1 = rr0 + 8;
                #pragma unroll
                for (int nf = 0; nf < 8; ++nf) {
                    int cc = cA + nf*8;
                    float bg0 = __ldg(b_g + cc);
                    float bg1 = __ldg(b_g + cc + 1);
                    float2 v0, v1;
                    v0.x = 1.f/(1.f + __expf(-(acc[mf][nf][0] + bg0)));
                    v0.y = 1.f/(1.f + __expf(-(acc[mf][nf][1] + bg1)));
                    v1.x = 1.f/(1.f + __expf(-(acc[mf][nf][2] + bg0)));
                    v1.y = 1.f/(1.f + __expf(-(acc[mf][nf][3] + bg1)));
                    *(float2*)(g_gate + (size_t)(r0 + rr0) * CZ + cc) = v0;
                    *(float2*)(g_gate + (size_t)(r0 + rr1) * CZ + cc) = v1;
                }
            }
        }
    }
}

// =====================================================================
// Kernel 2: einsum via mma.sync bf16 3-pass split (unchanged from R4).
// =====================================================================
#define KC     32
#define STR    40
#define TILE_E (128*STR)
#define BUF_E  (4*TILE_E)
#define K2_SMEM (2 * BUF_E * 2)

__global__ void __launch_bounds__(512) k2_einsum_mma() {
    extern __shared__ __nv_bfloat16 sb[];
    const uint32_t sbase = smem_u32(sb);

    const int t   = threadIdx.x;
    const int lid = t & 31;
    const int w   = t >> 5;
    const int wm  = w >> 2;
    const int wn  = w & 3;
    const int c   = blockIdx.z;
    const int m0  = blockIdx.y * 128;
    const int n0  = blockIdx.x * 128;

    const __nv_bfloat16* pAh = g_ah + (size_t)c * NR;
    const __nv_bfloat16* pAl = g_al + (size_t)c * NR;
    const __nv_bfloat16* pBh = g_bh + (size_t)c * NR;
    const __nv_bfloat16* pBl = g_bl + (size_t)c * NR;

    const int grow = t >> 2;
    const int gseg = t & 3;
    const size_t gA0 = (size_t)(m0 + grow) * NN + gseg * 8;
    const size_t gB0 = (size_t)(n0 + grow) * NN + gseg * 8;
    const uint32_t sw = (grow * STR + gseg * 8) * 2;

    const int quad = lid >> 3;
    const int l7   = lid & 7;
    uint32_t aoff[2];
    #pragma unroll
    for (int mf = 0; mf < 2; ++mf) {
        int r = wm*32 + mf*16 + (quad & 1)*8 + l7;
        aoff[mf] = (r * STR + (quad >> 1) * 8) * 2;
    }
    uint32_t boff[4];
    #pragma unroll
    for (int nf = 0; nf < 4; ++nf) {
        int r = wn*32 + nf*8 + l7;
        boff[nf] = (r * STR + ((lid >> 3) & 1) * 8) * 2;
    }

    float d[2][4][4];
    #pragma unroll
    for (int mf = 0; mf < 2; ++mf)
        #pragma unroll
        for (int nf = 0; nf < 4; ++nf)
            #pragma unroll
            for (int q = 0; q < 4; ++q) d[mf][nf][q] = 0.f;

    {
        uint32_t b0 = sbase;
        cp16(b0 + 0*TILE_E*2 + sw, pAh + gA0);
        cp16(b0 + 1*TILE_E*2 + sw, pAl + gA0);
        cp16(b0 + 2*TILE_E*2 + sw, pBh + gB0);
        cp16(b0 + 3*TILE_E*2 + sw, pBl + gB0);
        cp_commit();
    }

    for (int ch = 0; ch < 16; ++ch) {
        if (ch < 15) {
            uint32_t bb = sbase + ((ch + 1) & 1) * BUF_E * 2;
            int kk = (ch + 1) * KC;
            cp16(bb + 0*TILE_E*2 + sw, pAh + gA0 + kk);
            cp16(bb + 1*TILE_E*2 + sw, pAl + gA0 + kk);
            cp16(bb + 2*TILE_E*2 + sw, pBh + gB0 + kk);
            cp16(bb + 3*TILE_E*2 + sw, pBl + gB0 + kk);
            cp_commit();
            cp_wait1();
        } else {
            cp_wait0();
        }
        __syncthreads();

        const uint32_t bb = sbase + (ch & 1) * BUF_E * 2;
        const uint32_t bAH = bb;
        const uint32_t bAL = bb + TILE_E*2;
        const uint32_t bBH = bb + 2*TILE_E*2;
        const uint32_t bBL = bb + 3*TILE_E*2;

        #pragma unroll
        for (int ks = 0; ks < KC; ks += 16) {
            uint32_t ah[2][4], al[2][4], bh[4][2], bl[4][2];
            #pragma unroll
            for (int mf = 0; mf < 2; ++mf) ldmx4(ah[mf], bAH + aoff[mf] + ks*2);
            #pragma unroll
            for (int nf = 0; nf < 4; ++nf) ldmx2(bh[nf], bBH + boff[nf] + ks*2);
            #pragma unroll
            for (int nf = 0; nf < 4; ++nf) ldmx2(bl[nf], bBL + boff[nf] + ks*2);
            #pragma unroll
            for (int mf = 0; mf < 2; ++mf)
                #pragma unroll
                for (int nf = 0; nf < 4; ++nf)
                    mma16816(d[mf][nf], ah[mf], bh[nf]);
            #pragma unroll
            for (int mf = 0; mf < 2; ++mf)
                #pragma unroll
                for (int nf = 0; nf < 4; ++nf)
                    mma16816(d[mf][nf], ah[mf], bl[nf]);
            #pragma unroll
            for (int mf = 0; mf < 2; ++mf) ldmx4(al[mf], bAL + aoff[mf] + ks*2);
            #pragma unroll
            for (int mf = 0; mf < 2; ++mf)
                #pragma unroll
                for (int nf = 0; nf < 4; ++nf)
                    mma16816(d[mf][nf], al[mf], bh[nf]);
        }
        __syncthreads();
    }

    float* X = g_x + (size_t)c * NR;
    const int rb = m0 + wm*32 + (lid >> 2);
    const int cb = n0 + wn*32 + (lid & 3) * 2;
    #pragma unroll
    for (int mf = 0; mf < 2; ++mf)
        #pragma unroll
        for (int nf = 0; nf < 4; ++nf) {
            int row = rb + mf*16;
            int col = cb + nf*8;
            *(float2*)(X + (size_t)row * NN + col) =
                make_float2(d[mf][nf][0], d[mf][nf][1]);
            *(float2*)(X + (size_t)(row + 8) * NN + col) =
                make_float2(d[mf][nf][2], d[mf][nf][3]);
        }
}

// =====================================================================
// Kernel 3: gather x (c-major) -> LN over c -> @ w_z + b_z -> * gate -> out
// =====================================================================
__global__ void __launch_bounds__(256) k3_final(
    const float* __restrict__ w_z, const float* __restrict__ b_z,
    const float* __restrict__ ln_g, const float* __restrict__ ln_b,
    float* __restrict__ out)
{
    extern __shared__ float sm[];
    float* xS   = sm;
    float* wS   = sm + 128 * ZPAD;
    float* sum1 = wS + 128 * WPAD;
    float* sum2 = sum1 + 256;
    float* muS  = sum2 + 256;
    float* rsS  = muS + 64;

    const int t  = threadIdx.x;
    const int r0 = blockIdx.x * 64;
    const int i0 = r0 >> 9;
    const int j0 = r0 & 511;

    {
        const int joff = t & 63, part = t >> 6;
        const float* src = g_x + (size_t)(part*32) * NR + (size_t)i0 * NN + j0 + joff;
        #pragma unroll 8
        for (int q = 0; q < 32; ++q)
            xS[(part*32 + q) * ZPAD + joff] = src[(size_t)q * NR];
    }
    #pragma unroll
    for (int pass = 0; pass < 16; ++pass) {
        int idx = pass*256 + t;
        int wr = idx >> 5, wc4 = idx & 31;
        *(float4*)(wS + wr*WPAD + wc4*4) = *(const float4*)(w_z + wr*CZ + wc4*4);
    }
    __syncthreads();

    {
        const int row  = t & 63;
        const int part = t >> 6;
        float s = 0.f, s2 = 0.f;
        #pragma unroll
        for (int q = 0; q < 32; ++q) {
            float v = xS[(part*32 + q) * ZPAD + row];
            s += v; s2 += v * v;
        }
        sum1[part*64 + row] = s;
        sum2[part*64 + row] = s2;
        __syncthreads();
        if (part == 0) {
            float ts  = sum1[row] + sum1[64+row] + sum1[128+row] + sum1[192+row];
            float ts2 = sum2[row] + sum2[64+row] + sum2[128+row] + sum2[192+row];
            float mu  = ts * (1.0f/128.0f);
            float var = fmaxf(ts2 * (1.0f/128.0f) - mu*mu, 0.f);
            muS[row] = mu;
            rsS[row] = rsqrtf(var + EPSV);
        }
        __syncthreads();
        const float mu = muS[row], rs = rsS[row];
        #pragma unroll
        for (int q = 0; q < 32; ++q) {
            int cch = part*32 + q;
            xS[cch*ZPAD + row] = (xS[cch*ZPAD + row] - mu) * rs * ln_g[cch] + ln_b[cch];
        }
    }
    __syncthreads();

    const int tx = t & 15, ty = t >> 4;
    float acc[4][8];
    #pragma unroll
    for (int m = 0; m < 4; ++m)
        #pragma unroll
        for (int n = 0; n < 8; ++n) acc[m][n] = 0.f;

    #pragma unroll 4
    for (int k = 0; k < 128; ++k) {
        float4 a  = *(const float4*)(xS + k*ZPAD + ty*4);
        float4 b0 = *(const float4*)(wS + k*WPAD + tx*8);
        float4 b1 = *(const float4*)(wS + k*WPAD + tx*8 + 4);
        float av[4] = {a.x, a.y, a.z, a.w};
        float bv[8] = {b0.x,b0.y,b0.z,b0.w,b1.x,b1.y,b1.z,b1.w};
        #pragma unroll
        for (int m = 0; m < 4; ++m)
            #pragma unroll
            for (int n = 0; n < 8; ++n)
                acc[m][n] += av[m] * bv[n];
    }

    float4 bz0 = *(const float4*)(b_z + tx*8);
    float4 bz1 = *(const float4*)(b_z + tx*8 + 4);
    #pragma unroll
    for (int ii = 0; ii < 4; ++ii) {
        int r = r0 + ty*4 + ii;
        float4 gg0 = *(const float4*)(g_gate + (size_t)r * CZ + tx*8);
        float4 gg1 = *(const float4*)(g_gate + (size_t)r * CZ + tx*8 + 4);
        float4 v0, v1;
        v0.x = (acc[ii][0] + bz0.x) * gg0.x;
        v0.y = (acc[ii][1] + bz0.y) * gg0.y;
        v0.z = (acc[ii][2] + bz0.z) * gg0.z;
        v0.w = (acc[ii][3] + bz0.w) * gg0.w;
        v1.x = (acc[ii][4] + bz1.x) * gg1.x;
        v1.y = (acc[ii][5] + bz1.y) * gg1.y;
        v1.z = (acc[ii][6] + bz1.z) * gg1.z;
        v1.w = (acc[ii][7] + bz1.w) * gg1.w;
        *(float4*)(out + (size_t)r * CZ + tx*8)     = v0;
        *(float4*)(out + (size_t)r * CZ + tx*8 + 4) = v1;
    }
}

// =====================================================================
extern "C" void kernel_launch(void* const* d_in, const int* in_sizes, int n_in,
                              void* d_out, int out_size) {
    const float* z       = (const float*)d_in[0];
    const float* mask    = (const float*)d_in[1];
    const float* w_ab_p  = (const float*)d_in[2];
    const float* b_ab_p  = (const float*)d_in[3];
    const float* w_ab_g  = (const float*)d_in[4];
    const float* b_ab_g  = (const float*)d_in[5];
    const float* w_g     = (const float*)d_in[6];
    const float* b_g     = (const float*)d_in[7];
    const float* w_z     = (const float*)d_in[8];
    const float* b_z     = (const float*)d_in[9];
    const float* ln_in_g = (const float*)d_in[10];
    const float* ln_in_b = (const float*)d_in[11];
    const float* ln_out_g= (const float*)d_in[12];
    const float* ln_out_b= (const float*)d_in[13];
    float* out = (float*)d_out;

    const int SM3 = (128 * ZPAD + 128 * WPAD + 640) * (int)sizeof(float);
    cudaFuncSetAttribute(k1_mma,        cudaFuncAttributeMaxDynamicSharedMemorySize, K1_SMEM);
    cudaFuncSetAttribute(k2_einsum_mma, cudaFuncAttributeMaxDynamicSharedMemorySize, K2_SMEM);
    cudaFuncSetAttribute(k3_final,      cudaFuncAttributeMaxDynamicSharedMemorySize, SM3);

    k0_wsplit<<<320, 256>>>(w_ab_g, w_ab_p, w_g);
    k1_mma<<<NR / 128, 256, K1_SMEM>>>(z, mask, b_ab_p, b_ab_g, b_g,
                                       ln_in_g, ln_in_b);
    k2_einsum_mma<<<dim3(4, 4, 128), 512, K2_SMEM>>>();
    k3_final<<<NR / 64, 256, SM3>>>(w_z, b_z, ln_out_g, ln_out_b, out);
}

// round 7
// speedup vs baseline: 1.8021x; 1.1876x over previous
#include <cuda_runtime.h>
#include <cuda_bf16.h>
#include <math.h>
#include <cstdint>

#define NN   512
#define CZ   128
#define NR   (NN*NN)          // 262144
#define WPAD 132
#define ZPAD 68
#define EPSV 1e-5f

// ---------------- scratch (device globals; alloc-free) ----------------
__device__ __nv_bfloat16 g_ah[(size_t)CZ * NR];   // a hi [c][i][k]
__device__ __nv_bfloat16 g_al[(size_t)CZ * NR];   // a lo
__device__ __nv_bfloat16 g_bh[(size_t)CZ * NR];   // b hi [c][j][k]
__device__ __nv_bfloat16 g_bl[(size_t)CZ * NR];   // b lo
__device__ float g_gate[(size_t)NR * CZ];         // gate[r][c]
__device__ float g_x[(size_t)CZ * NR];            // x[c][i][j]
__device__ __nv_bfloat16 g_wH[640 * 128];         // packed weights hi [n][k]
__device__ __nv_bfloat16 g_wL[640 * 128];         // packed weights lo [n][k]

static __device__ __forceinline__ uint32_t smem_u32(const void* p) {
    return (uint32_t)__cvta_generic_to_shared(p);
}
static __device__ __forceinline__ void cp16(uint32_t dst, const void* src) {
    asm volatile("cp.async.cg.shared.global [%0], [%1], 16;" :: "r"(dst), "l"(src));
}
static __device__ __forceinline__ void cp_commit() {
    asm volatile("cp.async.commit_group;" ::: "memory");
}
static __device__ __forceinline__ void cp_wait1() {
    asm volatile("cp.async.wait_group 1;" ::: "memory");
}
static __device__ __forceinline__ void cp_wait0() {
    asm volatile("cp.async.wait_group 0;" ::: "memory");
}
static __device__ __forceinline__ void ldmx4(uint32_t* r, uint32_t addr) {
    asm volatile("ldmatrix.sync.aligned.m8n8.x4.shared.b16 {%0,%1,%2,%3}, [%4];"
                 : "=r"(r[0]), "=r"(r[1]), "=r"(r[2]), "=r"(r[3]) : "r"(addr));
}
static __device__ __forceinline__ void ldmx2(uint32_t* r, uint32_t addr) {
    asm volatile("ldmatrix.sync.aligned.m8n8.x2.shared.b16 {%0,%1}, [%2];"
                 : "=r"(r[0]), "=r"(r[1]) : "r"(addr));
}
static __device__ __forceinline__ void mma16816(float* d, const uint32_t* a, const uint32_t* b) {
    asm volatile("mma.sync.aligned.m16n8k16.row.col.f32.bf16.bf16.f32 "
                 "{%0,%1,%2,%3}, {%4,%5,%6,%7}, {%8,%9}, {%0,%1,%2,%3};"
                 : "+f"(d[0]), "+f"(d[1]), "+f"(d[2]), "+f"(d[3])
                 : "r"(a[0]), "r"(a[1]), "r"(a[2]), "r"(a[3]), "r"(b[0]), "r"(b[1]));
}
static __device__ __forceinline__ uint32_t packHL(float v) {
    __nv_bfloat16 h = __float2bfloat16(v);
    __nv_bfloat16 l = __float2bfloat16(v - __bfloat162float(h));
    return (uint32_t)__bfloat16_as_ushort(h) | ((uint32_t)__bfloat16_as_ushort(l) << 16);
}

// =====================================================================
// Kernel 0: split packed weights into bf16 hi/lo, transposed to [n][k].
// n: 0-255 = w_ab_g, 256-511 = w_ab_p, 512-639 = w_g
// =====================================================================
__global__ void __launch_bounds__(256) k0_wsplit(
    const float* __restrict__ w_ab_g, const float* __restrict__ w_ab_p,
    const float* __restrict__ w_g)
{
    int idx = blockIdx.x * 256 + threadIdx.x;
    if (idx >= 640 * 128) return;
    int n = idx >> 7, k = idx & 127;
    float v;
    if (n < 256)      v = w_ab_g[k * 256 + n];
    else if (n < 512) v = w_ab_p[k * 256 + (n - 256)];
    else              v = w_g[k * 128 + (n - 512)];
    __nv_bfloat16 h = __float2bfloat16(v);
    g_wH[idx] = h;
    g_wL[idx] = __float2bfloat16(v - __bfloat162float(h));
}

// =====================================================================
// Kernel 1 (v2): LN(z) + projections, mma.sync bf16 hi/lo 3-pass.
// 4096 CTAs x 64 rows, 256 thr (8 warps: 2m x 4n), warp tile 32x16.
// 10 weight chunks of 64 cols, G/P paired -> sigmoid stash in REGISTERS.
// smem 103.4 KB -> 2 CTAs/SM for cross-CTA overlap.
// =====================================================================
#define ASTR   136
#define OFF_ST 0                       // 33792 B: z fp32 -> (hi,lo) u32 staging
#define OFF_AH 33792                   // 17408 B
#define OFF_AL 51200                   // 17408 B
#define OFF_WH 68608                   // 17408 B
#define OFF_WL 86016                   // 17408 B
#define K1_SMEM 103424

__global__ void __launch_bounds__(256, 2) k1_mma(
    const float* __restrict__ z, const float* __restrict__ mask,
    const float* __restrict__ b_ab_p, const float* __restrict__ b_ab_g,
    const float* __restrict__ b_g,
    const float* __restrict__ ln_g,  const float* __restrict__ ln_b)
{
    extern __shared__ char smem[];
    const uint32_t sbase = smem_u32(smem);
    const int t   = threadIdx.x;
    const int lid = t & 31;
    const int w   = t >> 5;
    const int wm  = w >> 2;            // 0..1  (32 rows each)
    const int wn  = w & 3;             // 0..3  (16 cols each)
    const int r0  = blockIdx.x * 64;

    // ---- phase 1: z tile (64x128 fp32) into staging, stride 132 ----
    #pragma unroll
    for (int p = 0; p < 8; ++p) {
        int idx = p * 256 + t;
        int row = idx >> 5, c4 = idx & 31;
        cp16(sbase + OFF_ST + row * 528 + c4 * 16,
             z + (size_t)(r0 + row) * CZ + c4 * 4);
    }
    cp_commit(); cp_wait0();
    __syncthreads();

    // ---- phase 2: LN (4 thr/row) -> AH/AL bf16 hi/lo ----
    {
        const int row = t >> 2, qt = t & 3;
        const float* zr = (const float*)smem + row * 132 + qt * 32;
        float s = 0.f, s2 = 0.f;
        #pragma unroll
        for (int q = 0; q < 8; ++q) {
            float4 v = *(const float4*)(zr + q * 4);
            s  += v.x + v.y + v.z + v.w;
            s2 += v.x*v.x + v.y*v.y + v.z*v.z + v.w*v.w;
        }
        s  += __shfl_xor_sync(0xffffffffu, s, 1);
        s2 += __shfl_xor_sync(0xffffffffu, s2, 1);
        s  += __shfl_xor_sync(0xffffffffu, s, 2);
        s2 += __shfl_xor_sync(0xffffffffu, s2, 2);
        float mu  = s * (1.0f/128.0f);
        float var = fmaxf(s2 * (1.0f/128.0f) - mu*mu, 0.f);
        float rs  = rsqrtf(var + EPSV);

        __nv_bfloat16* aH = (__nv_bfloat16*)(smem + OFF_AH) + row * ASTR;
        __nv_bfloat16* aL = (__nv_bfloat16*)(smem + OFF_AL) + row * ASTR;
        #pragma unroll
        for (int q8 = 0; q8 < 4; ++q8) {
            __align__(16) __nv_bfloat16 hb[8], lb[8];
            #pragma unroll
            for (int j = 0; j < 8; ++j) {
                int c = qt * 32 + q8 * 8 + j;
                float v = (zr[q8*8 + j] - mu) * rs * __ldg(ln_g + c) + __ldg(ln_b + c);
                __nv_bfloat16 h = __float2bfloat16(v);
                hb[j] = h;
                lb[j] = __float2bfloat16(v - __bfloat162float(h));
            }
            *(uint4*)(aH + qt*32 + q8*8) = *(uint4*)hb;
            *(uint4*)(aL + qt*32 + q8*8) = *(uint4*)lb;
        }
    }

    // ldmatrix lane offsets (bytes)
    const int quad = lid >> 3;
    const int l7   = lid & 7;
    uint32_t aoff[2];
    #pragma unroll
    for (int mf = 0; mf < 2; ++mf) {
        int r = wm*32 + mf*16 + (quad & 1)*8 + l7;
        aoff[mf] = (r * ASTR + (quad >> 1) * 8) * 2;
    }
    const uint32_t boff = ((wn*16 + (quad & 1)*8 + l7) * ASTR + (quad >> 1) * 8) * 2;

    // chunk n-offsets into packed [640]: G/P pairs then gate halves
    const int noff[10] = {0, 256, 64, 320, 128, 384, 192, 448, 512, 576};

    float sig[2][2][4];   // register sigmoid stash (G chunk -> P chunk)

    const int rbase = wm*32 + (lid >> 2);
    const int cbase_w = wn*16 + (lid & 3)*2;

    for (int ci = 0; ci < 10; ++ci) {
        __syncthreads();   // prior mma reads of W / staging reads complete
        // ---- load weight chunk [64 n][128 k] hi+lo ----
        #pragma unroll
        for (int p = 0; p < 4; ++p) {
            int idx = p * 256 + t;
            int n = idx >> 4, seg = idx & 15;
            cp16(sbase + OFF_WH + n * 272 + seg * 16,
                 g_wH + (size_t)(noff[ci] + n) * 128 + seg * 8);
            cp16(sbase + OFF_WL + n * 272 + seg * 16,
                 g_wL + (size_t)(noff[ci] + n) * 128 + seg * 8);
        }
        cp_commit(); cp_wait0();
        __syncthreads();

        // ---- mma: 3-pass hi/lo, warp tile 32x16 ----
        float acc[2][2][4];
        #pragma unroll
        for (int mf = 0; mf < 2; ++mf)
            #pragma unroll
            for (int nf = 0; nf < 2; ++nf)
                #pragma unroll
                for (int q = 0; q < 4; ++q) acc[mf][nf][q] = 0.f;

        #pragma unroll
        for (int ks = 0; ks < 128; ks += 16) {
            uint32_t ah[2][4], al[2][4], bh[2][2], bl[2][2], r4[4];
            ldmx4(ah[0], sbase + OFF_AH + aoff[0] + ks*2);
            ldmx4(ah[1], sbase + OFF_AH + aoff[1] + ks*2);
            ldmx4(al[0], sbase + OFF_AL + aoff[0] + ks*2);
            ldmx4(al[1], sbase + OFF_AL + aoff[1] + ks*2);
            ldmx4(r4, sbase + OFF_WH + boff + ks*2);
            bh[0][0] = r4[0]; bh[0][1] = r4[2];
            bh[1][0] = r4[1]; bh[1][1] = r4[3];
            ldmx4(r4, sbase + OFF_WL + boff + ks*2);
            bl[0][0] = r4[0]; bl[0][1] = r4[2];
            bl[1][0] = r4[1]; bl[1][1] = r4[3];
            #pragma unroll
            for (int mf = 0; mf < 2; ++mf)
                #pragma unroll
                for (int nf = 0; nf < 2; ++nf)
                    mma16816(acc[mf][nf], ah[mf], bh[nf]);
            #pragma unroll
            for (int mf = 0; mf < 2; ++mf)
                #pragma unroll
                for (int nf = 0; nf < 2; ++nf)
                    mma16816(acc[mf][nf], ah[mf], bl[nf]);
            #pragma unroll
            for (int mf = 0; mf < 2; ++mf)
                #pragma unroll
                for (int nf = 0; nf < 2; ++nf)
                    mma16816(acc[mf][nf], al[mf], bh[nf]);
        }

        if (ci >= 8) {
            // ---- gate: sigmoid -> fp32 row-major ----
            const int cb2 = (ci - 8) * 64;
            #pragma unroll
            for (int mf = 0; mf < 2; ++mf) {
                int rr0 = rbase + mf*16, rr1 = rr0 + 8;
                #pragma unroll
                for (int nf = 0; nf < 2; ++nf) {
                    int cc = cbase_w + nf*8;
                    float bg0 = __ldg(b_g + cb2 + cc);
                    float bg1 = __ldg(b_g + cb2 + cc + 1);
                    float2 v0, v1;
                    v0.x = 1.f/(1.f + __expf(-(acc[mf][nf][0] + bg0)));
                    v0.y = 1.f/(1.f + __expf(-(acc[mf][nf][1] + bg1)));
                    v1.x = 1.f/(1.f + __expf(-(acc[mf][nf][2] + bg0)));
                    v1.y = 1.f/(1.f + __expf(-(acc[mf][nf][3] + bg1)));
                    *(float2*)(g_gate + (size_t)(r0 + rr0) * CZ + cb2 + cc) = v0;
                    *(float2*)(g_gate + (size_t)(r0 + rr1) * CZ + cb2 + cc) = v1;
                }
            }
        } else if ((ci & 1) == 0) {
            // ---- G chunk: sigmoid into registers ----
            const float* bg = b_ab_g + noff[ci];
            #pragma unroll
            for (int mf = 0; mf < 2; ++mf)
                #pragma unroll
                for (int nf = 0; nf < 2; ++nf) {
                    int cc = cbase_w + nf*8;
                    float b0 = __ldg(bg + cc), b1 = __ldg(bg + cc + 1);
                    sig[mf][nf][0] = 1.f/(1.f + __expf(-(acc[mf][nf][0] + b0)));
                    sig[mf][nf][1] = 1.f/(1.f + __expf(-(acc[mf][nf][1] + b1)));
                    sig[mf][nf][2] = 1.f/(1.f + __expf(-(acc[mf][nf][2] + b0)));
                    sig[mf][nf][3] = 1.f/(1.f + __expf(-(acc[mf][nf][3] + b1)));
                }
        } else {
            // ---- P chunk: combine, pack (hi,lo) u32, stage transposed ----
            const int p2 = (ci - 1) >> 1;           // 0..3
            const float* bp = b_ab_p + (noff[ci] - 256);
            uint32_t* stg = (uint32_t*)smem;        // [cc][rr] stride 132
            #pragma unroll
            for (int mf = 0; mf < 2; ++mf) {
                int rr0 = rbase + mf*16, rr1 = rr0 + 8;
                float m0 = __ldg(mask + r0 + rr0);
                float m1 = __ldg(mask + r0 + rr1);
                #pragma unroll
                for (int nf = 0; nf < 2; ++nf) {
                    int cc = cbase_w + nf*8;
                    float b0 = __ldg(bp + cc), b1 = __ldg(bp + cc + 1);
                    stg[cc*132 + rr0]     = packHL(m0 * sig[mf][nf][0] * (acc[mf][nf][0] + b0));
                    stg[(cc+1)*132 + rr0] = packHL(m0 * sig[mf][nf][1] * (acc[mf][nf][1] + b1));
                    stg[cc*132 + rr1]     = packHL(m1 * sig[mf][nf][2] * (acc[mf][nf][2] + b0));
                    stg[(cc+1)*132 + rr1] = packHL(m1 * sig[mf][nf][3] * (acc[mf][nf][3] + b1));
                }
            }
            __syncthreads();
            // coalesced c-major global write (16 k's per thread)
            __nv_bfloat16* dH = (p2 < 2) ? g_ah : g_bh;
            __nv_bfloat16* dL = (p2 < 2) ? g_al : g_bl;
            const int cch = (p2 & 1) * 64 + (t >> 2);
            const int rrb = (t & 3) * 16;
            size_t off = (size_t)cch * NR + r0 + rrb;
            const uint32_t* sp = stg + (t >> 2) * 132 + rrb;
            __align__(16) unsigned short hb[16], lb[16];
            #pragma unroll
            for (int i = 0; i < 16; ++i) {
                uint32_t wv = sp[i];
                hb[i] = (unsigned short)(wv & 0xffffu);
                lb[i] = (unsigned short)(wv >> 16);
            }
            *(uint4*)(dH + off)     = *(uint4*)(hb);
            *(uint4*)(dH + off + 8) = *(uint4*)(hb + 8);
            *(uint4*)(dL + off)     = *(uint4*)(lb);
            *(uint4*)(dL + off + 8) = *(uint4*)(lb + 8);
        }
    }
}

// =====================================================================
// Kernel 2: einsum via mma.sync bf16 3-pass split (unchanged).
// =====================================================================
#define KC     32
#define STR    40
#define TILE_E (128*STR)
#define BUF_E  (4*TILE_E)
#define K2_SMEM (2 * BUF_E * 2)

__global__ void __launch_bounds__(512) k2_einsum_mma() {
    extern __shared__ __nv_bfloat16 sb[];
    const uint32_t sbase = smem_u32(sb);

    const int t   = threadIdx.x;
    const int lid = t & 31;
    const int w   = t >> 5;
    const int wm  = w >> 2;
    const int wn  = w & 3;
    const int c   = blockIdx.z;
    const int m0  = blockIdx.y * 128;
    const int n0  = blockIdx.x * 128;

    const __nv_bfloat16* pAh = g_ah + (size_t)c * NR;
    const __nv_bfloat16* pAl = g_al + (size_t)c * NR;
    const __nv_bfloat16* pBh = g_bh + (size_t)c * NR;
    const __nv_bfloat16* pBl = g_bl + (size_t)c * NR;

    const int grow = t >> 2;
    const int gseg = t & 3;
    const size_t gA0 = (size_t)(m0 + grow) * NN + gseg * 8;
    const size_t gB0 = (size_t)(n0 + grow) * NN + gseg * 8;
    const uint32_t sw = (grow * STR + gseg * 8) * 2;

    const int quad = lid >> 3;
    const int l7   = lid & 7;
    uint32_t aoff[2];
    #pragma unroll
    for (int mf = 0; mf < 2; ++mf) {
        int r = wm*32 + mf*16 + (quad & 1)*8 + l7;
        aoff[mf] = (r * STR + (quad >> 1) * 8) * 2;
    }
    uint32_t boff[4];
    #pragma unroll
    for (int nf = 0; nf < 4; ++nf) {
        int r = wn*32 + nf*8 + l7;
        boff[nf] = (r * STR + ((lid >> 3) & 1) * 8) * 2;
    }

    float d[2][4][4];
    #pragma unroll
    for (int mf = 0; mf < 2; ++mf)
        #pragma unroll
        for (int nf = 0; nf < 4; ++nf)
            #pragma unroll
            for (int q = 0; q < 4; ++q) d[mf][nf][q] = 0.f;

    {
        uint32_t b0 = sbase;
        cp16(b0 + 0*TILE_E*2 + sw, pAh + gA0);
        cp16(b0 + 1*TILE_E*2 + sw, pAl + gA0);
        cp16(b0 + 2*TILE_E*2 + sw, pBh + gB0);
        cp16(b0 + 3*TILE_E*2 + sw, pBl + gB0);
        cp_commit();
    }

    for (int ch = 0; ch < 16; ++ch) {
        if (ch < 15) {
            uint32_t bb = sbase + ((ch + 1) & 1) * BUF_E * 2;
            int kk = (ch + 1) * KC;
            cp16(bb + 0*TILE_E*2 + sw, pAh + gA0 + kk);
            cp16(bb + 1*TILE_E*2 + sw, pAl + gA0 + kk);
            cp16(bb + 2*TILE_E*2 + sw, pBh + gB0 + kk);
            cp16(bb + 3*TILE_E*2 + sw, pBl + gB0 + kk);
            cp_commit();
            cp_wait1();
        } else {
            cp_wait0();
        }
        __syncthreads();

        const uint32_t bb = sbase + (ch & 1) * BUF_E * 2;
        const uint32_t bAH = bb;
        const uint32_t bAL = bb + TILE_E*2;
        const uint32_t bBH = bb + 2*TILE_E*2;
        const uint32_t bBL = bb + 3*TILE_E*2;

        #pragma unroll
        for (int ks = 0; ks < KC; ks += 16) {
            uint32_t ah[2][4], al[2][4], bh[4][2], bl[4][2];
            #pragma unroll
            for (int mf = 0; mf < 2; ++mf) ldmx4(ah[mf], bAH + aoff[mf] + ks*2);
            #pragma unroll
            for (int nf = 0; nf < 4; ++nf) ldmx2(bh[nf], bBH + boff[nf] + ks*2);
            #pragma unroll
            for (int nf = 0; nf < 4; ++nf) ldmx2(bl[nf], bBL + boff[nf] + ks*2);
            #pragma unroll
            for (int mf = 0; mf < 2; ++mf)
                #pragma unroll
                for (int nf = 0; nf < 4; ++nf)
                    mma16816(d[mf][nf], ah[mf], bh[nf]);
            #pragma unroll
            for (int mf = 0; mf < 2; ++mf)
                #pragma unroll
                for (int nf = 0; nf < 4; ++nf)
                    mma16816(d[mf][nf], ah[mf], bl[nf]);
            #pragma unroll
            for (int mf = 0; mf < 2; ++mf) ldmx4(al[mf], bAL + aoff[mf] + ks*2);
            #pragma unroll
            for (int mf = 0; mf < 2; ++mf)
                #pragma unroll
                for (int nf = 0; nf < 4; ++nf)
                    mma16816(d[mf][nf], al[mf], bh[nf]);
        }
        __syncthreads();
    }

    float* X = g_x + (size_t)c * NR;
    const int rb = m0 + wm*32 + (lid >> 2);
    const int cb = n0 + wn*32 + (lid & 3) * 2;
    #pragma unroll
    for (int mf = 0; mf < 2; ++mf)
        #pragma unroll
        for (int nf = 0; nf < 4; ++nf) {
            int row = rb + mf*16;
            int col = cb + nf*8;
            *(float2*)(X + (size_t)row * NN + col) =
                make_float2(d[mf][nf][0], d[mf][nf][1]);
            *(float2*)(X + (size_t)(row + 8) * NN + col) =
                make_float2(d[mf][nf][2], d[mf][nf][3]);
        }
}

// =====================================================================
// Kernel 3: gather x (c-major) -> LN over c -> @ w_z + b_z -> * gate -> out
// =====================================================================
__global__ void __launch_bounds__(256) k3_final(
    const float* __restrict__ w_z, const float* __restrict__ b_z,
    const float* __restrict__ ln_g, const float* __restrict__ ln_b,
    float* __restrict__ out)
{
    extern __shared__ float sm[];
    float* xS   = sm;
    float* wS   = sm + 128 * ZPAD;
    float* sum1 = wS + 128 * WPAD;
    float* sum2 = sum1 + 256;
    float* muS  = sum2 + 256;
    float* rsS  = muS + 64;

    const int t  = threadIdx.x;
    const int r0 = blockIdx.x * 64;
    const int i0 = r0 >> 9;
    const int j0 = r0 & 511;

    {
        const int joff = t & 63, part = t >> 6;
        const float* src = g_x + (size_t)(part*32) * NR + (size_t)i0 * NN + j0 + joff;
        #pragma unroll 8
        for (int q = 0; q < 32; ++q)
            xS[(part*32 + q) * ZPAD + joff] = src[(size_t)q * NR];
    }
    #pragma unroll
    for (int pass = 0; pass < 16; ++pass) {
        int idx = pass*256 + t;
        int wr = idx >> 5, wc4 = idx & 31;
        *(float4*)(wS + wr*WPAD + wc4*4) = *(const float4*)(w_z + wr*CZ + wc4*4);
    }
    __syncthreads();

    {
        const int row  = t & 63;
        const int part = t >> 6;
        float s = 0.f, s2 = 0.f;
        #pragma unroll
        for (int q = 0; q < 32; ++q) {
            float v = xS[(part*32 + q) * ZPAD + row];
            s += v; s2 += v * v;
        }
        sum1[part*64 + row] = s;
        sum2[part*64 + row] = s2;
        __syncthreads();
        if (part == 0) {
            float ts  = sum1[row] + sum1[64+row] + sum1[128+row] + sum1[192+row];
            float ts2 = sum2[row] + sum2[64+row] + sum2[128+row] + sum2[192+row];
            float mu  = ts * (1.0f/128.0f);
            float var = fmaxf(ts2 * (1.0f/128.0f) - mu*mu, 0.f);
            muS[row] = mu;
            rsS[row] = rsqrtf(var + EPSV);
        }
        __syncthreads();
        const float mu = muS[row], rs = rsS[row];
        #pragma unroll
        for (int q = 0; q < 32; ++q) {
            int cch = part*32 + q;
            xS[cch*ZPAD + row] = (xS[cch*ZPAD + row] - mu) * rs * ln_g[cch] + ln_b[cch];
        }
    }
    __syncthreads();

    const int tx = t & 15, ty = t >> 4;
    float acc[4][8];
    #pragma unroll
    for (int m = 0; m < 4; ++m)
        #pragma unroll
        for (int n = 0; n < 8; ++n) acc[m][n] = 0.f;

    #pragma unroll 4
    for (int k = 0; k < 128; ++k) {
        float4 a  = *(const float4*)(xS + k*ZPAD + ty*4);
        float4 b0 = *(const float4*)(wS + k*WPAD + tx*8);
        float4 b1 = *(const float4*)(wS + k*WPAD + tx*8 + 4);
        float av[4] = {a.x, a.y, a.z, a.w};
        float bv[8] = {b0.x,b0.y,b0.z,b0.w,b1.x,b1.y,b1.z,b1.w};
        #pragma unroll
        for (int m = 0; m < 4; ++m)
            #pragma unroll
            for (int n = 0; n < 8; ++n)
                acc[m][n] += av[m] * bv[n];
    }

    float4 bz0 = *(const float4*)(b_z + tx*8);
    float4 bz1 = *(const float4*)(b_z + tx*8 + 4);
    #pragma unroll
    for (int ii = 0; ii < 4; ++ii) {
        int r = r0 + ty*4 + ii;
        float4 gg0 = *(const float4*)(g_gate + (size_t)r * CZ + tx*8);
        float4 gg1 = *(const float4*)(g_gate + (size_t)r * CZ + tx*8 + 4);
        float4 v0, v1;
        v0.x = (acc[ii][0] + bz0.x) * gg0.x;
        v0.y = (acc[ii][1] + bz0.y) * gg0.y;
        v0.z = (acc[ii][2] + bz0.z) * gg0.z;
        v0.w = (acc[ii][3] + bz0.w) * gg0.w;
        v1.x = (acc[ii][4] + bz1.x) * gg1.x;
        v1.y = (acc[ii][5] + bz1.y) * gg1.y;
        v1.z = (acc[ii][6] + bz1.z) * gg1.z;
        v1.w = (acc[ii][7] + bz1.w) * gg1.w;
        *(float4*)(out + (size_t)r * CZ + tx*8)     = v0;
        *(float4*)(out + (size_t)r * CZ + tx*8 + 4) = v1;
    }
}

// =====================================================================
extern "C" void kernel_launch(void* const* d_in, const int* in_sizes, int n_in,
                              void* d_out, int out_size) {
    const float* z       = (const float*)d_in[0];
    const float* mask    = (const float*)d_in[1];
    const float* w_ab_p  = (const float*)d_in[2];
    const float* b_ab_p  = (const float*)d_in[3];
    const float* w_ab_g  = (const float*)d_in[4];
    const float* b_ab_g  = (const float*)d_in[5];
    const float* w_g     = (const float*)d_in[6];
    const float* b_g     = (const float*)d_in[7];
    const float* w_z     = (const float*)d_in[8];
    const float* b_z     = (const float*)d_in[9];
    const float* ln_in_g = (const float*)d_in[10];
    const float* ln_in_b = (const float*)d_in[11];
    const float* ln_out_g= (const float*)d_in[12];
    const float* ln_out_b= (const float*)d_in[13];
    float* out = (float*)d_out;

    const int SM3 = (128 * ZPAD + 128 * WPAD + 640) * (int)sizeof(float);
    cudaFuncSetAttribute(k1_mma,        cudaFuncAttributeMaxDynamicSharedMemorySize, K1_SMEM);
    cudaFuncSetAttribute(k2_einsum_mma, cudaFuncAttributeMaxDynamicSharedMemorySize, K2_SMEM);
    cudaFuncSetAttribute(k3_final,      cudaFuncAttributeMaxDynamicSharedMemorySize, SM3);

    k0_wsplit<<<320, 256>>>(w_ab_g, w_ab_p, w_g);
    k1_mma<<<NR / 64, 256, K1_SMEM>>>(z, mask, b_ab_p, b_ab_g, b_g,
                                      ln_in_g, ln_in_b);
    k2_einsum_mma<<<dim3(4, 4, 128), 512, K2_SMEM>>>();
    k3_final<<<NR / 64, 256, SM3>>>(w_z, b_z, ln_out_g, ln_out_b, out);
}

// round 8
// speedup vs baseline: 1.9442x; 1.0788x over previous
#include <cuda_runtime.h>
#include <cuda_bf16.h>
#include <math.h>
#include <cstdint>

#define NN   512
#define CZ   128
#define NR   (NN*NN)          // 262144
#define EPSV 1e-5f

// ---------------- scratch (device globals; alloc-free) ----------------
__device__ __nv_bfloat16 g_ah[(size_t)CZ * NR];   // a hi [c][i][k]
__device__ __nv_bfloat16 g_al[(size_t)CZ * NR];   // a lo
__device__ __nv_bfloat16 g_bh[(size_t)CZ * NR];   // b hi [c][j][k]
__device__ __nv_bfloat16 g_bl[(size_t)CZ * NR];   // b lo
__device__ float g_gate[(size_t)NR * CZ];         // gate[r][c]
__device__ float g_x[(size_t)CZ * NR];            // x[c][i][j]
__device__ __nv_bfloat16 g_wH[768 * 128];         // packed weights hi [n][k]
__device__ __nv_bfloat16 g_wL[768 * 128];         // packed weights lo [n][k]

static __device__ __forceinline__ uint32_t smem_u32(const void* p) {
    return (uint32_t)__cvta_generic_to_shared(p);
}
static __device__ __forceinline__ void cp16(uint32_t dst, const void* src) {
    asm volatile("cp.async.cg.shared.global [%0], [%1], 16;" :: "r"(dst), "l"(src));
}
static __device__ __forceinline__ void cp_commit() {
    asm volatile("cp.async.commit_group;" ::: "memory");
}
static __device__ __forceinline__ void cp_wait1() {
    asm volatile("cp.async.wait_group 1;" ::: "memory");
}
static __device__ __forceinline__ void cp_wait0() {
    asm volatile("cp.async.wait_group 0;" ::: "memory");
}
static __device__ __forceinline__ void ldmx4(uint32_t* r, uint32_t addr) {
    asm volatile("ldmatrix.sync.aligned.m8n8.x4.shared.b16 {%0,%1,%2,%3}, [%4];"
                 : "=r"(r[0]), "=r"(r[1]), "=r"(r[2]), "=r"(r[3]) : "r"(addr));
}
static __device__ __forceinline__ void ldmx2(uint32_t* r, uint32_t addr) {
    asm volatile("ldmatrix.sync.aligned.m8n8.x2.shared.b16 {%0,%1}, [%2];"
                 : "=r"(r[0]), "=r"(r[1]) : "r"(addr));
}
static __device__ __forceinline__ void mma16816(float* d, const uint32_t* a, const uint32_t* b) {
    asm volatile("mma.sync.aligned.m16n8k16.row.col.f32.bf16.bf16.f32 "
                 "{%0,%1,%2,%3}, {%4,%5,%6,%7}, {%8,%9}, {%0,%1,%2,%3};"
                 : "+f"(d[0]), "+f"(d[1]), "+f"(d[2]), "+f"(d[3])
                 : "r"(a[0]), "r"(a[1]), "r"(a[2]), "r"(a[3]), "r"(b[0]), "r"(b[1]));
}
static __device__ __forceinline__ uint32_t packHL(float v) {
    __nv_bfloat16 h = __float2bfloat16(v);
    __nv_bfloat16 l = __float2bfloat16(v - __bfloat162float(h));
    return (uint32_t)__bfloat16_as_ushort(h) | ((uint32_t)__bfloat16_as_ushort(l) << 16);
}

// =====================================================================
// Kernel 0: split weights into bf16 hi/lo, transposed to [n][k].
// n: 0-255 = w_ab_g, 256-511 = w_ab_p, 512-639 = w_g, 640-767 = w_z
// =====================================================================
__global__ void __launch_bounds__(256) k0_wsplit(
    const float* __restrict__ w_ab_g, const float* __restrict__ w_ab_p,
    const float* __restrict__ w_g,   const float* __restrict__ w_z)
{
    int idx = blockIdx.x * 256 + threadIdx.x;   // 384 blocks
    if (idx >= 768 * 128) return;
    int n = idx >> 7, k = idx & 127;
    float v;
    if (n < 256)      v = w_ab_g[k * 256 + n];
    else if (n < 512) v = w_ab_p[k * 256 + (n - 256)];
    else if (n < 640) v = w_g[k * 128 + (n - 512)];
    else              v = w_z[k * 128 + (n - 640)];
    __nv_bfloat16 h = __float2bfloat16(v);
    g_wH[idx] = h;
    g_wL[idx] = __float2bfloat16(v - __bfloat162float(h));
}

// =====================================================================
// Kernel 1 (v2): LN(z) + projections, mma.sync bf16 hi/lo 3-pass.
// 4096 CTAs x 64 rows, 256 thr (8 warps: 2m x 4n), warp tile 32x16.
// =====================================================================
#define ASTR   136
#define OFF_ST 0                       // 33792 B fp32 staging
#define OFF_AH 33792
#define OFF_AL 51200
#define OFF_WH 68608
#define OFF_WL 86016
#define K1_SMEM 103424

__global__ void __launch_bounds__(256, 2) k1_mma(
    const float* __restrict__ z, const float* __restrict__ mask,
    const float* __restrict__ b_ab_p, const float* __restrict__ b_ab_g,
    const float* __restrict__ b_g,
    const float* __restrict__ ln_g,  const float* __restrict__ ln_b)
{
    extern __shared__ char smem[];
    const uint32_t sbase = smem_u32(smem);
    const int t   = threadIdx.x;
    const int lid = t & 31;
    const int w   = t >> 5;
    const int wm  = w >> 2;
    const int wn  = w & 3;
    const int r0  = blockIdx.x * 64;

    #pragma unroll
    for (int p = 0; p < 8; ++p) {
        int idx = p * 256 + t;
        int row = idx >> 5, c4 = idx & 31;
        cp16(sbase + OFF_ST + row * 528 + c4 * 16,
             z + (size_t)(r0 + row) * CZ + c4 * 4);
    }
    cp_commit(); cp_wait0();
    __syncthreads();

    {
        const int row = t >> 2, qt = t & 3;
        const float* zr = (const float*)smem + row * 132 + qt * 32;
        float s = 0.f, s2 = 0.f;
        #pragma unroll
        for (int q = 0; q < 8; ++q) {
            float4 v = *(const float4*)(zr + q * 4);
            s  += v.x + v.y + v.z + v.w;
            s2 += v.x*v.x + v.y*v.y + v.z*v.z + v.w*v.w;
        }
        s  += __shfl_xor_sync(0xffffffffu, s, 1);
        s2 += __shfl_xor_sync(0xffffffffu, s2, 1);
        s  += __shfl_xor_sync(0xffffffffu, s, 2);
        s2 += __shfl_xor_sync(0xffffffffu, s2, 2);
        float mu  = s * (1.0f/128.0f);
        float var = fmaxf(s2 * (1.0f/128.0f) - mu*mu, 0.f);
        float rs  = rsqrtf(var + EPSV);

        __nv_bfloat16* aH = (__nv_bfloat16*)(smem + OFF_AH) + row * ASTR;
        __nv_bfloat16* aL = (__nv_bfloat16*)(smem + OFF_AL) + row * ASTR;
        #pragma unroll
        for (int q8 = 0; q8 < 4; ++q8) {
            __align__(16) __nv_bfloat16 hb[8], lb[8];
            #pragma unroll
            for (int j = 0; j < 8; ++j) {
                int c = qt * 32 + q8 * 8 + j;
                float v = (zr[q8*8 + j] - mu) * rs * __ldg(ln_g + c) + __ldg(ln_b + c);
                __nv_bfloat16 h = __float2bfloat16(v);
                hb[j] = h;
                lb[j] = __float2bfloat16(v - __bfloat162float(h));
            }
            *(uint4*)(aH + qt*32 + q8*8) = *(uint4*)hb;
            *(uint4*)(aL + qt*32 + q8*8) = *(uint4*)lb;
        }
    }

    const int quad = lid >> 3;
    const int l7   = lid & 7;
    uint32_t aoff[2];
    #pragma unroll
    for (int mf = 0; mf < 2; ++mf) {
        int r = wm*32 + mf*16 + (quad & 1)*8 + l7;
        aoff[mf] = (r * ASTR + (quad >> 1) * 8) * 2;
    }
    const uint32_t boff = ((wn*16 + (quad & 1)*8 + l7) * ASTR + (quad >> 1) * 8) * 2;

    const int noff[10] = {0, 256, 64, 320, 128, 384, 192, 448, 512, 576};
    float sig[2][2][4];
    const int rbase = wm*32 + (lid >> 2);
    const int cbase_w = wn*16 + (lid & 3)*2;

    for (int ci = 0; ci < 10; ++ci) {
        __syncthreads();
        #pragma unroll
        for (int p = 0; p < 4; ++p) {
            int idx = p * 256 + t;
            int n = idx >> 4, seg = idx & 15;
            cp16(sbase + OFF_WH + n * 272 + seg * 16,
                 g_wH + (size_t)(noff[ci] + n) * 128 + seg * 8);
            cp16(sbase + OFF_WL + n * 272 + seg * 16,
                 g_wL + (size_t)(noff[ci] + n) * 128 + seg * 8);
        }
        cp_commit(); cp_wait0();
        __syncthreads();

        float acc[2][2][4];
        #pragma unroll
        for (int mf = 0; mf < 2; ++mf)
            #pragma unroll
            for (int nf = 0; nf < 2; ++nf)
                #pragma unroll
                for (int q = 0; q < 4; ++q) acc[mf][nf][q] = 0.f;

        #pragma unroll
        for (int ks = 0; ks < 128; ks += 16) {
            uint32_t ah[2][4], al[2][4], bh[2][2], bl[2][2], r4[4];
            ldmx4(ah[0], sbase + OFF_AH + aoff[0] + ks*2);
            ldmx4(ah[1], sbase + OFF_AH + aoff[1] + ks*2);
            ldmx4(al[0], sbase + OFF_AL + aoff[0] + ks*2);
            ldmx4(al[1], sbase + OFF_AL + aoff[1] + ks*2);
            ldmx4(r4, sbase + OFF_WH + boff + ks*2);
            bh[0][0] = r4[0]; bh[0][1] = r4[2];
            bh[1][0] = r4[1]; bh[1][1] = r4[3];
            ldmx4(r4, sbase + OFF_WL + boff + ks*2);
            bl[0][0] = r4[0]; bl[0][1] = r4[2];
            bl[1][0] = r4[1]; bl[1][1] = r4[3];
            #pragma unroll
            for (int mf = 0; mf < 2; ++mf)
                #pragma unroll
                for (int nf = 0; nf < 2; ++nf)
                    mma16816(acc[mf][nf], ah[mf], bh[nf]);
            #pragma unroll
            for (int mf = 0; mf < 2; ++mf)
                #pragma unroll
                for (int nf = 0; nf < 2; ++nf)
                    mma16816(acc[mf][nf], ah[mf], bl[nf]);
            #pragma unroll
            for (int mf = 0; mf < 2; ++mf)
                #pragma unroll
                for (int nf = 0; nf < 2; ++nf)
                    mma16816(acc[mf][nf], al[mf], bh[nf]);
        }

        if (ci >= 8) {
            const int cb2 = (ci - 8) * 64;
            #pragma unroll
            for (int mf = 0; mf < 2; ++mf) {
                int rr0 = rbase + mf*16, rr1 = rr0 + 8;
                #pragma unroll
                for (int nf = 0; nf < 2; ++nf) {
                    int cc = cbase_w + nf*8;
                    float bg0 = __ldg(b_g + cb2 + cc);
                    float bg1 = __ldg(b_g + cb2 + cc + 1);
                    float2 v0, v1;
                    v0.x = 1.f/(1.f + __expf(-(acc[mf][nf][0] + bg0)));
                    v0.y = 1.f/(1.f + __expf(-(acc[mf][nf][1] + bg1)));
                    v1.x = 1.f/(1.f + __expf(-(acc[mf][nf][2] + bg0)));
                    v1.y = 1.f/(1.f + __expf(-(acc[mf][nf][3] + bg1)));
                    *(float2*)(g_gate + (size_t)(r0 + rr0) * CZ + cb2 + cc) = v0;
                    *(float2*)(g_gate + (size_t)(r0 + rr1) * CZ + cb2 + cc) = v1;
                }
            }
        } else if ((ci & 1) == 0) {
            const float* bg = b_ab_g + noff[ci];
            #pragma unroll
            for (int mf = 0; mf < 2; ++mf)
                #pragma unroll
                for (int nf = 0; nf < 2; ++nf) {
                    int cc = cbase_w + nf*8;
                    float b0 = __ldg(bg + cc), b1 = __ldg(bg + cc + 1);
                    sig[mf][nf][0] = 1.f/(1.f + __expf(-(acc[mf][nf][0] + b0)));
                    sig[mf][nf][1] = 1.f/(1.f + __expf(-(acc[mf][nf][1] + b1)));
                    sig[mf][nf][2] = 1.f/(1.f + __expf(-(acc[mf][nf][2] + b0)));
                    sig[mf][nf][3] = 1.f/(1.f + __expf(-(acc[mf][nf][3] + b1)));
                }
        } else {
            const int p2 = (ci - 1) >> 1;
            const float* bp = b_ab_p + (noff[ci] - 256);
            uint32_t* stg = (uint32_t*)smem;
            #pragma unroll
            for (int mf = 0; mf < 2; ++mf) {
                int rr0 = rbase + mf*16, rr1 = rr0 + 8;
                float m0 = __ldg(mask + r0 + rr0);
                float m1 = __ldg(mask + r0 + rr1);
                #pragma unroll
                for (int nf = 0; nf < 2; ++nf) {
                    int cc = cbase_w + nf*8;
                    float b0 = __ldg(bp + cc), b1 = __ldg(bp + cc + 1);
                    stg[cc*132 + rr0]     = packHL(m0 * sig[mf][nf][0] * (acc[mf][nf][0] + b0));
                    stg[(cc+1)*132 + rr0] = packHL(m0 * sig[mf][nf][1] * (acc[mf][nf][1] + b1));
                    stg[cc*132 + rr1]     = packHL(m1 * sig[mf][nf][2] * (acc[mf][nf][2] + b0));
                    stg[(cc+1)*132 + rr1] = packHL(m1 * sig[mf][nf][3] * (acc[mf][nf][3] + b1));
                }
            }
            __syncthreads();
            __nv_bfloat16* dH = (p2 < 2) ? g_ah : g_bh;
            __nv_bfloat16* dL = (p2 < 2) ? g_al : g_bl;
            const int cch = (p2 & 1) * 64 + (t >> 2);
            const int rrb = (t & 3) * 16;
            size_t off = (size_t)cch * NR + r0 + rrb;
            const uint32_t* sp = stg + (t >> 2) * 132 + rrb;
            __align__(16) unsigned short hb[16], lb[16];
            #pragma unroll
            for (int i = 0; i < 16; ++i) {
                uint32_t wv = sp[i];
                hb[i] = (unsigned short)(wv & 0xffffu);
                lb[i] = (unsigned short)(wv >> 16);
            }
            *(uint4*)(dH + off)     = *(uint4*)(hb);
            *(uint4*)(dH + off + 8) = *(uint4*)(hb + 8);
            *(uint4*)(dL + off)     = *(uint4*)(lb);
            *(uint4*)(dL + off + 8) = *(uint4*)(lb + 8);
        }
    }
}

// =====================================================================
// Kernel 2: einsum via mma.sync bf16 3-pass split (unchanged).
// =====================================================================
#define KC     32
#define STR    40
#define TILE_E (128*STR)
#define BUF_E  (4*TILE_E)
#define K2_SMEM (2 * BUF_E * 2)

__global__ void __launch_bounds__(512) k2_einsum_mma() {
    extern __shared__ __nv_bfloat16 sb[];
    const uint32_t sbase = smem_u32(sb);

    const int t   = threadIdx.x;
    const int lid = t & 31;
    const int w   = t >> 5;
    const int wm  = w >> 2;
    const int wn  = w & 3;
    const int c   = blockIdx.z;
    const int m0  = blockIdx.y * 128;
    const int n0  = blockIdx.x * 128;

    const __nv_bfloat16* pAh = g_ah + (size_t)c * NR;
    const __nv_bfloat16* pAl = g_al + (size_t)c * NR;
    const __nv_bfloat16* pBh = g_bh + (size_t)c * NR;
    const __nv_bfloat16* pBl = g_bl + (size_t)c * NR;

    const int grow = t >> 2;
    const int gseg = t & 3;
    const size_t gA0 = (size_t)(m0 + grow) * NN + gseg * 8;
    const size_t gB0 = (size_t)(n0 + grow) * NN + gseg * 8;
    const uint32_t sw = (grow * STR + gseg * 8) * 2;

    const int quad = lid >> 3;
    const int l7   = lid & 7;
    uint32_t aoff[2];
    #pragma unroll
    for (int mf = 0; mf < 2; ++mf) {
        int r = wm*32 + mf*16 + (quad & 1)*8 + l7;
        aoff[mf] = (r * STR + (quad >> 1) * 8) * 2;
    }
    uint32_t boff[4];
    #pragma unroll
    for (int nf = 0; nf < 4; ++nf) {
        int r = wn*32 + nf*8 + l7;
        boff[nf] = (r * STR + ((lid >> 3) & 1) * 8) * 2;
    }

    float d[2][4][4];
    #pragma unroll
    for (int mf = 0; mf < 2; ++mf)
        #pragma unroll
        for (int nf = 0; nf < 4; ++nf)
            #pragma unroll
            for (int q = 0; q < 4; ++q) d[mf][nf][q] = 0.f;

    {
        uint32_t b0 = sbase;
        cp16(b0 + 0*TILE_E*2 + sw, pAh + gA0);
        cp16(b0 + 1*TILE_E*2 + sw, pAl + gA0);
        cp16(b0 + 2*TILE_E*2 + sw, pBh + gB0);
        cp16(b0 + 3*TILE_E*2 + sw, pBl + gB0);
        cp_commit();
    }

    for (int ch = 0; ch < 16; ++ch) {
        if (ch < 15) {
            uint32_t bb = sbase + ((ch + 1) & 1) * BUF_E * 2;
            int kk = (ch + 1) * KC;
            cp16(bb + 0*TILE_E*2 + sw, pAh + gA0 + kk);
            cp16(bb + 1*TILE_E*2 + sw, pAl + gA0 + kk);
            cp16(bb + 2*TILE_E*2 + sw, pBh + gB0 + kk);
            cp16(bb + 3*TILE_E*2 + sw, pBl + gB0 + kk);
            cp_commit();
            cp_wait1();
        } else {
            cp_wait0();
        }
        __syncthreads();

        const uint32_t bb = sbase + (ch & 1) * BUF_E * 2;
        const uint32_t bAH = bb;
        const uint32_t bAL = bb + TILE_E*2;
        const uint32_t bBH = bb + 2*TILE_E*2;
        const uint32_t bBL = bb + 3*TILE_E*2;

        #pragma unroll
        for (int ks = 0; ks < KC; ks += 16) {
            uint32_t ah[2][4], al[2][4], bh[4][2], bl[4][2];
            #pragma unroll
            for (int mf = 0; mf < 2; ++mf) ldmx4(ah[mf], bAH + aoff[mf] + ks*2);
            #pragma unroll
            for (int nf = 0; nf < 4; ++nf) ldmx2(bh[nf], bBH + boff[nf] + ks*2);
            #pragma unroll
            for (int nf = 0; nf < 4; ++nf) ldmx2(bl[nf], bBL + boff[nf] + ks*2);
            #pragma unroll
            for (int mf = 0; mf < 2; ++mf)
                #pragma unroll
                for (int nf = 0; nf < 4; ++nf)
                    mma16816(d[mf][nf], ah[mf], bh[nf]);
            #pragma unroll
            for (int mf = 0; mf < 2; ++mf)
                #pragma unroll
                for (int nf = 0; nf < 4; ++nf)
                    mma16816(d[mf][nf], ah[mf], bl[nf]);
            #pragma unroll
            for (int mf = 0; mf < 2; ++mf) ldmx4(al[mf], bAL + aoff[mf] + ks*2);
            #pragma unroll
            for (int mf = 0; mf < 2; ++mf)
                #pragma unroll
                for (int nf = 0; nf < 4; ++nf)
                    mma16816(d[mf][nf], al[mf], bh[nf]);
        }
        __syncthreads();
    }

    float* X = g_x + (size_t)c * NR;
    const int rb = m0 + wm*32 + (lid >> 2);
    const int cb = n0 + wn*32 + (lid & 3) * 2;
    #pragma unroll
    for (int mf = 0; mf < 2; ++mf)
        #pragma unroll
        for (int nf = 0; nf < 4; ++nf) {
            int row = rb + mf*16;
            int col = cb + nf*8;
            *(float2*)(X + (size_t)row * NN + col) =
                make_float2(d[mf][nf][0], d[mf][nf][1]);
            *(float2*)(X + (size_t)(row + 8) * NN + col) =
                make_float2(d[mf][nf][2], d[mf][nf][3]);
        }
}

// =====================================================================
// Kernel 3 (v2): gather x -> LN -> @ w_z (mma 3-pass) -> *gate -> out.
// Same template as k1: 4096 CTAs x 64 rows, 256 thr, 2 chunks of 64.
// =====================================================================
__global__ void __launch_bounds__(256, 2) k3_mma(
    const float* __restrict__ b_z,
    const float* __restrict__ ln_g, const float* __restrict__ ln_b,
    float* __restrict__ out)
{
    extern __shared__ char smem[];
    const uint32_t sbase = smem_u32(smem);
    float* xS = (float*)smem;                    // [row][c] stride 132
    const int t   = threadIdx.x;
    const int lid = t & 31;
    const int w   = t >> 5;
    const int wm  = w >> 2;
    const int wn  = w & 3;
    const int r0  = blockIdx.x * 64;
    const int i0  = r0 >> 9;
    const int j0  = r0 & 511;

    // ---- gather x from c-major g_x, transposed into [row][c] ----
    {
        const int joff = t & 63, part = t >> 6;
        const float* src = g_x + (size_t)(part*32) * NR + (size_t)i0 * NN + j0 + joff;
        #pragma unroll 8
        for (int q = 0; q < 32; ++q)
            xS[joff*132 + part*32 + q] = src[(size_t)q * NR];
    }
    __syncthreads();

    // ---- LN over c -> bf16 hi/lo ----
    {
        const int row = t >> 2, qt = t & 3;
        const float* zr = xS + row * 132 + qt * 32;
        float s = 0.f, s2 = 0.f;
        #pragma unroll
        for (int q = 0; q < 8; ++q) {
            float4 v = *(const float4*)(zr + q * 4);
            s  += v.x + v.y + v.z + v.w;
            s2 += v.x*v.x + v.y*v.y + v.z*v.z + v.w*v.w;
        }
        s  += __shfl_xor_sync(0xffffffffu, s, 1);
        s2 += __shfl_xor_sync(0xffffffffu, s2, 1);
        s  += __shfl_xor_sync(0xffffffffu, s, 2);
        s2 += __shfl_xor_sync(0xffffffffu, s2, 2);
        float mu  = s * (1.0f/128.0f);
        float var = fmaxf(s2 * (1.0f/128.0f) - mu*mu, 0.f);
        float rs  = rsqrtf(var + EPSV);

        __nv_bfloat16* aH = (__nv_bfloat16*)(smem + OFF_AH) + row * ASTR;
        __nv_bfloat16* aL = (__nv_bfloat16*)(smem + OFF_AL) + row * ASTR;
        #pragma unroll
        for (int q8 = 0; q8 < 4; ++q8) {
            __align__(16) __nv_bfloat16 hb[8], lb[8];
            #pragma unroll
            for (int j = 0; j < 8; ++j) {
                int c = qt * 32 + q8 * 8 + j;
                float v = (zr[q8*8 + j] - mu) * rs * __ldg(ln_g + c) + __ldg(ln_b + c);
                __nv_bfloat16 h = __float2bfloat16(v);
                hb[j] = h;
                lb[j] = __float2bfloat16(v - __bfloat162float(h));
            }
            *(uint4*)(aH + qt*32 + q8*8) = *(uint4*)hb;
            *(uint4*)(aL + qt*32 + q8*8) = *(uint4*)lb;
        }
    }

    const int quad = lid >> 3;
    const int l7   = lid & 7;
    uint32_t aoff[2];
    #pragma unroll
    for (int mf = 0; mf < 2; ++mf) {
        int r = wm*32 + mf*16 + (quad & 1)*8 + l7;
        aoff[mf] = (r * ASTR + (quad >> 1) * 8) * 2;
    }
    const uint32_t boff = ((wn*16 + (quad & 1)*8 + l7) * ASTR + (quad >> 1) * 8) * 2;
    const int rbase = wm*32 + (lid >> 2);
    const int cbase_w = wn*16 + (lid & 3)*2;

    for (int ci = 0; ci < 2; ++ci) {
        __syncthreads();
        #pragma unroll
        for (int p = 0; p < 4; ++p) {
            int idx = p * 256 + t;
            int n = idx >> 4, seg = idx & 15;
            cp16(sbase + OFF_WH + n * 272 + seg * 16,
                 g_wH + (size_t)(640 + ci*64 + n) * 128 + seg * 8);
            cp16(sbase + OFF_WL + n * 272 + seg * 16,
                 g_wL + (size_t)(640 + ci*64 + n) * 128 + seg * 8);
        }
        cp_commit(); cp_wait0();
        __syncthreads();

        float acc[2][2][4];
        #pragma unroll
        for (int mf = 0; mf < 2; ++mf)
            #pragma unroll
            for (int nf = 0; nf < 2; ++nf)
                #pragma unroll
                for (int q = 0; q < 4; ++q) acc[mf][nf][q] = 0.f;

        #pragma unroll
        for (int ks = 0; ks < 128; ks += 16) {
            uint32_t ah[2][4], al[2][4], bh[2][2], bl[2][2], r4[4];
            ldmx4(ah[0], sbase + OFF_AH + aoff[0] + ks*2);
            ldmx4(ah[1], sbase + OFF_AH + aoff[1] + ks*2);
            ldmx4(al[0], sbase + OFF_AL + aoff[0] + ks*2);
            ldmx4(al[1], sbase + OFF_AL + aoff[1] + ks*2);
            ldmx4(r4, sbase + OFF_WH + boff + ks*2);
            bh[0][0] = r4[0]; bh[0][1] = r4[2];
            bh[1][0] = r4[1]; bh[1][1] = r4[3];
            ldmx4(r4, sbase + OFF_WL + boff + ks*2);
            bl[0][0] = r4[0]; bl[0][1] = r4[2];
            bl[1][0] = r4[1]; bl[1][1] = r4[3];
            #pragma unroll
            for (int mf = 0; mf < 2; ++mf)
                #pragma unroll
                for (int nf = 0; nf < 2; ++nf)
                    mma16816(acc[mf][nf], ah[mf], bh[nf]);
            #pragma unroll
            for (int mf = 0; mf < 2; ++mf)
                #pragma unroll
                for (int nf = 0; nf < 2; ++nf)
                    mma16816(acc[mf][nf], ah[mf], bl[nf]);
            #pragma unroll
            for (int mf = 0; mf < 2; ++mf)
                #pragma unroll
                for (int nf = 0; nf < 2; ++nf)
                    mma16816(acc[mf][nf], al[mf], bh[nf]);
        }

        // epilogue: (acc + b_z) * gate -> out (fp32 row-major)
        const int cb2 = ci * 64;
        #pragma unroll
        for (int mf = 0; mf < 2; ++mf) {
            int rr0 = rbase + mf*16, rr1 = rr0 + 8;
            #pragma unroll
            for (int nf = 0; nf < 2; ++nf) {
                int cc = cbase_w + nf*8;
                float b0 = __ldg(b_z + cb2 + cc);
                float b1 = __ldg(b_z + cb2 + cc + 1);
                float2 gg0 = *(const float2*)(g_gate + (size_t)(r0 + rr0) * CZ + cb2 + cc);
                float2 gg1 = *(const float2*)(g_gate + (size_t)(r0 + rr1) * CZ + cb2 + cc);
                float2 v0, v1;
                v0.x = (acc[mf][nf][0] + b0) * gg0.x;
                v0.y = (acc[mf][nf][1] + b1) * gg0.y;
                v1.x = (acc[mf][nf][2] + b0) * gg1.x;
                v1.y = (acc[mf][nf][3] + b1) * gg1.y;
                *(float2*)(out + (size_t)(r0 + rr0) * CZ + cb2 + cc) = v0;
                *(float2*)(out + (size_t)(r0 + rr1) * CZ + cb2 + cc) = v1;
            }
        }
    }
}

// =====================================================================
extern "C" void kernel_launch(void* const* d_in, const int* in_sizes, int n_in,
                              void* d_out, int out_size) {
    const float* z       = (const float*)d_in[0];
    const float* mask    = (const float*)d_in[1];
    const float* w_ab_p  = (const float*)d_in[2];
    const float* b_ab_p  = (const float*)d_in[3];
    const float* w_ab_g  = (const float*)d_in[4];
    const float* b_ab_g  = (const float*)d_in[5];
    const float* w_g     = (const float*)d_in[6];
    const float* b_g     = (const float*)d_in[7];
    const float* w_z     = (const float*)d_in[8];
    const float* b_z     = (const float*)d_in[9];
    const float* ln_in_g = (const float*)d_in[10];
    const float* ln_in_b = (const float*)d_in[11];
    const float* ln_out_g= (const float*)d_in[12];
    const float* ln_out_b= (const float*)d_in[13];
    float* out = (float*)d_out;

    cudaFuncSetAttribute(k1_mma,        cudaFuncAttributeMaxDynamicSharedMemorySize, K1_SMEM);
    cudaFuncSetAttribute(k2_einsum_mma, cudaFuncAttributeMaxDynamicSharedMemorySize, K2_SMEM);
    cudaFuncSetAttribute(k3_mma,        cudaFuncAttributeMaxDynamicSharedMemorySize, K1_SMEM);

    k0_wsplit<<<384, 256>>>(w_ab_g, w_ab_p, w_g, w_z);
    k1_mma<<<NR / 64, 256, K1_SMEM>>>(z, mask, b_ab_p, b_ab_g, b_g,
                                      ln_in_g, ln_in_b);
    k2_einsum_mma<<<dim3(4, 4, 128), 512, K2_SMEM>>>();
    k3_mma<<<NR / 64, 256, K1_SMEM>>>(b_z, ln_out_g, ln_out_b, out);
}

// round 9
// speedup vs baseline: 1.9469x; 1.0014x over previous
#include <cuda_runtime.h>
#include <cuda_bf16.h>
#include <math.h>
#include <cstdint>

#define NN   512
#define CZ   128
#define NR   (NN*NN)          // 262144
#define EPSV 1e-5f

// ---------------- scratch (device globals; alloc-free) ----------------
__device__ __nv_bfloat16 g_ah[(size_t)CZ * NR];   // a hi [c][i][k]
__device__ __nv_bfloat16 g_al[(size_t)CZ * NR];   // a lo
__device__ __nv_bfloat16 g_bh[(size_t)CZ * NR];   // b hi [c][j][k]
__device__ __nv_bfloat16 g_bl[(size_t)CZ * NR];   // b lo
__device__ float g_gate[(size_t)NR * CZ];         // gate[r][c]
__device__ float g_x[(size_t)CZ * NR];            // x[c][i][j]
__device__ __nv_bfloat16 g_wH[768 * 128];         // packed weights hi [n][k]
__device__ __nv_bfloat16 g_wL[768 * 128];         // packed weights lo [n][k]

static __device__ __forceinline__ uint32_t smem_u32(const void* p) {
    return (uint32_t)__cvta_generic_to_shared(p);
}
static __device__ __forceinline__ void cp16(uint32_t dst, const void* src) {
    asm volatile("cp.async.cg.shared.global [%0], [%1], 16;" :: "r"(dst), "l"(src));
}
static __device__ __forceinline__ void cp_commit() {
    asm volatile("cp.async.commit_group;" ::: "memory");
}
static __device__ __forceinline__ void cp_wait1() {
    asm volatile("cp.async.wait_group 1;" ::: "memory");
}
static __device__ __forceinline__ void cp_wait0() {
    asm volatile("cp.async.wait_group 0;" ::: "memory");
}
static __device__ __forceinline__ void ldmx4(uint32_t* r, uint32_t addr) {
    asm volatile("ldmatrix.sync.aligned.m8n8.x4.shared.b16 {%0,%1,%2,%3}, [%4];"
                 : "=r"(r[0]), "=r"(r[1]), "=r"(r[2]), "=r"(r[3]) : "r"(addr));
}
static __device__ __forceinline__ void ldmx2(uint32_t* r, uint32_t addr) {
    asm volatile("ldmatrix.sync.aligned.m8n8.x2.shared.b16 {%0,%1}, [%2];"
                 : "=r"(r[0]), "=r"(r[1]) : "r"(addr));
}
static __device__ __forceinline__ void mma16816(float* d, const uint32_t* a, const uint32_t* b) {
    asm volatile("mma.sync.aligned.m16n8k16.row.col.f32.bf16.bf16.f32 "
                 "{%0,%1,%2,%3}, {%4,%5,%6,%7}, {%8,%9}, {%0,%1,%2,%3};"
                 : "+f"(d[0]), "+f"(d[1]), "+f"(d[2]), "+f"(d[3])
                 : "r"(a[0]), "r"(a[1]), "r"(a[2]), "r"(a[3]), "r"(b[0]), "r"(b[1]));
}
static __device__ __forceinline__ uint32_t packHL(float v) {
    __nv_bfloat16 h = __float2bfloat16(v);
    __nv_bfloat16 l = __float2bfloat16(v - __bfloat162float(h));
    return (uint32_t)__bfloat16_as_ushort(h) | ((uint32_t)__bfloat16_as_ushort(l) << 16);
}

// =====================================================================
// Kernel 0: split weights into bf16 hi/lo, transposed to [n][k].
// n: 0-255 = w_ab_g, 256-511 = w_ab_p, 512-639 = w_g, 640-767 = w_z
// =====================================================================
__global__ void __launch_bounds__(256) k0_wsplit(
    const float* __restrict__ w_ab_g, const float* __restrict__ w_ab_p,
    const float* __restrict__ w_g,   const float* __restrict__ w_z)
{
    int idx = blockIdx.x * 256 + threadIdx.x;   // 384 blocks
    if (idx >= 768 * 128) return;
    int n = idx >> 7, k = idx & 127;
    float v;
    if (n < 256)      v = w_ab_g[k * 256 + n];
    else if (n < 512) v = w_ab_p[k * 256 + (n - 256)];
    else if (n < 640) v = w_g[k * 128 + (n - 512)];
    else              v = w_z[k * 128 + (n - 640)];
    __nv_bfloat16 h = __float2bfloat16(v);
    g_wH[idx] = h;
    g_wL[idx] = __float2bfloat16(v - __bfloat162float(h));
}

// =====================================================================
// Kernel 1 (v3): LN(z) + projections, mma.sync bf16 hi/lo 3-pass.
// 4096 CTAs x 64 rows, 256 thr (8 warps: 2m x 4n), warp tile 32x16.
// z via LDG (no fp32 staging); weights DOUBLE-BUFFERED (cp_wait1);
// P-chunk staging reuses the dead weight buffer. smem 104448 -> 2 CTAs/SM.
// =====================================================================
#define ASTR   136
#define OFF_AH 0
#define OFF_AL 17408
#define OFF_WB 34816                   // two 34816-B weight buffers
#define WBSZ   34816
#define K1_SMEM 104448

__global__ void __launch_bounds__(256, 2) k1_mma(
    const float* __restrict__ z, const float* __restrict__ mask,
    const float* __restrict__ b_ab_p, const float* __restrict__ b_ab_g,
    const float* __restrict__ b_g,
    const float* __restrict__ ln_g,  const float* __restrict__ ln_b)
{
    extern __shared__ char smem[];
    const uint32_t sbase = smem_u32(smem);
    const int t   = threadIdx.x;
    const int lid = t & 31;
    const int w   = t >> 5;
    const int wm  = w >> 2;
    const int wn  = w & 3;
    const int r0  = blockIdx.x * 64;

    const int noff[10] = {0, 256, 64, 320, 128, 384, 192, 448, 512, 576};

    // ---- prefetch weight chunk 0 into buffer 0 (overlaps z load + LN) ----
    {
        #pragma unroll
        for (int p = 0; p < 4; ++p) {
            int idx = p * 256 + t;
            int n = idx >> 4, seg = idx & 15;
            cp16(sbase + OFF_WB + n * 272 + seg * 16,
                 g_wH + (size_t)n * 128 + seg * 8);
            cp16(sbase + OFF_WB + 17408 + n * 272 + seg * 16,
                 g_wL + (size_t)n * 128 + seg * 8);
        }
        cp_commit();
    }

    // ---- z via LDG -> LN (4 thr/row, shfl) -> bf16 hi/lo smem ----
    {
        const int row = t >> 2, qt = t & 3;
        const float4* zr = (const float4*)(z + (size_t)(r0 + row) * CZ + qt * 32);
        float4 v[8];
        #pragma unroll
        for (int q = 0; q < 8; ++q) v[q] = __ldg(zr + q);
        float s = 0.f, s2 = 0.f;
        #pragma unroll
        for (int q = 0; q < 8; ++q) {
            s  += v[q].x + v[q].y + v[q].z + v[q].w;
            s2 += v[q].x*v[q].x + v[q].y*v[q].y + v[q].z*v[q].z + v[q].w*v[q].w;
        }
        s  += __shfl_xor_sync(0xffffffffu, s, 1);
        s2 += __shfl_xor_sync(0xffffffffu, s2, 1);
        s  += __shfl_xor_sync(0xffffffffu, s, 2);
        s2 += __shfl_xor_sync(0xffffffffu, s2, 2);
        float mu  = s * (1.0f/128.0f);
        float var = fmaxf(s2 * (1.0f/128.0f) - mu*mu, 0.f);
        float rs  = rsqrtf(var + EPSV);

        __nv_bfloat16* aH = (__nv_bfloat16*)(smem + OFF_AH) + row * ASTR + qt * 32;
        __nv_bfloat16* aL = (__nv_bfloat16*)(smem + OFF_AL) + row * ASTR + qt * 32;
        #pragma unroll
        for (int q8 = 0; q8 < 4; ++q8) {
            const float vv[8] = {v[q8*2].x, v[q8*2].y, v[q8*2].z, v[q8*2].w,
                                 v[q8*2+1].x, v[q8*2+1].y, v[q8*2+1].z, v[q8*2+1].w};
            __align__(16) __nv_bfloat16 hb[8], lb[8];
            #pragma unroll
            for (int j = 0; j < 8; ++j) {
                int c = qt * 32 + q8 * 8 + j;
                float val = (vv[j] - mu) * rs * __ldg(ln_g + c) + __ldg(ln_b + c);
                __nv_bfloat16 h = __float2bfloat16(val);
                hb[j] = h;
                lb[j] = __float2bfloat16(val - __bfloat162float(h));
            }
            *(uint4*)(aH + q8*8) = *(uint4*)hb;
            *(uint4*)(aL + q8*8) = *(uint4*)lb;
        }
    }

    const int quad = lid >> 3;
    const int l7   = lid & 7;
    uint32_t aoff[2];
    #pragma unroll
    for (int mf = 0; mf < 2; ++mf) {
        int r = wm*32 + mf*16 + (quad & 1)*8 + l7;
        aoff[mf] = (r * ASTR + (quad >> 1) * 8) * 2;
    }
    const uint32_t boff = ((wn*16 + (quad & 1)*8 + l7) * ASTR + (quad >> 1) * 8) * 2;

    float sig[2][2][4];
    const int rbase = wm*32 + (lid >> 2);
    const int cbase_w = wn*16 + (lid & 3)*2;

    for (int ci = 0; ci < 10; ++ci) {
        __syncthreads();   // A-writes visible (ci=0); prior staging reads done
        const uint32_t wb = sbase + OFF_WB + (ci & 1) * WBSZ;
        if (ci < 9) {
            const uint32_t wbn = sbase + OFF_WB + ((ci + 1) & 1) * WBSZ;
            #pragma unroll
            for (int p = 0; p < 4; ++p) {
                int idx = p * 256 + t;
                int n = idx >> 4, seg = idx & 15;
                cp16(wbn + n * 272 + seg * 16,
                     g_wH + (size_t)(noff[ci+1] + n) * 128 + seg * 8);
                cp16(wbn + 17408 + n * 272 + seg * 16,
                     g_wL + (size_t)(noff[ci+1] + n) * 128 + seg * 8);
            }
            cp_commit();
            cp_wait1();          // W[ci] complete; W[ci+1] in flight
        } else {
            cp_wait0();
        }
        __syncthreads();

        float acc[2][2][4];
        #pragma unroll
        for (int mf = 0; mf < 2; ++mf)
            #pragma unroll
            for (int nf = 0; nf < 2; ++nf)
                #pragma unroll
                for (int q = 0; q < 4; ++q) acc[mf][nf][q] = 0.f;

        #pragma unroll
        for (int ks = 0; ks < 128; ks += 16) {
            uint32_t ah[2][4], al[2][4], bh[2][2], bl[2][2], r4[4];
            ldmx4(ah[0], sbase + OFF_AH + aoff[0] + ks*2);
            ldmx4(ah[1], sbase + OFF_AH + aoff[1] + ks*2);
            ldmx4(al[0], sbase + OFF_AL + aoff[0] + ks*2);
            ldmx4(al[1], sbase + OFF_AL + aoff[1] + ks*2);
            ldmx4(r4, wb + boff + ks*2);
            bh[0][0] = r4[0]; bh[0][1] = r4[2];
            bh[1][0] = r4[1]; bh[1][1] = r4[3];
            ldmx4(r4, wb + 17408 + boff + ks*2);
            bl[0][0] = r4[0]; bl[0][1] = r4[2];
            bl[1][0] = r4[1]; bl[1][1] = r4[3];
            #pragma unroll
            for (int mf = 0; mf < 2; ++mf)
                #pragma unroll
                for (int nf = 0; nf < 2; ++nf)
                    mma16816(acc[mf][nf], ah[mf], bh[nf]);
            #pragma unroll
            for (int mf = 0; mf < 2; ++mf)
                #pragma unroll
                for (int nf = 0; nf < 2; ++nf)
                    mma16816(acc[mf][nf], ah[mf], bl[nf]);
            #pragma unroll
            for (int mf = 0; mf < 2; ++mf)
                #pragma unroll
                for (int nf = 0; nf < 2; ++nf)
                    mma16816(acc[mf][nf], al[mf], bh[nf]);
        }

        if (ci >= 8) {
            const int cb2 = (ci - 8) * 64;
            #pragma unroll
            for (int mf = 0; mf < 2; ++mf) {
                int rr0 = rbase + mf*16, rr1 = rr0 + 8;
                #pragma unroll
                for (int nf = 0; nf < 2; ++nf) {
                    int cc = cbase_w + nf*8;
                    float bg0 = __ldg(b_g + cb2 + cc);
                    float bg1 = __ldg(b_g + cb2 + cc + 1);
                    float2 v0, v1;
                    v0.x = 1.f/(1.f + __expf(-(acc[mf][nf][0] + bg0)));
                    v0.y = 1.f/(1.f + __expf(-(acc[mf][nf][1] + bg1)));
                    v1.x = 1.f/(1.f + __expf(-(acc[mf][nf][2] + bg0)));
                    v1.y = 1.f/(1.f + __expf(-(acc[mf][nf][3] + bg1)));
                    *(float2*)(g_gate + (size_t)(r0 + rr0) * CZ + cb2 + cc) = v0;
                    *(float2*)(g_gate + (size_t)(r0 + rr1) * CZ + cb2 + cc) = v1;
                }
            }
        } else if ((ci & 1) == 0) {
            const float* bg = b_ab_g + noff[ci];
            #pragma unroll
            for (int mf = 0; mf < 2; ++mf)
                #pragma unroll
                for (int nf = 0; nf < 2; ++nf) {
                    int cc = cbase_w + nf*8;
                    float b0 = __ldg(bg + cc), b1 = __ldg(bg + cc + 1);
                    sig[mf][nf][0] = 1.f/(1.f + __expf(-(acc[mf][nf][0] + b0)));
                    sig[mf][nf][1] = 1.f/(1.f + __expf(-(acc[mf][nf][1] + b1)));
                    sig[mf][nf][2] = 1.f/(1.f + __expf(-(acc[mf][nf][2] + b0)));
                    sig[mf][nf][3] = 1.f/(1.f + __expf(-(acc[mf][nf][3] + b1)));
                }
        } else {
            // P chunk: stage packed (hi,lo) into THIS chunk's dead W buffer
            const int p2 = (ci - 1) >> 1;
            const float* bp = b_ab_p + (noff[ci] - 256);
            __syncthreads();   // all warps done reading wb via ldmatrix
            uint32_t* stg = (uint32_t*)(smem + OFF_WB + (ci & 1) * WBSZ);
            #pragma unroll
            for (int mf = 0; mf < 2; ++mf) {
                int rr0 = rbase + mf*16, rr1 = rr0 + 8;
                float m0 = __ldg(mask + r0 + rr0);
                float m1 = __ldg(mask + r0 + rr1);
                #pragma unroll
                for (int nf = 0; nf < 2; ++nf) {
                    int cc = cbase_w + nf*8;
                    float b0 = __ldg(bp + cc), b1 = __ldg(bp + cc + 1);
                    stg[cc*68 + rr0]     = packHL(m0 * sig[mf][nf][0] * (acc[mf][nf][0] + b0));
                    stg[(cc+1)*68 + rr0] = packHL(m0 * sig[mf][nf][1] * (acc[mf][nf][1] + b1));
                    stg[cc*68 + rr1]     = packHL(m1 * sig[mf][nf][2] * (acc[mf][nf][2] + b0));
                    stg[(cc+1)*68 + rr1] = packHL(m1 * sig[mf][nf][3] * (acc[mf][nf][3] + b1));
                }
            }
            __syncthreads();
            __nv_bfloat16* dH = (p2 < 2) ? g_ah : g_bh;
            __nv_bfloat16* dL = (p2 < 2) ? g_al : g_bl;
            const int cch = (p2 & 1) * 64 + (t >> 2);
            const int rrb = (t & 3) * 16;
            size_t off = (size_t)cch * NR + r0 + rrb;
            const uint32_t* sp = stg + (t >> 2) * 68 + rrb;
            __align__(16) unsigned short hb[16], lb[16];
            #pragma unroll
            for (int i = 0; i < 16; ++i) {
                uint32_t wv = sp[i];
                hb[i] = (unsigned short)(wv & 0xffffu);
                lb[i] = (unsigned short)(wv >> 16);
            }
            *(uint4*)(dH + off)     = *(uint4*)(hb);
            *(uint4*)(dH + off + 8) = *(uint4*)(hb + 8);
            *(uint4*)(dL + off)     = *(uint4*)(lb);
            *(uint4*)(dL + off + 8) = *(uint4*)(lb + 8);
        }
    }
}

// =====================================================================
// Kernel 2: einsum via mma.sync bf16 3-pass split (unchanged).
// =====================================================================
#define KC     32
#define STR    40
#define TILE_E (128*STR)
#define BUF_E  (4*TILE_E)
#define K2_SMEM (2 * BUF_E * 2)

__global__ void __launch_bounds__(512) k2_einsum_mma() {
    extern __shared__ __nv_bfloat16 sb[];
    const uint32_t sbase = smem_u32(sb);

    const int t   = threadIdx.x;
    const int lid = t & 31;
    const int w   = t >> 5;
    const int wm  = w >> 2;
    const int wn  = w & 3;
    const int c   = blockIdx.z;
    const int m0  = blockIdx.y * 128;
    const int n0  = blockIdx.x * 128;

    const __nv_bfloat16* pAh = g_ah + (size_t)c * NR;
    const __nv_bfloat16* pAl = g_al + (size_t)c * NR;
    const __nv_bfloat16* pBh = g_bh + (size_t)c * NR;
    const __nv_bfloat16* pBl = g_bl + (size_t)c * NR;

    const int grow = t >> 2;
    const int gseg = t & 3;
    const size_t gA0 = (size_t)(m0 + grow) * NN + gseg * 8;
    const size_t gB0 = (size_t)(n0 + grow) * NN + gseg * 8;
    const uint32_t sw = (grow * STR + gseg * 8) * 2;

    const int quad = lid >> 3;
    const int l7   = lid & 7;
    uint32_t aoff[2];
    #pragma unroll
    for (int mf = 0; mf < 2; ++mf) {
        int r = wm*32 + mf*16 + (quad & 1)*8 + l7;
        aoff[mf] = (r * STR + (quad >> 1) * 8) * 2;
    }
    uint32_t boff[4];
    #pragma unroll
    for (int nf = 0; nf < 4; ++nf) {
        int r = wn*32 + nf*8 + l7;
        boff[nf] = (r * STR + ((lid >> 3) & 1) * 8) * 2;
    }

    float d[2][4][4];
    #pragma unroll
    for (int mf = 0; mf < 2; ++mf)
        #pragma unroll
        for (int nf = 0; nf < 4; ++nf)
            #pragma unroll
            for (int q = 0; q < 4; ++q) d[mf][nf][q] = 0.f;

    {
        uint32_t b0 = sbase;
        cp16(b0 + 0*TILE_E*2 + sw, pAh + gA0);
        cp16(b0 + 1*TILE_E*2 + sw, pAl + gA0);
        cp16(b0 + 2*TILE_E*2 + sw, pBh + gB0);
        cp16(b0 + 3*TILE_E*2 + sw, pBl + gB0);
        cp_commit();
    }

    for (int ch = 0; ch < 16; ++ch) {
        if (ch < 15) {
            uint32_t bb = sbase + ((ch + 1) & 1) * BUF_E * 2;
            int kk = (ch + 1) * KC;
            cp16(bb + 0*TILE_E*2 + sw, pAh + gA0 + kk);
            cp16(bb + 1*TILE_E*2 + sw, pAl + gA0 + kk);
            cp16(bb + 2*TILE_E*2 + sw, pBh + gB0 + kk);
            cp16(bb + 3*TILE_E*2 + sw, pBl + gB0 + kk);
            cp_commit();
            cp_wait1();
        } else {
            cp_wait0();
        }
        __syncthreads();

        const uint32_t bb = sbase + (ch & 1) * BUF_E * 2;
        const uint32_t bAH = bb;
        const uint32_t bAL = bb + TILE_E*2;
        const uint32_t bBH = bb + 2*TILE_E*2;
        const uint32_t bBL = bb + 3*TILE_E*2;

        #pragma unroll
        for (int ks = 0; ks < KC; ks += 16) {
            uint32_t ah[2][4], al[2][4], bh[4][2], bl[4][2];
            #pragma unroll
            for (int mf = 0; mf < 2; ++mf) ldmx4(ah[mf], bAH + aoff[mf] + ks*2);
            #pragma unroll
            for (int nf = 0; nf < 4; ++nf) ldmx2(bh[nf], bBH + boff[nf] + ks*2);
            #pragma unroll
            for (int nf = 0; nf < 4; ++nf) ldmx2(bl[nf], bBL + boff[nf] + ks*2);
            #pragma unroll
            for (int mf = 0; mf < 2; ++mf)
                #pragma unroll
                for (int nf = 0; nf < 4; ++nf)
                    mma16816(d[mf][nf], ah[mf], bh[nf]);
            #pragma unroll
            for (int mf = 0; mf < 2; ++mf)
                #pragma unroll
                for (int nf = 0; nf < 4; ++nf)
                    mma16816(d[mf][nf], ah[mf], bl[nf]);
            #pragma unroll
            for (int mf = 0; mf < 2; ++mf) ldmx4(al[mf], bAL + aoff[mf] + ks*2);
            #pragma unroll
            for (int mf = 0; mf < 2; ++mf)
                #pragma unroll
                for (int nf = 0; nf < 4; ++nf)
                    mma16816(d[mf][nf], al[mf], bh[nf]);
        }
        __syncthreads();
    }

    float* X = g_x + (size_t)c * NR;
    const int rb = m0 + wm*32 + (lid >> 2);
    const int cb = n0 + wn*32 + (lid & 3) * 2;
    #pragma unroll
    for (int mf = 0; mf < 2; ++mf)
        #pragma unroll
        for (int nf = 0; nf < 4; ++nf) {
            int row = rb + mf*16;
            int col = cb + nf*8;
            *(float2*)(X + (size_t)row * NN + col) =
                make_float2(d[mf][nf][0], d[mf][nf][1]);
            *(float2*)(X + (size_t)(row + 8) * NN + col) =
                make_float2(d[mf][nf][2], d[mf][nf][3]);
        }
}

// =====================================================================
// Kernel 3 (v2.1): gather x -> LN -> @ w_z (mma 3-pass) -> *gate -> out.
// Full-unroll gather (32 outstanding loads).
// =====================================================================
#define K3_AH 33792
#define K3_AL 51200
#define K3_WH 68608
#define K3_WL 86016
#define K3_SMEM 103424

__global__ void __launch_bounds__(256, 2) k3_mma(
    const float* __restrict__ b_z,
    const float* __restrict__ ln_g, const float* __restrict__ ln_b,
    float* __restrict__ out)
{
    extern __shared__ char smem[];
    const uint32_t sbase = smem_u32(smem);
    float* xS = (float*)smem;                    // [row][c] stride 132
    const int t   = threadIdx.x;
    const int lid = t & 31;
    const int w   = t >> 5;
    const int wm  = w >> 2;
    const int wn  = w & 3;
    const int r0  = blockIdx.x * 64;
    const int i0  = r0 >> 9;
    const int j0  = r0 & 511;

    {
        const int joff = t & 63, part = t >> 6;
        const float* src = g_x + (size_t)(part*32) * NR + (size_t)i0 * NN + j0 + joff;
        #pragma unroll
        for (int q = 0; q < 32; ++q)
            xS[joff*132 + part*32 + q] = src[(size_t)q * NR];
    }
    __syncthreads();

    {
        const int row = t >> 2, qt = t & 3;
        const float* zr = xS + row * 132 + qt * 32;
        float s = 0.f, s2 = 0.f;
        #pragma unroll
        for (int q = 0; q < 8; ++q) {
            float4 v = *(const float4*)(zr + q * 4);
            s  += v.x + v.y + v.z + v.w;
            s2 += v.x*v.x + v.y*v.y + v.z*v.z + v.w*v.w;
        }
        s  += __shfl_xor_sync(0xffffffffu, s, 1);
        s2 += __shfl_xor_sync(0xffffffffu, s2, 1);
        s  += __shfl_xor_sync(0xffffffffu, s, 2);
        s2 += __shfl_xor_sync(0xffffffffu, s2, 2);
        float mu  = s * (1.0f/128.0f);
        float var = fmaxf(s2 * (1.0f/128.0f) - mu*mu, 0.f);
        float rs  = rsqrtf(var + EPSV);

        __nv_bfloat16* aH = (__nv_bfloat16*)(smem + K3_AH) + row * ASTR;
        __nv_bfloat16* aL = (__nv_bfloat16*)(smem + K3_AL) + row * ASTR;
        #pragma unroll
        for (int q8 = 0; q8 < 4; ++q8) {
            __align__(16) __nv_bfloat16 hb[8], lb[8];
            #pragma unroll
            for (int j = 0; j < 8; ++j) {
                int c = qt * 32 + q8 * 8 + j;
                float v = (zr[q8*8 + j] - mu) * rs * __ldg(ln_g + c) + __ldg(ln_b + c);
                __nv_bfloat16 h = __float2bfloat16(v);
                hb[j] = h;
                lb[j] = __float2bfloat16(v - __bfloat162float(h));
            }
            *(uint4*)(aH + qt*32 + q8*8) = *(uint4*)hb;
            *(uint4*)(aL + qt*32 + q8*8) = *(uint4*)lb;
        }
    }

    const int quad = lid >> 3;
    const int l7   = lid & 7;
    uint32_t aoff[2];
    #pragma unroll
    for (int mf = 0; mf < 2; ++mf) {
        int r = wm*32 + mf*16 + (quad & 1)*8 + l7;
        aoff[mf] = (r * ASTR + (quad >> 1) * 8) * 2;
    }
    const uint32_t boff = ((wn*16 + (quad & 1)*8 + l7) * ASTR + (quad >> 1) * 8) * 2;
    const int rbase = wm*32 + (lid >> 2);
    const int cbase_w = wn*16 + (lid & 3)*2;

    for (int ci = 0; ci < 2; ++ci) {
        __syncthreads();
        #pragma unroll
        for (int p = 0; p < 4; ++p) {
            int idx = p * 256 + t;
            int n = idx >> 4, seg = idx & 15;
            cp16(sbase + K3_WH + n * 272 + seg * 16,
                 g_wH + (size_t)(640 + ci*64 + n) * 128 + seg * 8);
            cp16(sbase + K3_WL + n * 272 + seg * 16,
                 g_wL + (size_t)(640 + ci*64 + n) * 128 + seg * 8);
        }
        cp_commit(); cp_wait0();
        __syncthreads();

        float acc[2][2][4];
        #pragma unroll
        for (int mf = 0; mf < 2; ++mf)
            #pragma unroll
            for (int nf = 0; nf < 2; ++nf)
                #pragma unroll
                for (int q = 0; q < 4; ++q) acc[mf][nf][q] = 0.f;

        #pragma unroll
        for (int ks = 0; ks < 128; ks += 16) {
            uint32_t ah[2][4], al[2][4], bh[2][2], bl[2][2], r4[4];
            ldmx4(ah[0], sbase + K3_AH + aoff[0] + ks*2);
            ldmx4(ah[1], sbase + K3_AH + aoff[1] + ks*2);
            ldmx4(al[0], sbase + K3_AL + aoff[0] + ks*2);
            ldmx4(al[1], sbase + K3_AL + aoff[1] + ks*2);
            ldmx4(r4, sbase + K3_WH + boff + ks*2);
            bh[0][0] = r4[0]; bh[0][1] = r4[2];
            bh[1][0] = r4[1]; bh[1][1] = r4[3];
            ldmx4(r4, sbase + K3_WL + boff + ks*2);
            bl[0][0] = r4[0]; bl[0][1] = r4[2];
            bl[1][0] = r4[1]; bl[1][1] = r4[3];
            #pragma unroll
            for (int mf = 0; mf < 2; ++mf)
                #pragma unroll
                for (int nf = 0; nf < 2; ++nf)
                    mma16816(acc[mf][nf], ah[mf], bh[nf]);
            #pragma unroll
            for (int mf = 0; mf < 2; ++mf)
                #pragma unroll
                for (int nf = 0; nf < 2; ++nf)
                    mma16816(acc[mf][nf], ah[mf], bl[nf]);
            #pragma unroll
            for (int mf = 0; mf < 2; ++mf)
                #pragma unroll
                for (int nf = 0; nf < 2; ++nf)
                    mma16816(acc[mf][nf], al[mf], bh[nf]);
        }

        const int cb2 = ci * 64;
        #pragma unroll
        for (int mf = 0; mf < 2; ++mf) {
            int rr0 = rbase + mf*16, rr1 = rr0 + 8;
            #pragma unroll
            for (int nf = 0; nf < 2; ++nf) {
                int cc = cbase_w + nf*8;
                float b0 = __ldg(b_z + cb2 + cc);
                float b1 = __ldg(b_z + cb2 + cc + 1);
                float2 gg0 = *(const float2*)(g_gate + (size_t)(r0 + rr0) * CZ + cb2 + cc);
                float2 gg1 = *(const float2*)(g_gate + (size_t)(r0 + rr1) * CZ + cb2 + cc);
                float2 v0, v1;
                v0.x = (acc[mf][nf][0] + b0) * gg0.x;
                v0.y = (acc[mf][nf][1] + b1) * gg0.y;
                v1.x = (acc[mf][nf][2] + b0) * gg1.x;
                v1.y = (acc[mf][nf][3] + b1) * gg1.y;
                *(float2*)(out + (size_t)(r0 + rr0) * CZ + cb2 + cc) = v0;
                *(float2*)(out + (size_t)(r0 + rr1) * CZ + cb2 + cc) = v1;
            }
        }
    }
}

// =====================================================================
extern "C" void kernel_launch(void* const* d_in, const int* in_sizes, int n_in,
                              void* d_out, int out_size) {
    const float* z       = (const float*)d_in[0];
    const float* mask    = (const float*)d_in[1];
    const float* w_ab_p  = (const float*)d_in[2];
    const float* b_ab_p  = (const float*)d_in[3];
    const float* w_ab_g  = (const float*)d_in[4];
    const float* b_ab_g  = (const float*)d_in[5];
    const float* w_g     = (const float*)d_in[6];
    const float* b_g     = (const float*)d_in[7];
    const float* w_z     = (const float*)d_in[8];
    const float* b_z     = (const float*)d_in[9];
    const float* ln_in_g = (const float*)d_in[10];
    const float* ln_in_b = (const float*)d_in[11];
    const float* ln_out_g= (const float*)d_in[12];
    const float* ln_out_b= (const float*)d_in[13];
    float* out = (float*)d_out;

    cudaFuncSetAttribute(k1_mma,        cudaFuncAttributeMaxDynamicSharedMemorySize, K1_SMEM);
    cudaFuncSetAttribute(k2_einsum_mma, cudaFuncAttributeMaxDynamicSharedMemorySize, K2_SMEM);
    cudaFuncSetAttribute(k3_mma,        cudaFuncAttributeMaxDynamicSharedMemorySize, K3_SMEM);

    k0_wsplit<<<384, 256>>>(w_ab_g, w_ab_p, w_g, w_z);
    k1_mma<<<NR / 64, 256, K1_SMEM>>>(z, mask, b_ab_p, b_ab_g, b_g,
                                      ln_in_g, ln_in_b);
    k2_einsum_mma<<<dim3(4, 4, 128), 512, K2_SMEM>>>();
    k3_mma<<<NR / 64, 256, K3_SMEM>>>(b_z, ln_out_g, ln_out_b, out);
}

// round 10
// speedup vs baseline: 2.3992x; 1.2323x over previous
#include <cuda_runtime.h>
#include <cuda_fp16.h>
#include <math.h>
#include <cstdint>

#define NN   512
#define CZ   128
#define NR   (NN*NN)          // 262144
#define EPSV 1e-5f

// ---------------- scratch (device globals; alloc-free) ----------------
__device__ __half g_ah[(size_t)CZ * NR];   // a hi [c][i][k]
__device__ __half g_al[(size_t)CZ * NR];   // a lo
__device__ __half g_bh[(size_t)CZ * NR];   // b hi [c][j][k] (b is hi-only)
__device__ float g_gate[(size_t)NR * CZ];  // gate[r][c]
__device__ float g_x[(size_t)CZ * NR];     // x[c][i][j]
__device__ __half g_wH[768 * 128];         // packed weights hi [n][k]
__device__ __half g_wL[768 * 128];         // packed weights lo [n][k]

static __device__ __forceinline__ uint32_t smem_u32(const void* p) {
    return (uint32_t)__cvta_generic_to_shared(p);
}
static __device__ __forceinline__ void cp16(uint32_t dst, const void* src) {
    asm volatile("cp.async.cg.shared.global [%0], [%1], 16;" :: "r"(dst), "l"(src));
}
static __device__ __forceinline__ void cp_commit() {
    asm volatile("cp.async.commit_group;" ::: "memory");
}
static __device__ __forceinline__ void cp_wait1() {
    asm volatile("cp.async.wait_group 1;" ::: "memory");
}
static __device__ __forceinline__ void cp_wait0() {
    asm volatile("cp.async.wait_group 0;" ::: "memory");
}
static __device__ __forceinline__ void ldmx4(uint32_t* r, uint32_t addr) {
    asm volatile("ldmatrix.sync.aligned.m8n8.x4.shared.b16 {%0,%1,%2,%3}, [%4];"
                 : "=r"(r[0]), "=r"(r[1]), "=r"(r[2]), "=r"(r[3]) : "r"(addr));
}
static __device__ __forceinline__ void ldmx2(uint32_t* r, uint32_t addr) {
    asm volatile("ldmatrix.sync.aligned.m8n8.x2.shared.b16 {%0,%1}, [%2];"
                 : "=r"(r[0]), "=r"(r[1]) : "r"(addr));
}
static __device__ __forceinline__ void mma16816(float* d, const uint32_t* a, const uint32_t* b) {
    asm volatile("mma.sync.aligned.m16n8k16.row.col.f32.f16.f16.f32 "
                 "{%0,%1,%2,%3}, {%4,%5,%6,%7}, {%8,%9}, {%0,%1,%2,%3};"
                 : "+f"(d[0]), "+f"(d[1]), "+f"(d[2]), "+f"(d[3])
                 : "r"(a[0]), "r"(a[1]), "r"(a[2]), "r"(a[3]), "r"(b[0]), "r"(b[1]));
}
static __device__ __forceinline__ uint32_t packHL(float v) {
    __half h = __float2half(v);
    __half l = __float2half(v - __half2float(h));
    return (uint32_t)__half_as_ushort(h) | ((uint32_t)__half_as_ushort(l) << 16);
}

// =====================================================================
// Kernel 0: split weights into fp16 hi/lo, transposed to [n][k].
// n: 0-255 = w_ab_g, 256-511 = w_ab_p, 512-639 = w_g, 640-767 = w_z
// =====================================================================
__global__ void __launch_bounds__(256) k0_wsplit(
    const float* __restrict__ w_ab_g, const float* __restrict__ w_ab_p,
    const float* __restrict__ w_g,   const float* __restrict__ w_z)
{
    int idx = blockIdx.x * 256 + threadIdx.x;   // 384 blocks
    if (idx >= 768 * 128) return;
    int n = idx >> 7, k = idx & 127;
    float v;
    if (n < 256)      v = w_ab_g[k * 256 + n];
    else if (n < 512) v = w_ab_p[k * 256 + (n - 256)];
    else if (n < 640) v = w_g[k * 128 + (n - 512)];
    else              v = w_z[k * 128 + (n - 640)];
    __half h = __float2half(v);
    g_wH[idx] = h;
    g_wL[idx] = __float2half(v - __half2float(h));
}

// =====================================================================
// Kernel 1 (v4): LN(z) + projections, fp16 2-pass (znH*WH + znL*WH).
// 4096 CTAs x 64 rows, 256 thr (8 warps: 2m x 4n), warp tile 32x16.
// W hi-only, double-buffered. smem 69632 -> 2 CTAs/SM (RF-bound).
// =====================================================================
#define ASTR   136
#define OFF_AH 0
#define OFF_AL 17408
#define OFF_WB 34816                   // two 17408-B WH buffers
#define WBSZ   17408
#define K1_SMEM 69632

__global__ void __launch_bounds__(256, 2) k1_mma(
    const float* __restrict__ z, const float* __restrict__ mask,
    const float* __restrict__ b_ab_p, const float* __restrict__ b_ab_g,
    const float* __restrict__ b_g,
    const float* __restrict__ ln_g,  const float* __restrict__ ln_b)
{
    extern __shared__ char smem[];
    const uint32_t sbase = smem_u32(smem);
    const int t   = threadIdx.x;
    const int lid = t & 31;
    const int w   = t >> 5;
    const int wm  = w >> 2;
    const int wn  = w & 3;
    const int r0  = blockIdx.x * 64;

    const int noff[10] = {0, 256, 64, 320, 128, 384, 192, 448, 512, 576};

    // ---- prefetch WH chunk 0 into buffer 0 ----
    {
        #pragma unroll
        for (int p = 0; p < 4; ++p) {
            int idx = p * 256 + t;
            int n = idx >> 4, seg = idx & 15;
            cp16(sbase + OFF_WB + n * 272 + seg * 16,
                 g_wH + (size_t)n * 128 + seg * 8);
        }
        cp_commit();
    }

    // ---- z via LDG -> LN (4 thr/row, shfl) -> fp16 hi/lo smem ----
    {
        const int row = t >> 2, qt = t & 3;
        const float4* zr = (const float4*)(z + (size_t)(r0 + row) * CZ + qt * 32);
        float4 v[8];
        #pragma unroll
        for (int q = 0; q < 8; ++q) v[q] = __ldg(zr + q);
        float s = 0.f, s2 = 0.f;
        #pragma unroll
        for (int q = 0; q < 8; ++q) {
            s  += v[q].x + v[q].y + v[q].z + v[q].w;
            s2 += v[q].x*v[q].x + v[q].y*v[q].y + v[q].z*v[q].z + v[q].w*v[q].w;
        }
        s  += __shfl_xor_sync(0xffffffffu, s, 1);
        s2 += __shfl_xor_sync(0xffffffffu, s2, 1);
        s  += __shfl_xor_sync(0xffffffffu, s, 2);
        s2 += __shfl_xor_sync(0xffffffffu, s2, 2);
        float mu  = s * (1.0f/128.0f);
        float var = fmaxf(s2 * (1.0f/128.0f) - mu*mu, 0.f);
        float rs  = rsqrtf(var + EPSV);

        __half* aH = (__half*)(smem + OFF_AH) + row * ASTR + qt * 32;
        __half* aL = (__half*)(smem + OFF_AL) + row * ASTR + qt * 32;
        #pragma unroll
        for (int q8 = 0; q8 < 4; ++q8) {
            const float vv[8] = {v[q8*2].x, v[q8*2].y, v[q8*2].z, v[q8*2].w,
                                 v[q8*2+1].x, v[q8*2+1].y, v[q8*2+1].z, v[q8*2+1].w};
            __align__(16) __half hb[8], lb[8];
            #pragma unroll
            for (int j = 0; j < 8; ++j) {
                int c = qt * 32 + q8 * 8 + j;
                float val = (vv[j] - mu) * rs * __ldg(ln_g + c) + __ldg(ln_b + c);
                __half h = __float2half(val);
                hb[j] = h;
                lb[j] = __float2half(val - __half2float(h));
            }
            *(uint4*)(aH + q8*8) = *(uint4*)hb;
            *(uint4*)(aL + q8*8) = *(uint4*)lb;
        }
    }

    const int quad = lid >> 3;
    const int l7   = lid & 7;
    uint32_t aoff[2];
    #pragma unroll
    for (int mf = 0; mf < 2; ++mf) {
        int r = wm*32 + mf*16 + (quad & 1)*8 + l7;
        aoff[mf] = (r * ASTR + (quad >> 1) * 8) * 2;
    }
    const uint32_t boff = ((wn*16 + (quad & 1)*8 + l7) * ASTR + (quad >> 1) * 8) * 2;

    float sig[2][2][4];
    const int rbase = wm*32 + (lid >> 2);
    const int cbase_w = wn*16 + (lid & 3)*2;

    for (int ci = 0; ci < 10; ++ci) {
        __syncthreads();   // A visible (ci=0); prior staging reads done
        const uint32_t wb = sbase + OFF_WB + (ci & 1) * WBSZ;
        if (ci < 9) {
            const uint32_t wbn = sbase + OFF_WB + ((ci + 1) & 1) * WBSZ;
            #pragma unroll
            for (int p = 0; p < 4; ++p) {
                int idx = p * 256 + t;
                int n = idx >> 4, seg = idx & 15;
                cp16(wbn + n * 272 + seg * 16,
                     g_wH + (size_t)(noff[ci+1] + n) * 128 + seg * 8);
            }
            cp_commit();
            cp_wait1();
        } else {
            cp_wait0();
        }
        __syncthreads();

        float acc[2][2][4];
        #pragma unroll
        for (int mf = 0; mf < 2; ++mf)
            #pragma unroll
            for (int nf = 0; nf < 2; ++nf)
                #pragma unroll
                for (int q = 0; q < 4; ++q) acc[mf][nf][q] = 0.f;

        #pragma unroll
        for (int ks = 0; ks < 128; ks += 16) {
            uint32_t ah[2][4], al[2][4], bh[2][2], r4[4];
            ldmx4(ah[0], sbase + OFF_AH + aoff[0] + ks*2);
            ldmx4(ah[1], sbase + OFF_AH + aoff[1] + ks*2);
            ldmx4(al[0], sbase + OFF_AL + aoff[0] + ks*2);
            ldmx4(al[1], sbase + OFF_AL + aoff[1] + ks*2);
            ldmx4(r4, wb + boff + ks*2);
            bh[0][0] = r4[0]; bh[0][1] = r4[2];
            bh[1][0] = r4[1]; bh[1][1] = r4[3];
            #pragma unroll
            for (int mf = 0; mf < 2; ++mf)
                #pragma unroll
                for (int nf = 0; nf < 2; ++nf)
                    mma16816(acc[mf][nf], ah[mf], bh[nf]);
            #pragma unroll
            for (int mf = 0; mf < 2; ++mf)
                #pragma unroll
                for (int nf = 0; nf < 2; ++nf)
                    mma16816(acc[mf][nf], al[mf], bh[nf]);
        }

        if (ci >= 8) {
            const int cb2 = (ci - 8) * 64;
            #pragma unroll
            for (int mf = 0; mf < 2; ++mf) {
                int rr0 = rbase + mf*16, rr1 = rr0 + 8;
                #pragma unroll
                for (int nf = 0; nf < 2; ++nf) {
                    int cc = cbase_w + nf*8;
                    float bg0 = __ldg(b_g + cb2 + cc);
                    float bg1 = __ldg(b_g + cb2 + cc + 1);
                    float2 v0, v1;
                    v0.x = 1.f/(1.f + __expf(-(acc[mf][nf][0] + bg0)));
                    v0.y = 1.f/(1.f + __expf(-(acc[mf][nf][1] + bg1)));
                    v1.x = 1.f/(1.f + __expf(-(acc[mf][nf][2] + bg0)));
                    v1.y = 1.f/(1.f + __expf(-(acc[mf][nf][3] + bg1)));
                    *(float2*)(g_gate + (size_t)(r0 + rr0) * CZ + cb2 + cc) = v0;
                    *(float2*)(g_gate + (size_t)(r0 + rr1) * CZ + cb2 + cc) = v1;
                }
            }
        } else if ((ci & 1) == 0) {
            const float* bg = b_ab_g + noff[ci];
            #pragma unroll
            for (int mf = 0; mf < 2; ++mf)
                #pragma unroll
                for (int nf = 0; nf < 2; ++nf) {
                    int cc = cbase_w + nf*8;
                    float b0 = __ldg(bg + cc), b1 = __ldg(bg + cc + 1);
                    sig[mf][nf][0] = 1.f/(1.f + __expf(-(acc[mf][nf][0] + b0)));
                    sig[mf][nf][1] = 1.f/(1.f + __expf(-(acc[mf][nf][1] + b1)));
                    sig[mf][nf][2] = 1.f/(1.f + __expf(-(acc[mf][nf][2] + b0)));
                    sig[mf][nf][3] = 1.f/(1.f + __expf(-(acc[mf][nf][3] + b1)));
                }
        } else {
            // P chunk: stage packed (hi,lo) into THIS chunk's dead W buffer
            const int p2 = (ci - 1) >> 1;
            const float* bp = b_ab_p + (noff[ci] - 256);
            __syncthreads();   // all warps done reading wb via ldmatrix
            uint32_t* stg = (uint32_t*)(smem + OFF_WB + (ci & 1) * WBSZ);
            #pragma unroll
            for (int mf = 0; mf < 2; ++mf) {
                int rr0 = rbase + mf*16, rr1 = rr0 + 8;
                float m0 = __ldg(mask + r0 + rr0);
                float m1 = __ldg(mask + r0 + rr1);
                #pragma unroll
                for (int nf = 0; nf < 2; ++nf) {
                    int cc = cbase_w + nf*8;
                    float b0 = __ldg(bp + cc), b1 = __ldg(bp + cc + 1);
                    stg[cc*68 + rr0]     = packHL(m0 * sig[mf][nf][0] * (acc[mf][nf][0] + b0));
                    stg[(cc+1)*68 + rr0] = packHL(m0 * sig[mf][nf][1] * (acc[mf][nf][1] + b1));
                    stg[cc*68 + rr1]     = packHL(m1 * sig[mf][nf][2] * (acc[mf][nf][2] + b0));
                    stg[(cc+1)*68 + rr1] = packHL(m1 * sig[mf][nf][3] * (acc[mf][nf][3] + b1));
                }
            }
            __syncthreads();
            const int cch = (p2 & 1) * 64 + (t >> 2);
            const int rrb = (t & 3) * 16;
            size_t off = (size_t)cch * NR + r0 + rrb;
            const uint32_t* sp = stg + (t >> 2) * 68 + rrb;
            __align__(16) unsigned short hb[16], lb[16];
            #pragma unroll
            for (int i = 0; i < 16; ++i) {
                uint32_t wv = sp[i];
                hb[i] = (unsigned short)(wv & 0xffffu);
                lb[i] = (unsigned short)(wv >> 16);
            }
            if (p2 < 2) {   // a: hi + lo
                *(uint4*)(g_ah + off)     = *(uint4*)(hb);
                *(uint4*)(g_ah + off + 8) = *(uint4*)(hb + 8);
                *(uint4*)(g_al + off)     = *(uint4*)(lb);
                *(uint4*)(g_al + off + 8) = *(uint4*)(lb + 8);
            } else {        // b: hi only
                *(uint4*)(g_bh + off)     = *(uint4*)(hb);
                *(uint4*)(g_bh + off + 8) = *(uint4*)(hb + 8);
            }
        }
    }
}

// =====================================================================
// Kernel 2 (v2): einsum fp16 2-pass (aH*bH + aL*bH), b hi-only.
// CTA 128x128, 512 thr, K-chunk 32, double buffer (3 tiles each).
// =====================================================================
#define KC     32
#define STR    40
#define TILE_E (128*STR)
#define BUF_E  (3*TILE_E)
#define K2_SMEM (2 * BUF_E * 2)         // 61440

__global__ void __launch_bounds__(512) k2_einsum_mma() {
    extern __shared__ __half sb[];
    const uint32_t sbase = smem_u32(sb);

    const int t   = threadIdx.x;
    const int lid = t & 31;
    const int w   = t >> 5;
    const int wm  = w >> 2;
    const int wn  = w & 3;
    const int c   = blockIdx.z;
    const int m0  = blockIdx.y * 128;
    const int n0  = blockIdx.x * 128;

    const __half* pAh = g_ah + (size_t)c * NR;
    const __half* pAl = g_al + (size_t)c * NR;
    const __half* pBh = g_bh + (size_t)c * NR;

    const int grow = t >> 2;
    const int gseg = t & 3;
    const size_t gA0 = (size_t)(m0 + grow) * NN + gseg * 8;
    const size_t gB0 = (size_t)(n0 + grow) * NN + gseg * 8;
    const uint32_t sw = (grow * STR + gseg * 8) * 2;

    const int quad = lid >> 3;
    const int l7   = lid & 7;
    uint32_t aoff[2];
    #pragma unroll
    for (int mf = 0; mf < 2; ++mf) {
        int r = wm*32 + mf*16 + (quad & 1)*8 + l7;
        aoff[mf] = (r * STR + (quad >> 1) * 8) * 2;
    }
    uint32_t boff[4];
    #pragma unroll
    for (int nf = 0; nf < 4; ++nf) {
        int r = wn*32 + nf*8 + l7;
        boff[nf] = (r * STR + ((lid >> 3) & 1) * 8) * 2;
    }

    float d[2][4][4];
    #pragma unroll
    for (int mf = 0; mf < 2; ++mf)
        #pragma unroll
        for (int nf = 0; nf < 4; ++nf)
            #pragma unroll
            for (int q = 0; q < 4; ++q) d[mf][nf][q] = 0.f;

    {
        uint32_t b0 = sbase;
        cp16(b0 + 0*TILE_E*2 + sw, pAh + gA0);
        cp16(b0 + 1*TILE_E*2 + sw, pAl + gA0);
        cp16(b0 + 2*TILE_E*2 + sw, pBh + gB0);
        cp_commit();
    }

    for (int ch = 0; ch < 16; ++ch) {
        if (ch < 15) {
            uint32_t bb = sbase + ((ch + 1) & 1) * BUF_E * 2;
            int kk = (ch + 1) * KC;
            cp16(bb + 0*TILE_E*2 + sw, pAh + gA0 + kk);
            cp16(bb + 1*TILE_E*2 + sw, pAl + gA0 + kk);
            cp16(bb + 2*TILE_E*2 + sw, pBh + gB0 + kk);
            cp_commit();
            cp_wait1();
        } else {
            cp_wait0();
        }
        __syncthreads();

        const uint32_t bb = sbase + (ch & 1) * BUF_E * 2;
        const uint32_t bAH = bb;
        const uint32_t bAL = bb + TILE_E*2;
        const uint32_t bBH = bb + 2*TILE_E*2;

        #pragma unroll
        for (int ks = 0; ks < KC; ks += 16) {
            uint32_t ah[2][4], al[2][4], bh[4][2];
            #pragma unroll
            for (int mf = 0; mf < 2; ++mf) ldmx4(ah[mf], bAH + aoff[mf] + ks*2);
            #pragma unroll
            for (int nf = 0; nf < 4; ++nf) ldmx2(bh[nf], bBH + boff[nf] + ks*2);
            #pragma unroll
            for (int mf = 0; mf < 2; ++mf)
                #pragma unroll
                for (int nf = 0; nf < 4; ++nf)
                    mma16816(d[mf][nf], ah[mf], bh[nf]);
            #pragma unroll
            for (int mf = 0; mf < 2; ++mf) ldmx4(al[mf], bAL + aoff[mf] + ks*2);
            #pragma unroll
            for (int mf = 0; mf < 2; ++mf)
                #pragma unroll
                for (int nf = 0; nf < 4; ++nf)
                    mma16816(d[mf][nf], al[mf], bh[nf]);
        }
        __syncthreads();
    }

    float* X = g_x + (size_t)c * NR;
    const int rb = m0 + wm*32 + (lid >> 2);
    const int cb = n0 + wn*32 + (lid & 3) * 2;
    #pragma unroll
    for (int mf = 0; mf < 2; ++mf)
        #pragma unroll
        for (int nf = 0; nf < 4; ++nf) {
            int row = rb + mf*16;
            int col = cb + nf*8;
            *(float2*)(X + (size_t)row * NN + col) =
                make_float2(d[mf][nf][0], d[mf][nf][1]);
            *(float2*)(X + (size_t)(row + 8) * NN + col) =
                make_float2(d[mf][nf][2], d[mf][nf][3]);
        }
}

// =====================================================================
// Kernel 3 (v3): gather x -> LN -> @ w_z (fp16 3-pass) -> *gate -> out.
// =====================================================================
#define K3_AH 33792
#define K3_AL 51200
#define K3_WH 68608
#define K3_WL 86016
#define K3_SMEM 103424

__global__ void __launch_bounds__(256, 2) k3_mma(
    const float* __restrict__ b_z,
    const float* __restrict__ ln_g, const float* __restrict__ ln_b,
    float* __restrict__ out)
{
    extern __shared__ char smem[];
    const uint32_t sbase = smem_u32(smem);
    float* xS = (float*)smem;                    // [row][c] stride 132
    const int t   = threadIdx.x;
    const int lid = t & 31;
    const int w   = t >> 5;
    const int wm  = w >> 2;
    const int wn  = w & 3;
    const int r0  = blockIdx.x * 64;
    const int i0  = r0 >> 9;
    const int j0  = r0 & 511;

    {
        const int joff = t & 63, part = t >> 6;
        const float* src = g_x + (size_t)(part*32) * NR + (size_t)i0 * NN + j0 + joff;
        #pragma unroll
        for (int q = 0; q < 32; ++q)
            xS[joff*132 + part*32 + q] = src[(size_t)q * NR];
    }
    __syncthreads();

    {
        const int row = t >> 2, qt = t & 3;
        const float* zr = xS + row * 132 + qt * 32;
        float s = 0.f, s2 = 0.f;
        #pragma unroll
        for (int q = 0; q < 8; ++q) {
            float4 v = *(const float4*)(zr + q * 4);
            s  += v.x + v.y + v.z + v.w;
            s2 += v.x*v.x + v.y*v.y + v.z*v.z + v.w*v.w;
        }
        s  += __shfl_xor_sync(0xffffffffu, s, 1);
        s2 += __shfl_xor_sync(0xffffffffu, s2, 1);
        s  += __shfl_xor_sync(0xffffffffu, s, 2);
        s2 += __shfl_xor_sync(0xffffffffu, s2, 2);
        float mu  = s * (1.0f/128.0f);
        float var = fmaxf(s2 * (1.0f/128.0f) - mu*mu, 0.f);
        float rs  = rsqrtf(var + EPSV);

        __half* aH = (__half*)(smem + K3_AH) + row * ASTR;
        __half* aL = (__half*)(smem + K3_AL) + row * ASTR;
        #pragma unroll
        for (int q8 = 0; q8 < 4; ++q8) {
            __align__(16) __half hb[8], lb[8];
            #pragma unroll
            for (int j = 0; j < 8; ++j) {
                int c = qt * 32 + q8 * 8 + j;
                float v = (zr[q8*8 + j] - mu) * rs * __ldg(ln_g + c) + __ldg(ln_b + c);
                __half h = __float2half(v);
                hb[j] = h;
                lb[j] = __float2half(v - __half2float(h));
            }
            *(uint4*)(aH + qt*32 + q8*8) = *(uint4*)hb;
            *(uint4*)(aL + qt*32 + q8*8) = *(uint4*)lb;
        }
    }

    const int quad = lid >> 3;
    const int l7   = lid & 7;
    uint32_t aoff[2];
    #pragma unroll
    for (int mf = 0; mf < 2; ++mf) {
        int r = wm*32 + mf*16 + (quad & 1)*8 + l7;
        aoff[mf] = (r * ASTR + (quad >> 1) * 8) * 2;
    }
    const uint32_t boff = ((wn*16 + (quad & 1)*8 + l7) * ASTR + (quad >> 1) * 8) * 2;
    const int rbase = wm*32 + (lid >> 2);
    const int cbase_w = wn*16 + (lid & 3)*2;

    for (int ci = 0; ci < 2; ++ci) {
        __syncthreads();
        #pragma unroll
        for (int p = 0; p < 4; ++p) {
            int idx = p * 256 + t;
            int n = idx >> 4, seg = idx & 15;
            cp16(sbase + K3_WH + n * 272 + seg * 16,
                 g_wH + (size_t)(640 + ci*64 + n) * 128 + seg * 8);
            cp16(sbase + K3_WL + n * 272 + seg * 16,
                 g_wL + (size_t)(640 + ci*64 + n) * 128 + seg * 8);
        }
        cp_commit(); cp_wait0();
        __syncthreads();

        float acc[2][2][4];
        #pragma unroll
        for (int mf = 0; mf < 2; ++mf)
            #pragma unroll
            for (int nf = 0; nf < 2; ++nf)
                #pragma unroll
                for (int q = 0; q < 4; ++q) acc[mf][nf][q] = 0.f;

        #pragma unroll
        for (int ks = 0; ks < 128; ks += 16) {
            uint32_t ah[2][4], al[2][4], bh[2][2], bl[2][2], r4[4];
            ldmx4(ah[0], sbase + K3_AH + aoff[0] + ks*2);
            ldmx4(ah[1], sbase + K3_AH + aoff[1] + ks*2);
            ldmx4(al[0], sbase + K3_AL + aoff[0] + ks*2);
            ldmx4(al[1], sbase + K3_AL + aoff[1] + ks*2);
            ldmx4(r4, sbase + K3_WH + boff + ks*2);
            bh[0][0] = r4[0]; bh[0][1] = r4[2];
            bh[1][0] = r4[1]; bh[1][1] = r4[3];
            ldmx4(r4, sbase + K3_WL + boff + ks*2);
            bl[0][0] = r4[0]; bl[0][1] = r4[2];
            bl[1][0] = r4[1]; bl[1][1] = r4[3];
            #pragma unroll
            for (int mf = 0; mf < 2; ++mf)
                #pragma unroll
                for (int nf = 0; nf < 2; ++nf)
                    mma16816(acc[mf][nf], ah[mf], bh[nf]);
            #pragma unroll
            for (int mf = 0; mf < 2; ++mf)
                #pragma unroll
                for (int nf = 0; nf < 2; ++nf)
                    mma16816(acc[mf][nf], ah[mf], bl[nf]);
            #pragma unroll
            for (int mf = 0; mf < 2; ++mf)
                #pragma unroll
                for (int nf = 0; nf < 2; ++nf)
                    mma16816(acc[mf][nf], al[mf], bh[nf]);
        }

        const int cb2 = ci * 64;
        #pragma unroll
        for (int mf = 0; mf < 2; ++mf) {
            int rr0 = rbase + mf*16, rr1 = rr0 + 8;
            #pragma unroll
            for (int nf = 0; nf < 2; ++nf) {
                int cc = cbase_w + nf*8;
                float b0 = __ldg(b_z + cb2 + cc);
                float b1 = __ldg(b_z + cb2 + cc + 1);
                float2 gg0 = *(const float2*)(g_gate + (size_t)(r0 + rr0) * CZ + cb2 + cc);
                float2 gg1 = *(const float2*)(g_gate + (size_t)(r0 + rr1) * CZ + cb2 + cc);
                float2 v0, v1;
                v0.x = (acc[mf][nf][0] + b0) * gg0.x;
                v0.y = (acc[mf][nf][1] + b1) * gg0.y;
                v1.x = (acc[mf][nf][2] + b0) * gg1.x;
                v1.y = (acc[mf][nf][3] + b1) * gg1.y;
                *(float2*)(out + (size_t)(r0 + rr0) * CZ + cb2 + cc) = v0;
                *(float2*)(out + (size_t)(r0 + rr1) * CZ + cb2 + cc) = v1;
            }
        }
    }
}

// =====================================================================
extern "C" void kernel_launch(void* const* d_in, const int* in_sizes, int n_in,
                              void* d_out, int out_size) {
    const float* z       = (const float*)d_in[0];
    const float* mask    = (const float*)d_in[1];
    const float* w_ab_p  = (const float*)d_in[2];
    const float* b_ab_p  = (const float*)d_in[3];
    const float* w_ab_g  = (const float*)d_in[4];
    const float* b_ab_g  = (const float*)d_in[5];
    const float* w_g     = (const float*)d_in[6];
    const float* b_g     = (const float*)d_in[7];
    const float* w_z     = (const float*)d_in[8];
    const float* b_z     = (const float*)d_in[9];
    const float* ln_in_g = (const float*)d_in[10];
    const float* ln_in_b = (const float*)d_in[11];
    const float* ln_out_g= (const float*)d_in[12];
    const float* ln_out_b= (const float*)d_in[13];
    float* out = (float*)d_out;

    cudaFuncSetAttribute(k1_mma,        cudaFuncAttributeMaxDynamicSharedMemorySize, K1_SMEM);
    cudaFuncSetAttribute(k2_einsum_mma, cudaFuncAttributeMaxDynamicSharedMemorySize, K2_SMEM);
    cudaFuncSetAttribute(k3_mma,        cudaFuncAttributeMaxDynamicSharedMemorySize, K3_SMEM);

    k0_wsplit<<<384, 256>>>(w_ab_g, w_ab_p, w_g, w_z);
    k1_mma<<<NR / 64, 256, K1_SMEM>>>(z, mask, b_ab_p, b_ab_g, b_g,
                                      ln_in_g, ln_in_b);
    k2_einsum_mma<<<dim3(4, 4, 128), 512, K2_SMEM>>>();
    k3_mma<<<NR / 64, 256, K3_SMEM>>>(b_z, ln_out_g, ln_out_b, out);
}

// round 11
// speedup vs baseline: 3.1122x; 1.2972x over previous
#include <cuda_runtime.h>
#include <cuda_fp16.h>
#include <math.h>
#include <cstdint>

#define NN   512
#define CZ   128
#define NR   (NN*NN)          // 262144
#define EPSV 1e-5f

// ---------------- scratch (device globals; alloc-free) ----------------
__device__ __half g_ah[(size_t)CZ * NR];   // a hi [c][i][k]
__device__ __half g_bh[(size_t)CZ * NR];   // b hi [c][j][k]
__device__ __half g_gate[(size_t)NR * CZ]; // gate[r][c]  (fp16)
__device__ float g_x[(size_t)CZ * NR];     // x[c][i][j]  (fp32)
__device__ __half g_wH[768 * 128];         // packed weights hi [n][k]
__device__ __half g_wL[768 * 128];         // packed weights lo [n][k]

static __device__ __forceinline__ uint32_t smem_u32(const void* p) {
    return (uint32_t)__cvta_generic_to_shared(p);
}
static __device__ __forceinline__ void cp16(uint32_t dst, const void* src) {
    asm volatile("cp.async.cg.shared.global [%0], [%1], 16;" :: "r"(dst), "l"(src));
}
static __device__ __forceinline__ void cp_commit() {
    asm volatile("cp.async.commit_group;" ::: "memory");
}
static __device__ __forceinline__ void cp_wait1() {
    asm volatile("cp.async.wait_group 1;" ::: "memory");
}
static __device__ __forceinline__ void cp_wait0() {
    asm volatile("cp.async.wait_group 0;" ::: "memory");
}
static __device__ __forceinline__ void ldmx4(uint32_t* r, uint32_t addr) {
    asm volatile("ldmatrix.sync.aligned.m8n8.x4.shared.b16 {%0,%1,%2,%3}, [%4];"
                 : "=r"(r[0]), "=r"(r[1]), "=r"(r[2]), "=r"(r[3]) : "r"(addr));
}
static __device__ __forceinline__ void ldmx2(uint32_t* r, uint32_t addr) {
    asm volatile("ldmatrix.sync.aligned.m8n8.x2.shared.b16 {%0,%1}, [%2];"
                 : "=r"(r[0]), "=r"(r[1]) : "r"(addr));
}
static __device__ __forceinline__ void mma16816(float* d, const uint32_t* a, const uint32_t* b) {
    asm volatile("mma.sync.aligned.m16n8k16.row.col.f32.f16.f16.f32 "
                 "{%0,%1,%2,%3}, {%4,%5,%6,%7}, {%8,%9}, {%0,%1,%2,%3};"
                 : "+f"(d[0]), "+f"(d[1]), "+f"(d[2]), "+f"(d[3])
                 : "r"(a[0]), "r"(a[1]), "r"(a[2]), "r"(a[3]), "r"(b[0]), "r"(b[1]));
}

// =====================================================================
// Kernel 0: split weights into fp16 hi/lo, transposed to [n][k].
// n: 0-255 = w_ab_g, 256-511 = w_ab_p, 512-639 = w_g, 640-767 = w_z
// =====================================================================
__global__ void __launch_bounds__(256) k0_wsplit(
    const float* __restrict__ w_ab_g, const float* __restrict__ w_ab_p,
    const float* __restrict__ w_g,   const float* __restrict__ w_z)
{
    int idx = blockIdx.x * 256 + threadIdx.x;   // 384 blocks
    if (idx >= 768 * 128) return;
    int n = idx >> 7, k = idx & 127;
    float v;
    if (n < 256)      v = w_ab_g[k * 256 + n];
    else if (n < 512) v = w_ab_p[k * 256 + (n - 256)];
    else if (n < 640) v = w_g[k * 128 + (n - 512)];
    else              v = w_z[k * 128 + (n - 640)];
    __half h = __float2half(v);
    g_wH[idx] = h;
    g_wL[idx] = __float2half(v - __half2float(h));
}

// =====================================================================
// Kernel 1 (v5): LN(z) + projections, fp16 SINGLE-pass (znH * WH).
// 4096 CTAs x 64 rows, 256 thr (8 warps: 2m x 4n), warp tile 32x16.
// smem 52224 -> reg-limited 2 CTAs/SM; W double-buffered.
// =====================================================================
#define ASTR   136
#define OFF_AH 0                       // 17408 B
#define OFF_WB 17408                   // two 17408-B WH buffers
#define WBSZ   17408
#define K1_SMEM 52224

__global__ void __launch_bounds__(256, 2) k1_mma(
    const float* __restrict__ z, const float* __restrict__ mask,
    const float* __restrict__ b_ab_p, const float* __restrict__ b_ab_g,
    const float* __restrict__ b_g,
    const float* __restrict__ ln_g,  const float* __restrict__ ln_b)
{
    extern __shared__ char smem[];
    const uint32_t sbase = smem_u32(smem);
    const int t   = threadIdx.x;
    const int lid = t & 31;
    const int w   = t >> 5;
    const int wm  = w >> 2;
    const int wn  = w & 3;
    const int r0  = blockIdx.x * 64;

    const int noff[10] = {0, 256, 64, 320, 128, 384, 192, 448, 512, 576};

    // ---- prefetch WH chunk 0 into buffer 0 ----
    {
        #pragma unroll
        for (int p = 0; p < 4; ++p) {
            int idx = p * 256 + t;
            int n = idx >> 4, seg = idx & 15;
            cp16(sbase + OFF_WB + n * 272 + seg * 16,
                 g_wH + (size_t)n * 128 + seg * 8);
        }
        cp_commit();
    }

    // ---- z via LDG -> LN (4 thr/row, shfl) -> fp16 hi smem ----
    {
        const int row = t >> 2, qt = t & 3;
        const float4* zr = (const float4*)(z + (size_t)(r0 + row) * CZ + qt * 32);
        float4 v[8];
        #pragma unroll
        for (int q = 0; q < 8; ++q) v[q] = __ldg(zr + q);
        float s = 0.f, s2 = 0.f;
        #pragma unroll
        for (int q = 0; q < 8; ++q) {
            s  += v[q].x + v[q].y + v[q].z + v[q].w;
            s2 += v[q].x*v[q].x + v[q].y*v[q].y + v[q].z*v[q].z + v[q].w*v[q].w;
        }
        s  += __shfl_xor_sync(0xffffffffu, s, 1);
        s2 += __shfl_xor_sync(0xffffffffu, s2, 1);
        s  += __shfl_xor_sync(0xffffffffu, s, 2);
        s2 += __shfl_xor_sync(0xffffffffu, s2, 2);
        float mu  = s * (1.0f/128.0f);
        float var = fmaxf(s2 * (1.0f/128.0f) - mu*mu, 0.f);
        float rs  = rsqrtf(var + EPSV);

        __half* aH = (__half*)(smem + OFF_AH) + row * ASTR + qt * 32;
        #pragma unroll
        for (int q8 = 0; q8 < 4; ++q8) {
            const float vv[8] = {v[q8*2].x, v[q8*2].y, v[q8*2].z, v[q8*2].w,
                                 v[q8*2+1].x, v[q8*2+1].y, v[q8*2+1].z, v[q8*2+1].w};
            __align__(16) __half hb[8];
            #pragma unroll
            for (int j = 0; j < 8; ++j) {
                int c = qt * 32 + q8 * 8 + j;
                hb[j] = __float2half((vv[j] - mu) * rs * __ldg(ln_g + c) + __ldg(ln_b + c));
            }
            *(uint4*)(aH + q8*8) = *(uint4*)hb;
        }
    }

    const int quad = lid >> 3;
    const int l7   = lid & 7;
    uint32_t aoff[2];
    #pragma unroll
    for (int mf = 0; mf < 2; ++mf) {
        int r = wm*32 + mf*16 + (quad & 1)*8 + l7;
        aoff[mf] = (r * ASTR + (quad >> 1) * 8) * 2;
    }
    const uint32_t boff = ((wn*16 + (quad & 1)*8 + l7) * ASTR + (quad >> 1) * 8) * 2;

    float sig[2][2][4];
    const int rbase = wm*32 + (lid >> 2);
    const int cbase_w = wn*16 + (lid & 3)*2;

    for (int ci = 0; ci < 10; ++ci) {
        __syncthreads();   // A visible (ci=0); prior staging reads done
        const uint32_t wb = sbase + OFF_WB + (ci & 1) * WBSZ;
        if (ci < 9) {
            const uint32_t wbn = sbase + OFF_WB + ((ci + 1) & 1) * WBSZ;
            #pragma unroll
            for (int p = 0; p < 4; ++p) {
                int idx = p * 256 + t;
                int n = idx >> 4, seg = idx & 15;
                cp16(wbn + n * 272 + seg * 16,
                     g_wH + (size_t)(noff[ci+1] + n) * 128 + seg * 8);
            }
            cp_commit();
            cp_wait1();
        } else {
            cp_wait0();
        }
        __syncthreads();

        float acc[2][2][4];
        #pragma unroll
        for (int mf = 0; mf < 2; ++mf)
            #pragma unroll
            for (int nf = 0; nf < 2; ++nf)
                #pragma unroll
                for (int q = 0; q < 4; ++q) acc[mf][nf][q] = 0.f;

        #pragma unroll
        for (int ks = 0; ks < 128; ks += 16) {
            uint32_t ah[2][4], bh[2][2], r4[4];
            ldmx4(ah[0], sbase + OFF_AH + aoff[0] + ks*2);
            ldmx4(ah[1], sbase + OFF_AH + aoff[1] + ks*2);
            ldmx4(r4, wb + boff + ks*2);
            bh[0][0] = r4[0]; bh[0][1] = r4[2];
            bh[1][0] = r4[1]; bh[1][1] = r4[3];
            #pragma unroll
            for (int mf = 0; mf < 2; ++mf)
                #pragma unroll
                for (int nf = 0; nf < 2; ++nf)
                    mma16816(acc[mf][nf], ah[mf], bh[nf]);
        }

        if (ci >= 8) {
            const int cb2 = (ci - 8) * 64;
            #pragma unroll
            for (int mf = 0; mf < 2; ++mf) {
                int rr0 = rbase + mf*16, rr1 = rr0 + 8;
                #pragma unroll
                for (int nf = 0; nf < 2; ++nf) {
                    int cc = cbase_w + nf*8;
                    float bg0 = __ldg(b_g + cb2 + cc);
                    float bg1 = __ldg(b_g + cb2 + cc + 1);
                    __half2 h0, h1;
                    h0.x = __float2half(1.f/(1.f + __expf(-(acc[mf][nf][0] + bg0))));
                    h0.y = __float2half(1.f/(1.f + __expf(-(acc[mf][nf][1] + bg1))));
                    h1.x = __float2half(1.f/(1.f + __expf(-(acc[mf][nf][2] + bg0))));
                    h1.y = __float2half(1.f/(1.f + __expf(-(acc[mf][nf][3] + bg1))));
                    *(__half2*)(g_gate + (size_t)(r0 + rr0) * CZ + cb2 + cc) = h0;
                    *(__half2*)(g_gate + (size_t)(r0 + rr1) * CZ + cb2 + cc) = h1;
                }
            }
        } else if ((ci & 1) == 0) {
            const float* bg = b_ab_g + noff[ci];
            #pragma unroll
            for (int mf = 0; mf < 2; ++mf)
                #pragma unroll
                for (int nf = 0; nf < 2; ++nf) {
                    int cc = cbase_w + nf*8;
                    float b0 = __ldg(bg + cc), b1 = __ldg(bg + cc + 1);
                    sig[mf][nf][0] = 1.f/(1.f + __expf(-(acc[mf][nf][0] + b0)));
                    sig[mf][nf][1] = 1.f/(1.f + __expf(-(acc[mf][nf][1] + b1)));
                    sig[mf][nf][2] = 1.f/(1.f + __expf(-(acc[mf][nf][2] + b0)));
                    sig[mf][nf][3] = 1.f/(1.f + __expf(-(acc[mf][nf][3] + b1)));
                }
        } else {
            // P chunk: hi value staged (u32 low half) into THIS chunk's dead W buffer
            const int p2 = (ci - 1) >> 1;
            const float* bp = b_ab_p + (noff[ci] - 256);
            __syncthreads();   // all warps done reading wb via ldmatrix
            uint32_t* stg = (uint32_t*)(smem + OFF_WB + (ci & 1) * WBSZ);
            #pragma unroll
            for (int mf = 0; mf < 2; ++mf) {
                int rr0 = rbase + mf*16, rr1 = rr0 + 8;
                float m0 = __ldg(mask + r0 + rr0);
                float m1 = __ldg(mask + r0 + rr1);
                #pragma unroll
                for (int nf = 0; nf < 2; ++nf) {
                    int cc = cbase_w + nf*8;
                    float b0 = __ldg(bp + cc), b1 = __ldg(bp + cc + 1);
                    stg[cc*68 + rr0]     = (uint32_t)__half_as_ushort(
                        __float2half(m0 * sig[mf][nf][0] * (acc[mf][nf][0] + b0)));
                    stg[(cc+1)*68 + rr0] = (uint32_t)__half_as_ushort(
                        __float2half(m0 * sig[mf][nf][1] * (acc[mf][nf][1] + b1)));
                    stg[cc*68 + rr1]     = (uint32_t)__half_as_ushort(
                        __float2half(m1 * sig[mf][nf][2] * (acc[mf][nf][2] + b0)));
                    stg[(cc+1)*68 + rr1] = (uint32_t)__half_as_ushort(
                        __float2half(m1 * sig[mf][nf][3] * (acc[mf][nf][3] + b1)));
                }
            }
            __syncthreads();
            __half* dH = (p2 < 2) ? g_ah : g_bh;
            const int cch = (p2 & 1) * 64 + (t >> 2);
            const int rrb = (t & 3) * 16;
            size_t off = (size_t)cch * NR + r0 + rrb;
            const uint32_t* sp = stg + (t >> 2) * 68 + rrb;
            __align__(16) unsigned short hb[16];
            #pragma unroll
            for (int i = 0; i < 16; ++i) hb[i] = (unsigned short)(sp[i] & 0xffffu);
            *(uint4*)(dH + off)     = *(uint4*)(hb);
            *(uint4*)(dH + off + 8) = *(uint4*)(hb + 8);
        }
    }
}

// =====================================================================
// Kernel 2 (v3): einsum fp16 SINGLE-pass (aH * bH).
// CTA 128x128, 512 thr, K-chunk 32, double buffer (2 tiles each).
// =====================================================================
#define KC     32
#define STR    40
#define TILE_E (128*STR)
#define BUF_E  (2*TILE_E)
#define K2_SMEM (2 * BUF_E * 2)         // 40960

__global__ void __launch_bounds__(512) k2_einsum_mma() {
    extern __shared__ __half sb[];
    const uint32_t sbase = smem_u32(sb);

    const int t   = threadIdx.x;
    const int lid = t & 31;
    const int w   = t >> 5;
    const int wm  = w >> 2;
    const int wn  = w & 3;
    const int c   = blockIdx.z;
    const int m0  = blockIdx.y * 128;
    const int n0  = blockIdx.x * 128;

    const __half* pAh = g_ah + (size_t)c * NR;
    const __half* pBh = g_bh + (size_t)c * NR;

    const int grow = t >> 2;
    const int gseg = t & 3;
    const size_t gA0 = (size_t)(m0 + grow) * NN + gseg * 8;
    const size_t gB0 = (size_t)(n0 + grow) * NN + gseg * 8;
    const uint32_t sw = (grow * STR + gseg * 8) * 2;

    const int quad = lid >> 3;
    const int l7   = lid & 7;
    uint32_t aoff[2];
    #pragma unroll
    for (int mf = 0; mf < 2; ++mf) {
        int r = wm*32 + mf*16 + (quad & 1)*8 + l7;
        aoff[mf] = (r * STR + (quad >> 1) * 8) * 2;
    }
    uint32_t boff[4];
    #pragma unroll
    for (int nf = 0; nf < 4; ++nf) {
        int r = wn*32 + nf*8 + l7;
        boff[nf] = (r * STR + ((lid >> 3) & 1) * 8) * 2;
    }

    float d[2][4][4];
    #pragma unroll
    for (int mf = 0; mf < 2; ++mf)
        #pragma unroll
        for (int nf = 0; nf < 4; ++nf)
            #pragma unroll
            for (int q = 0; q < 4; ++q) d[mf][nf][q] = 0.f;

    {
        uint32_t b0 = sbase;
        cp16(b0 + 0*TILE_E*2 + sw, pAh + gA0);
        cp16(b0 + 1*TILE_E*2 + sw, pBh + gB0);
        cp_commit();
    }

    for (int ch = 0; ch < 16; ++ch) {
        if (ch < 15) {
            uint32_t bb = sbase + ((ch + 1) & 1) * BUF_E * 2;
            int kk = (ch + 1) * KC;
            cp16(bb + 0*TILE_E*2 + sw, pAh + gA0 + kk);
            cp16(bb + 1*TILE_E*2 + sw, pBh + gB0 + kk);
            cp_commit();
            cp_wait1();
        } else {
            cp_wait0();
        }
        __syncthreads();

        const uint32_t bb = sbase + (ch & 1) * BUF_E * 2;
        const uint32_t bAH = bb;
        const uint32_t bBH = bb + TILE_E*2;

        #pragma unroll
        for (int ks = 0; ks < KC; ks += 16) {
            uint32_t ah[2][4], bh[4][2];
            #pragma unroll
            for (int mf = 0; mf < 2; ++mf) ldmx4(ah[mf], bAH + aoff[mf] + ks*2);
            #pragma unroll
            for (int nf = 0; nf < 4; ++nf) ldmx2(bh[nf], bBH + boff[nf] + ks*2);
            #pragma unroll
            for (int mf = 0; mf < 2; ++mf)
                #pragma unroll
                for (int nf = 0; nf < 4; ++nf)
                    mma16816(d[mf][nf], ah[mf], bh[nf]);
        }
        __syncthreads();
    }

    float* X = g_x + (size_t)c * NR;
    const int rb = m0 + wm*32 + (lid >> 2);
    const int cb = n0 + wn*32 + (lid & 3) * 2;
    #pragma unroll
    for (int mf = 0; mf < 2; ++mf)
        #pragma unroll
        for (int nf = 0; nf < 4; ++nf) {
            int row = rb + mf*16;
            int col = cb + nf*8;
            *(float2*)(X + (size_t)row * NN + col) =
                make_float2(d[mf][nf][0], d[mf][nf][1]);
            *(float2*)(X + (size_t)(row + 8) * NN + col) =
                make_float2(d[mf][nf][2], d[mf][nf][3]);
        }
}

// =====================================================================
// Kernel 3 (v4): gather x -> LN -> @ w_z (fp16 3-pass) -> *gate(fp16) -> out.
// =====================================================================
#define K3_AH 33792
#define K3_AL 51200
#define K3_WH 68608
#define K3_WL 86016
#define K3_SMEM 103424

__global__ void __launch_bounds__(256, 2) k3_mma(
    const float* __restrict__ b_z,
    const float* __restrict__ ln_g, const float* __restrict__ ln_b,
    float* __restrict__ out)
{
    extern __shared__ char smem[];
    const uint32_t sbase = smem_u32(smem);
    float* xS = (float*)smem;                    // [row][c] stride 132
    const int t   = threadIdx.x;
    const int lid = t & 31;
    const int w   = t >> 5;
    const int wm  = w >> 2;
    const int wn  = w & 3;
    const int r0  = blockIdx.x * 64;
    const int i0  = r0 >> 9;
    const int j0  = r0 & 511;

    {
        const int joff = t & 63, part = t >> 6;
        const float* src = g_x + (size_t)(part*32) * NR + (size_t)i0 * NN + j0 + joff;
        #pragma unroll
        for (int q = 0; q < 32; ++q)
            xS[joff*132 + part*32 + q] = src[(size_t)q * NR];
    }
    __syncthreads();

    {
        const int row = t >> 2, qt = t & 3;
        const float* zr = xS + row * 132 + qt * 32;
        float s = 0.f, s2 = 0.f;
        #pragma unroll
        for (int q = 0; q < 8; ++q) {
            float4 v = *(const float4*)(zr + q * 4);
            s  += v.x + v.y + v.z + v.w;
            s2 += v.x*v.x + v.y*v.y + v.z*v.z + v.w*v.w;
        }
        s  += __shfl_xor_sync(0xffffffffu, s, 1);
        s2 += __shfl_xor_sync(0xffffffffu, s2, 1);
        s  += __shfl_xor_sync(0xffffffffu, s, 2);
        s2 += __shfl_xor_sync(0xffffffffu, s2, 2);
        float mu  = s * (1.0f/128.0f);
        float var = fmaxf(s2 * (1.0f/128.0f) - mu*mu, 0.f);
        float rs  = rsqrtf(var + EPSV);

        __half* aH = (__half*)(smem + K3_AH) + row * ASTR;
        __half* aL = (__half*)(smem + K3_AL) + row * ASTR;
        #pragma unroll
        for (int q8 = 0; q8 < 4; ++q8) {
            __align__(16) __half hb[8], lb[8];
            #pragma unroll
            for (int j = 0; j < 8; ++j) {
                int c = qt * 32 + q8 * 8 + j;
                float v = (zr[q8*8 + j] - mu) * rs * __ldg(ln_g + c) + __ldg(ln_b + c);
                __half h = __float2half(v);
                hb[j] = h;
                lb[j] = __float2half(v - __half2float(h));
            }
            *(uint4*)(aH + qt*32 + q8*8) = *(uint4*)hb;
            *(uint4*)(aL + qt*32 + q8*8) = *(uint4*)lb;
        }
    }

    const int quad = lid >> 3;
    const int l7   = lid & 7;
    uint32_t aoff[2];
    #pragma unroll
    for (int mf = 0; mf < 2; ++mf) {
        int r = wm*32 + mf*16 + (quad & 1)*8 + l7;
        aoff[mf] = (r * ASTR + (quad >> 1) * 8) * 2;
    }
    const uint32_t boff = ((wn*16 + (quad & 1)*8 + l7) * ASTR + (quad >> 1) * 8) * 2;
    const int rbase = wm*32 + (lid >> 2);
    const int cbase_w = wn*16 + (lid & 3)*2;

    for (int ci = 0; ci < 2; ++ci) {
        __syncthreads();
        #pragma unroll
        for (int p = 0; p < 4; ++p) {
            int idx = p * 256 + t;
            int n = idx >> 4, seg = idx & 15;
            cp16(sbase + K3_WH + n * 272 + seg * 16,
                 g_wH + (size_t)(640 + ci*64 + n) * 128 + seg * 8);
            cp16(sbase + K3_WL + n * 272 + seg * 16,
                 g_wL + (size_t)(640 + ci*64 + n) * 128 + seg * 8);
        }
        cp_commit(); cp_wait0();
        __syncthreads();

        float acc[2][2][4];
        #pragma unroll
        for (int mf = 0; mf < 2; ++mf)
            #pragma unroll
            for (int nf = 0; nf < 2; ++nf)
                #pragma unroll
                for (int q = 0; q < 4; ++q) acc[mf][nf][q] = 0.f;

        #pragma unroll
        for (int ks = 0; ks < 128; ks += 16) {
            uint32_t ah[2][4], al[2][4], bh[2][2], bl[2][2], r4[4];
            ldmx4(ah[0], sbase + K3_AH + aoff[0] + ks*2);
            ldmx4(ah[1], sbase + K3_AH + aoff[1] + ks*2);
            ldmx4(al[0], sbase + K3_AL + aoff[0] + ks*2);
            ldmx4(al[1], sbase + K3_AL + aoff[1] + ks*2);
            ldmx4(r4, sbase + K3_WH + boff + ks*2);
            bh[0][0] = r4[0]; bh[0][1] = r4[2];
            bh[1][0] = r4[1]; bh[1][1] = r4[3];
            ldmx4(r4, sbase + K3_WL + boff + ks*2);
            bl[0][0] = r4[0]; bl[0][1] = r4[2];
            bl[1][0] = r4[1]; bl[1][1] = r4[3];
            #pragma unroll
            for (int mf = 0; mf < 2; ++mf)
                #pragma unroll
                for (int nf = 0; nf < 2; ++nf)
                    mma16816(acc[mf][nf], ah[mf], bh[nf]);
            #pragma unroll
            for (int mf = 0; mf < 2; ++mf)
                #pragma unroll
                for (int nf = 0; nf < 2; ++nf)
                    mma16816(acc[mf][nf], ah[mf], bl[nf]);
            #pragma unroll
            for (int mf = 0; mf < 2; ++mf)
                #pragma unroll
                for (int nf = 0; nf < 2; ++nf)
                    mma16816(acc[mf][nf], al[mf], bh[nf]);
        }

        const int cb2 = ci * 64;
        #pragma unroll
        for (int mf = 0; mf < 2; ++mf) {
            int rr0 = rbase + mf*16, rr1 = rr0 + 8;
            #pragma unroll
            for (int nf = 0; nf < 2; ++nf) {
                int cc = cbase_w + nf*8;
                float b0 = __ldg(b_z + cb2 + cc);
                float b1 = __ldg(b_z + cb2 + cc + 1);
                float2 gg0 = __half22float2(*(const __half2*)(g_gate + (size_t)(r0 + rr0) * CZ + cb2 + cc));
                float2 gg1 = __half22float2(*(const __half2*)(g_gate + (size_t)(r0 + rr1) * CZ + cb2 + cc));
                float2 v0, v1;
                v0.x = (acc[mf][nf][0] + b0) * gg0.x;
                v0.y = (acc[mf][nf][1] + b1) * gg0.y;
                v1.x = (acc[mf][nf][2] + b0) * gg1.x;
                v1.y = (acc[mf][nf][3] + b1) * gg1.y;
                *(float2*)(out + (size_t)(r0 + rr0) * CZ + cb2 + cc) = v0;
                *(float2*)(out + (size_t)(r0 + rr1) * CZ + cb2 + cc) = v1;
            }
        }
    }
}

// =====================================================================
extern "C" void kernel_launch(void* const* d_in, const int* in_sizes, int n_in,
                              void* d_out, int out_size) {
    const float* z       = (const float*)d_in[0];
    const float* mask    = (const float*)d_in[1];
    const float* w_ab_p  = (const float*)d_in[2];
    const float* b_ab_p  = (const float*)d_in[3];
    const float* w_ab_g  = (const float*)d_in[4];
    const float* b_ab_g  = (const float*)d_in[5];
    const float* w_g     = (const float*)d_in[6];
    const float* b_g     = (const float*)d_in[7];
    const float* w_z     = (const float*)d_in[8];
    const float* b_z     = (const float*)d_in[9];
    const float* ln_in_g = (const float*)d_in[10];
    const float* ln_in_b = (const float*)d_in[11];
    const float* ln_out_g= (const float*)d_in[12];
    const float* ln_out_b= (const float*)d_in[13];
    float* out = (float*)d_out;

    cudaFuncSetAttribute(k1_mma,        cudaFuncAttributeMaxDynamicSharedMemorySize, K1_SMEM);
    cudaFuncSetAttribute(k2_einsum_mma, cudaFuncAttributeMaxDynamicSharedMemorySize, K2_SMEM);
    cudaFuncSetAttribute(k3_mma,        cudaFuncAttributeMaxDynamicSharedMemorySize, K3_SMEM);

    k0_wsplit<<<384, 256>>>(w_ab_g, w_ab_p, w_g, w_z);
    k1_mma<<<NR / 64, 256, K1_SMEM>>>(z, mask, b_ab_p, b_ab_g, b_g,
                                      ln_in_g, ln_in_b);
    k2_einsum_mma<<<dim3(4, 4, 128), 512, K2_SMEM>>>();
    k3_mma<<<NR / 64, 256, K3_SMEM>>>(b_z, ln_out_g, ln_out_b, out);
}